// round 13
// baseline (speedup 1.0000x reference)
#include <cuda_runtime.h>

#define Bb 2
#define Ss 1024
#define Dd 768
#define DV 32
#define NV 64
#define D3 256
#define BS (Bb*Ss)
#define Kd 768
#define EPSV 1e-8f
#define LNEPS 1e-5f
#define NORMED_ELEMS ((size_t)Bb*Ss*Dd)

// ---------------- scratch ----------------
__device__ float g_QK[BS*64];
__device__ float g_V[BS*Dd];
__device__ float g_ABR[BS*Dd];
__device__ float g_emb2[NV*DV];
__device__ float g_gm[NV];
__device__ float g_ws [(size_t)BS*Ss];
__device__ float g_wap[(size_t)BS*Ss];
__device__ float g_wbd[(size_t)BS*Ss];
__device__ float g_wrs[(size_t)BS*Ss];
__device__ float g_invden[4*BS];
__device__ float g_comb[BS*Dd];
__device__ float g_res[BS*Dd];

// ---------------- helpers ----------------
__device__ __forceinline__ float f2tf32(float f) {
    unsigned r;
    asm("cvt.rna.tf32.f32 %0, %1;" : "=r"(r) : "f"(f));
    return __uint_as_float(r);
}
__device__ __forceinline__ void mma_tf32(float* c, const unsigned* a, const unsigned* b) {
    asm volatile("mma.sync.aligned.m16n8k8.row.col.f32.tf32.tf32.f32 "
                 "{%0,%1,%2,%3}, {%4,%5,%6,%7}, {%8,%9}, {%0,%1,%2,%3};"
                 : "+f"(c[0]), "+f"(c[1]), "+f"(c[2]), "+f"(c[3])
                 : "r"(a[0]), "r"(a[1]), "r"(a[2]), "r"(a[3]), "r"(b[0]), "r"(b[1]));
}
__device__ __forceinline__ unsigned smem_u32(const void* p) {
    return (unsigned)__cvta_generic_to_shared(p);
}
#define CP_ASYNC16(dst, src) \
    asm volatile("cp.async.ca.shared.global [%0], [%1], 16;" :: "r"(dst), "l"(src))
#define CP_COMMIT() asm volatile("cp.async.commit_group;" ::: "memory")
#define CP_WAIT0()  asm volatile("cp.async.wait_group 0;" ::: "memory")

// ======== fused projection GEMM (BK=32, double-buffered, n-offset selectable) ========
__global__ __launch_bounds__(256)
void gemm_fused(const float* __restrict__ X,
                const float* __restrict__ Wq, const float* __restrict__ Wk,
                const float* __restrict__ Wv, const float* __restrict__ Wa,
                const float* __restrict__ Wb, const float* __restrict__ Wr,
                float* __restrict__ Cqk, float* __restrict__ Cv, float* __restrict__ Cabr,
                int n_off)
{
    extern __shared__ float sm[];
    float (*As)[32][136] = (float (*)[32][136])sm;
    float (*Bs)[32][72]  = (float (*)[32][72])(sm + 2*32*136);

    int tid = threadIdx.x;
    int lane = tid & 31, warp = tid >> 5;
    int wm = warp & 3, wn = warp >> 2;
    int gid = lane >> 2, tig = lane & 3;
    int m0 = blockIdx.y * 128, n0 = (blockIdx.x + n_off) * 64;

    float c[2][4][4];
    #pragma unroll
    for (int mt = 0; mt < 2; mt++)
        #pragma unroll
        for (int nt = 0; nt < 4; nt++)
            #pragma unroll
            for (int e = 0; e < 4; e++) c[mt][nt][e] = 0.f;

    int ra = tid >> 2;
    int ka = (tid & 3) * 4;
    int sw = 8 * (tid & 3);
    const float* xp0 = X + (size_t)(m0 + ra) * Kd + ka;
    const float* xp1 = X + (size_t)(m0 + ra + 64) * Kd + ka;
    int rW = n0 + ra;
    const float* wp;
    if      (rW <   32) wp = Wq + (size_t)rW * Kd;
    else if (rW <   64) wp = Wk + (size_t)(rW -   32) * Kd;
    else if (rW <  832) wp = Wv + (size_t)(rW -   64) * Kd;
    else if (rW < 1088) wp = Wa + (size_t)(rW -  832) * Kd;
    else if (rW < 1344) wp = Wb + (size_t)(rW - 1088) * Kd;
    else                wp = Wr + (size_t)(rW - 1344) * Kd;
    wp += ka;

    int ca = ra ^ sw, ca1 = (ra + 64) ^ sw;

    {
        float4 a00 = *(const float4*)(xp0);
        float4 a01 = *(const float4*)(xp0 + 16);
        float4 a10 = *(const float4*)(xp1);
        float4 a11 = *(const float4*)(xp1 + 16);
        float4 b0  = *(const float4*)(wp);
        float4 b1  = *(const float4*)(wp + 16);
        As[0][ka+0][ca]  = f2tf32(a00.x); As[0][ka+1][ca]  = f2tf32(a00.y);
        As[0][ka+2][ca]  = f2tf32(a00.z); As[0][ka+3][ca]  = f2tf32(a00.w);
        As[0][ka+16][ca] = f2tf32(a01.x); As[0][ka+17][ca] = f2tf32(a01.y);
        As[0][ka+18][ca] = f2tf32(a01.z); As[0][ka+19][ca] = f2tf32(a01.w);
        As[0][ka+0][ca1]  = f2tf32(a10.x); As[0][ka+1][ca1]  = f2tf32(a10.y);
        As[0][ka+2][ca1]  = f2tf32(a10.z); As[0][ka+3][ca1]  = f2tf32(a10.w);
        As[0][ka+16][ca1] = f2tf32(a11.x); As[0][ka+17][ca1] = f2tf32(a11.y);
        As[0][ka+18][ca1] = f2tf32(a11.z); As[0][ka+19][ca1] = f2tf32(a11.w);
        Bs[0][ka+0][ca]  = f2tf32(b0.x); Bs[0][ka+1][ca]  = f2tf32(b0.y);
        Bs[0][ka+2][ca]  = f2tf32(b0.z); Bs[0][ka+3][ca]  = f2tf32(b0.w);
        Bs[0][ka+16][ca] = f2tf32(b1.x); Bs[0][ka+17][ca] = f2tf32(b1.y);
        Bs[0][ka+18][ca] = f2tf32(b1.z); Bs[0][ka+19][ca] = f2tf32(b1.w);
    }
    __syncthreads();

    const int NIT = Kd / 32;
    for (int it = 0; it < NIT; it++) {
        int cur = it & 1;
        float4 a00, a01, a10, a11, b0, b1;
        if (it + 1 < NIT) {
            int k0 = (it + 1) * 32;
            a00 = *(const float4*)(xp0 + k0);
            a01 = *(const float4*)(xp0 + k0 + 16);
            a10 = *(const float4*)(xp1 + k0);
            a11 = *(const float4*)(xp1 + k0 + 16);
            b0  = *(const float4*)(wp  + k0);
            b1  = *(const float4*)(wp  + k0 + 16);
        }
        #pragma unroll
        for (int ks = 0; ks < 32; ks += 8) {
            int swl = 8 * ((ks >> 2) & 3);
            int swh = 8 * (((ks + 4) >> 2) & 3);
            int klo = ks + tig, khi = ks + tig + 4;
            unsigned a[2][4], b[4][2];
            #pragma unroll
            for (int mt = 0; mt < 2; mt++) {
                int mr = wm*32 + mt*16 + gid;
                a[mt][0] = __float_as_uint(As[cur][klo][ mr      ^ swl]);
                a[mt][1] = __float_as_uint(As[cur][klo][(mr + 8) ^ swl]);
                a[mt][2] = __float_as_uint(As[cur][khi][ mr      ^ swh]);
                a[mt][3] = __float_as_uint(As[cur][khi][(mr + 8) ^ swh]);
            }
            #pragma unroll
            for (int nt = 0; nt < 4; nt++) {
                int nc = wn*32 + nt*8 + gid;
                b[nt][0] = __float_as_uint(Bs[cur][klo][nc ^ swl]);
                b[nt][1] = __float_as_uint(Bs[cur][khi][nc ^ swh]);
            }
            #pragma unroll
            for (int mt = 0; mt < 2; mt++)
                #pragma unroll
                for (int nt = 0; nt < 4; nt++)
                    mma_tf32(c[mt][nt], a[mt], b[nt]);
        }
        if (it + 1 < NIT) {
            int nx = cur ^ 1;
            As[nx][ka+0][ca]  = f2tf32(a00.x); As[nx][ka+1][ca]  = f2tf32(a00.y);
            As[nx][ka+2][ca]  = f2tf32(a00.z); As[nx][ka+3][ca]  = f2tf32(a00.w);
            As[nx][ka+16][ca] = f2tf32(a01.x); As[nx][ka+17][ca] = f2tf32(a01.y);
            As[nx][ka+18][ca] = f2tf32(a01.z); As[nx][ka+19][ca] = f2tf32(a01.w);
            As[nx][ka+0][ca1]  = f2tf32(a10.x); As[nx][ka+1][ca1]  = f2tf32(a10.y);
            As[nx][ka+2][ca1]  = f2tf32(a10.z); As[nx][ka+3][ca1]  = f2tf32(a10.w);
            As[nx][ka+16][ca1] = f2tf32(a11.x); As[nx][ka+17][ca1] = f2tf32(a11.y);
            As[nx][ka+18][ca1] = f2tf32(a11.z); As[nx][ka+19][ca1] = f2tf32(a11.w);
            Bs[nx][ka+0][ca]  = f2tf32(b0.x); Bs[nx][ka+1][ca]  = f2tf32(b0.y);
            Bs[nx][ka+2][ca]  = f2tf32(b0.z); Bs[nx][ka+3][ca]  = f2tf32(b0.w);
            Bs[nx][ka+16][ca] = f2tf32(b1.x); Bs[nx][ka+17][ca] = f2tf32(b1.y);
            Bs[nx][ka+18][ca] = f2tf32(b1.z); Bs[nx][ka+19][ca] = f2tf32(b1.w);
        }
        __syncthreads();
    }

    float* Cd; int strideN, cbase;
    if (n0 == 0)       { Cd = Cqk;  strideN = 64;  cbase = 0; }
    else if (n0 < 832) { Cd = Cv;   strideN = Dd;  cbase = n0 - 64; }
    else               { Cd = Cabr; strideN = Dd;  cbase = n0 - 832; }

    #pragma unroll
    for (int mt = 0; mt < 2; mt++) {
        int r0 = m0 + wm*32 + mt*16 + gid;
        #pragma unroll
        for (int nt = 0; nt < 4; nt++) {
            int cc = cbase + wn*32 + nt*8 + tig*2;
            *(float2*)(Cd + (size_t)r0 * strideN + cc)     = make_float2(c[mt][nt][0], c[mt][nt][1]);
            *(float2*)(Cd + (size_t)(r0+8) * strideN + cc) = make_float2(c[mt][nt][2], c[mt][nt][3]);
        }
    }
}

// ======== generic GEMM (BK=32, used for Wo) ========
__global__ __launch_bounds__(256)
void gemm_tc(const float* __restrict__ X, const float* __restrict__ W0,
             float* __restrict__ C, int N)
{
    extern __shared__ float sm[];
    float (*As)[32][136] = (float (*)[32][136])sm;
    float (*Bs)[32][72]  = (float (*)[32][72])(sm + 2*32*136);

    int tid = threadIdx.x;
    int lane = tid & 31, warp = tid >> 5;
    int wm = warp & 3, wn = warp >> 2;
    int gid = lane >> 2, tig = lane & 3;
    int m0 = blockIdx.y * 128, n0 = blockIdx.x * 64;

    float c[2][4][4];
    #pragma unroll
    for (int mt = 0; mt < 2; mt++)
        #pragma unroll
        for (int nt = 0; nt < 4; nt++)
            #pragma unroll
            for (int e = 0; e < 4; e++) c[mt][nt][e] = 0.f;

    int ra = tid >> 2;
    int ka = (tid & 3) * 4;
    int sw = 8 * (tid & 3);
    const float* xp0 = X + (size_t)(m0 + ra) * Kd + ka;
    const float* xp1 = X + (size_t)(m0 + ra + 64) * Kd + ka;
    const float* wp  = W0 + (size_t)(n0 + ra) * Kd + ka;
    int ca = ra ^ sw, ca1 = (ra + 64) ^ sw;

    {
        float4 a00 = *(const float4*)(xp0);
        float4 a01 = *(const float4*)(xp0 + 16);
        float4 a10 = *(const float4*)(xp1);
        float4 a11 = *(const float4*)(xp1 + 16);
        float4 b0  = *(const float4*)(wp);
        float4 b1  = *(const float4*)(wp + 16);
        As[0][ka+0][ca]  = f2tf32(a00.x); As[0][ka+1][ca]  = f2tf32(a00.y);
        As[0][ka+2][ca]  = f2tf32(a00.z); As[0][ka+3][ca]  = f2tf32(a00.w);
        As[0][ka+16][ca] = f2tf32(a01.x); As[0][ka+17][ca] = f2tf32(a01.y);
        As[0][ka+18][ca] = f2tf32(a01.z); As[0][ka+19][ca] = f2tf32(a01.w);
        As[0][ka+0][ca1]  = f2tf32(a10.x); As[0][ka+1][ca1]  = f2tf32(a10.y);
        As[0][ka+2][ca1]  = f2tf32(a10.z); As[0][ka+3][ca1]  = f2tf32(a10.w);
        As[0][ka+16][ca1] = f2tf32(a11.x); As[0][ka+17][ca1] = f2tf32(a11.y);
        As[0][ka+18][ca1] = f2tf32(a11.z); As[0][ka+19][ca1] = f2tf32(a11.w);
        Bs[0][ka+0][ca]  = f2tf32(b0.x); Bs[0][ka+1][ca]  = f2tf32(b0.y);
        Bs[0][ka+2][ca]  = f2tf32(b0.z); Bs[0][ka+3][ca]  = f2tf32(b0.w);
        Bs[0][ka+16][ca] = f2tf32(b1.x); Bs[0][ka+17][ca] = f2tf32(b1.y);
        Bs[0][ka+18][ca] = f2tf32(b1.z); Bs[0][ka+19][ca] = f2tf32(b1.w);
    }
    __syncthreads();

    const int NIT = Kd / 32;
    for (int it = 0; it < NIT; it++) {
        int cur = it & 1;
        float4 a00, a01, a10, a11, b0, b1;
        if (it + 1 < NIT) {
            int k0 = (it + 1) * 32;
            a00 = *(const float4*)(xp0 + k0);
            a01 = *(const float4*)(xp0 + k0 + 16);
            a10 = *(const float4*)(xp1 + k0);
            a11 = *(const float4*)(xp1 + k0 + 16);
            b0  = *(const float4*)(wp  + k0);
            b1  = *(const float4*)(wp  + k0 + 16);
        }
        #pragma unroll
        for (int ks = 0; ks < 32; ks += 8) {
            int swl = 8 * ((ks >> 2) & 3);
            int swh = 8 * (((ks + 4) >> 2) & 3);
            int klo = ks + tig, khi = ks + tig + 4;
            unsigned a[2][4], b[4][2];
            #pragma unroll
            for (int mt = 0; mt < 2; mt++) {
                int mr = wm*32 + mt*16 + gid;
                a[mt][0] = __float_as_uint(As[cur][klo][ mr      ^ swl]);
                a[mt][1] = __float_as_uint(As[cur][klo][(mr + 8) ^ swl]);
                a[mt][2] = __float_as_uint(As[cur][khi][ mr      ^ swh]);
                a[mt][3] = __float_as_uint(As[cur][khi][(mr + 8) ^ swh]);
            }
            #pragma unroll
            for (int nt = 0; nt < 4; nt++) {
                int nc = wn*32 + nt*8 + gid;
                b[nt][0] = __float_as_uint(Bs[cur][klo][nc ^ swl]);
                b[nt][1] = __float_as_uint(Bs[cur][khi][nc ^ swh]);
            }
            #pragma unroll
            for (int mt = 0; mt < 2; mt++)
                #pragma unroll
                for (int nt = 0; nt < 4; nt++)
                    mma_tf32(c[mt][nt], a[mt], b[nt]);
        }
        if (it + 1 < NIT) {
            int nx = cur ^ 1;
            As[nx][ka+0][ca]  = f2tf32(a00.x); As[nx][ka+1][ca]  = f2tf32(a00.y);
            As[nx][ka+2][ca]  = f2tf32(a00.z); As[nx][ka+3][ca]  = f2tf32(a00.w);
            As[nx][ka+16][ca] = f2tf32(a01.x); As[nx][ka+17][ca] = f2tf32(a01.y);
            As[nx][ka+18][ca] = f2tf32(a01.z); As[nx][ka+19][ca] = f2tf32(a01.w);
            As[nx][ka+0][ca1]  = f2tf32(a10.x); As[nx][ka+1][ca1]  = f2tf32(a10.y);
            As[nx][ka+2][ca1]  = f2tf32(a10.z); As[nx][ka+3][ca1]  = f2tf32(a10.w);
            As[nx][ka+16][ca1] = f2tf32(a11.x); As[nx][ka+17][ca1] = f2tf32(a11.y);
            As[nx][ka+18][ca1] = f2tf32(a11.z); As[nx][ka+19][ca1] = f2tf32(a11.w);
            Bs[nx][ka+0][ca]  = f2tf32(b0.x); Bs[nx][ka+1][ca]  = f2tf32(b0.y);
            Bs[nx][ka+2][ca]  = f2tf32(b0.z); Bs[nx][ka+3][ca]  = f2tf32(b0.w);
            Bs[nx][ka+16][ca] = f2tf32(b1.x); Bs[nx][ka+17][ca] = f2tf32(b1.y);
            Bs[nx][ka+18][ca] = f2tf32(b1.z); Bs[nx][ka+19][ca] = f2tf32(b1.w);
        }
        __syncthreads();
    }
    #pragma unroll
    for (int mt = 0; mt < 2; mt++) {
        int r0 = m0 + wm*32 + mt*16 + gid;
        #pragma unroll
        for (int nt = 0; nt < 4; nt++) {
            int cc = n0 + wn*32 + nt*8 + tig*2;
            *(float2*)(C + (size_t)r0 * N + cc)     = make_float2(c[mt][nt][0], c[mt][nt][1]);
            *(float2*)(C + (size_t)(r0+8) * N + cc) = make_float2(c[mt][nt][2], c[mt][nt][3]);
        }
    }
}

// ======== combine v3 (unchanged) ========
__global__ __launch_bounds__(256)
void combine_tc3()
{
    extern __shared__ float dynsm[];
    float (*As)[2][32][72] = (float (*)[2][32][72])dynsm;
    float (*Bs)[2][32][72] = (float (*)[2][32][72])(dynsm + 2*2*32*72);

    int bz = blockIdx.z;
    int b = bz / 3, t = bz % 3;
    const float* Wt = (t == 0) ? g_wap : (t == 1) ? g_wbd : g_wrs;
    int m0 = (int)(gridDim.y - 1 - blockIdx.y) * 64;
    int n0 = blockIdx.x * 64;
    int colbase = t * D3 + n0;

    int tid = threadIdx.x;
    int lane = tid & 31, warp = tid >> 5;
    int wm = warp & 3, wn = warp >> 2;
    int gid = lane >> 2, tig = lane & 3;

    float c[2][4][4];
    #pragma unroll
    for (int p = 0; p < 2; p++)
        #pragma unroll
        for (int nt = 0; nt < 4; nt++)
            #pragma unroll
            for (int e = 0; e < 4; e++) c[p][nt][e] = 0.f;

    int ra = tid >> 2;
    int ka = (tid & 3) * 4;
    int cA = ra ^ (8 * (tid & 3));
    int kb = tid >> 4;
    int nb = (tid & 15) * 4;
    int swb = 8 * ((kb >> 2) & 3);
    int nbs = nb ^ swb;

    const float* aws = g_ws + (size_t)(b*Ss + m0 + ra) * Ss + ka;
    const float* awt = Wt   + (size_t)(b*Ss + m0 + ra) * Ss + ka;
    const float* bpv = g_V   + (size_t)(b*Ss + kb) * Dd + colbase + nb;
    const float* bpt = g_ABR + (size_t)(b*Ss + kb) * Dd + colbase + nb;

    const int NIT = m0/32 + 2;

    {
        float4 a00 = *(const float4*)(aws);
        float4 a01 = *(const float4*)(aws + 16);
        float4 a10 = *(const float4*)(awt);
        float4 a11 = *(const float4*)(awt + 16);
        float4 b00 = *(const float4*)(bpv);
        float4 b01 = *(const float4*)(bpv + (size_t)16 * Dd);
        float4 b10 = *(const float4*)(bpt);
        float4 b11 = *(const float4*)(bpt + (size_t)16 * Dd);
        As[0][0][ka+0][cA] = f2tf32(a00.x); As[0][0][ka+1][cA] = f2tf32(a00.y);
        As[0][0][ka+2][cA] = f2tf32(a00.z); As[0][0][ka+3][cA] = f2tf32(a00.w);
        As[0][0][ka+16][cA] = f2tf32(a01.x); As[0][0][ka+17][cA] = f2tf32(a01.y);
        As[0][0][ka+18][cA] = f2tf32(a01.z); As[0][0][ka+19][cA] = f2tf32(a01.w);
        As[0][1][ka+0][cA] = f2tf32(a10.x); As[0][1][ka+1][cA] = f2tf32(a10.y);
        As[0][1][ka+2][cA] = f2tf32(a10.z); As[0][1][ka+3][cA] = f2tf32(a10.w);
        As[0][1][ka+16][cA] = f2tf32(a11.x); As[0][1][ka+17][cA] = f2tf32(a11.y);
        As[0][1][ka+18][cA] = f2tf32(a11.z); As[0][1][ka+19][cA] = f2tf32(a11.w);
        *(float4*)&Bs[0][0][kb   ][nbs] = make_float4(f2tf32(b00.x), f2tf32(b00.y), f2tf32(b00.z), f2tf32(b00.w));
        *(float4*)&Bs[0][0][kb+16][nbs] = make_float4(f2tf32(b01.x), f2tf32(b01.y), f2tf32(b01.z), f2tf32(b01.w));
        *(float4*)&Bs[0][1][kb   ][nbs] = make_float4(f2tf32(b10.x), f2tf32(b10.y), f2tf32(b10.z), f2tf32(b10.w));
        *(float4*)&Bs[0][1][kb+16][nbs] = make_float4(f2tf32(b11.x), f2tf32(b11.y), f2tf32(b11.z), f2tf32(b11.w));
    }
    __syncthreads();

    for (int it = 0; it < NIT; it++) {
        int cur = it & 1;
        float4 a00, a01, a10, a11, b00, b01, b10, b11;
        if (it + 1 < NIT) {
            int k0 = (it + 1) * 32;
            a00 = *(const float4*)(aws + k0);
            a01 = *(const float4*)(aws + k0 + 16);
            a10 = *(const float4*)(awt + k0);
            a11 = *(const float4*)(awt + k0 + 16);
            b00 = *(const float4*)(bpv + (size_t)k0 * Dd);
            b01 = *(const float4*)(bpv + (size_t)(k0+16) * Dd);
            b10 = *(const float4*)(bpt + (size_t)k0 * Dd);
            b11 = *(const float4*)(bpt + (size_t)(k0+16) * Dd);
        }
        #pragma unroll
        for (int ks = 0; ks < 32; ks += 8) {
            int swl = 8 * ((ks >> 2) & 3);
            int swh = 8 * (((ks + 4) >> 2) & 3);
            int klo = ks + tig, khi = ks + tig + 4;
            int mr = wm*16 + gid;
            #pragma unroll
            for (int p = 0; p < 2; p++) {
                unsigned a[4], bfr[4][2];
                a[0] = __float_as_uint(As[cur][p][klo][ mr      ^ swl]);
                a[1] = __float_as_uint(As[cur][p][klo][(mr + 8) ^ swl]);
                a[2] = __float_as_uint(As[cur][p][khi][ mr      ^ swh]);
                a[3] = __float_as_uint(As[cur][p][khi][(mr + 8) ^ swh]);
                #pragma unroll
                for (int nt = 0; nt < 4; nt++) {
                    int nc = wn*32 + nt*8 + gid;
                    bfr[nt][0] = __float_as_uint(Bs[cur][p][klo][nc ^ swl]);
                    bfr[nt][1] = __float_as_uint(Bs[cur][p][khi][nc ^ swh]);
                }
                #pragma unroll
                for (int nt = 0; nt < 4; nt++)
                    mma_tf32(c[p][nt], a, bfr[nt]);
            }
        }
        if (it + 1 < NIT) {
            int nx = cur ^ 1;
            As[nx][0][ka+0][cA] = f2tf32(a00.x); As[nx][0][ka+1][cA] = f2tf32(a00.y);
            As[nx][0][ka+2][cA] = f2tf32(a00.z); As[nx][0][ka+3][cA] = f2tf32(a00.w);
            As[nx][0][ka+16][cA] = f2tf32(a01.x); As[nx][0][ka+17][cA] = f2tf32(a01.y);
            As[nx][0][ka+18][cA] = f2tf32(a01.z); As[nx][0][ka+19][cA] = f2tf32(a01.w);
            As[nx][1][ka+0][cA] = f2tf32(a10.x); As[nx][1][ka+1][cA] = f2tf32(a10.y);
            As[nx][1][ka+2][cA] = f2tf32(a10.z); As[nx][1][ka+3][cA] = f2tf32(a10.w);
            As[nx][1][ka+16][cA] = f2tf32(a11.x); As[nx][1][ka+17][cA] = f2tf32(a11.y);
            As[nx][1][ka+18][cA] = f2tf32(a11.z); As[nx][1][ka+19][cA] = f2tf32(a11.w);
            *(float4*)&Bs[nx][0][kb   ][nbs] = make_float4(f2tf32(b00.x), f2tf32(b00.y), f2tf32(b00.z), f2tf32(b00.w));
            *(float4*)&Bs[nx][0][kb+16][nbs] = make_float4(f2tf32(b01.x), f2tf32(b01.y), f2tf32(b01.z), f2tf32(b01.w));
            *(float4*)&Bs[nx][1][kb   ][nbs] = make_float4(f2tf32(b10.x), f2tf32(b10.y), f2tf32(b10.z), f2tf32(b10.w));
            *(float4*)&Bs[nx][1][kb+16][nbs] = make_float4(f2tf32(b11.x), f2tf32(b11.y), f2tf32(b11.z), f2tf32(b11.w));
        }
        __syncthreads();
    }

    int r0 = m0 + wm*16 + gid;
    float is0 = g_invden[b*Ss + r0],     it0 = g_invden[(t+1)*BS + b*Ss + r0];
    float is1 = g_invden[b*Ss + r0 + 8], it1 = g_invden[(t+1)*BS + b*Ss + r0 + 8];
    int rg = b*Ss + r0;
    #pragma unroll
    for (int nt = 0; nt < 4; nt++) {
        int cc = colbase + wn*32 + nt*8 + tig*2;
        *(float2*)(g_comb + (size_t)rg * Dd + cc) =
            make_float2(is0*c[0][nt][0] + it0*c[1][nt][0],
                        is0*c[0][nt][1] + it0*c[1][nt][1]);
        *(float2*)(g_comb + (size_t)(rg+8) * Dd + cc) =
            make_float2(is1*c[0][nt][2] + it1*c[1][nt][2],
                        is1*c[0][nt][3] + it1*c[1][nt][3]);
    }
}

// ---------------- merged setup ----------------
__global__ __launch_bounds__(256)
void setup_kernel(const float* __restrict__ vemb, const float* __restrict__ spec,
                  const float* __restrict__ Wspec, const float* __restrict__ adj,
                  const float* __restrict__ vg)
{
    int tid = threadIdx.x;
    if (blockIdx.x == 0) {
        __shared__ float eb[NV*DV];
        __shared__ float adj_s[NV*NV];
        for (int t = tid; t < NV*DV; t += 256) {
            int u = t / DV, d = t % DV;
            float s = vemb[t];
            #pragma unroll
            for (int h = 0; h < 6; h++) s += 0.1f * spec[u*6+h] * Wspec[d*6+h];
            eb[t] = s;
        }
        for (int t = tid; t < NV*NV; t += 256) adj_s[t] = adj[t];
        __syncthreads();
        for (int t = tid; t < NV*DV; t += 256) {
            int v = t / DV, d = t % DV;
            float s = eb[t];
            #pragma unroll 8
            for (int u = 0; u < NV; u++) s += 0.1f * adj_s[u*NV + v] * eb[u*DV + d];
            g_emb2[t] = s;
        }
    } else {
        int v = blockIdx.x - 1;
        float s = 0.f;
        for (int c = tid; c < Dd; c += 256) {
            float x = vg[(size_t)v*Dd + c];
            s += 1.f / (1.f + __expf(-x));
        }
        __shared__ float red[256];
        red[tid] = s; __syncthreads();
        for (int off = 128; off; off >>= 1) {
            if (tid < off) red[tid] += red[tid + off];
            __syncthreads();
        }
        if (tid == 0) g_gm[v] = red[0] * (1.f / Dd);
    }
}

// ---------------- row-persistent attention: vertex-permuted, float4 pi stores ----------------
// Fs logical column c holds vertex vmap(c) = ((c&7)>>1)*16 + (c>>3)*2 + (c&1),
// so each lane (tig) ends up owning 16 CONSECUTIVE vertices [tig*16, tig*16+16).
__global__ __launch_bounds__(256)
void attn_row(float* __restrict__ pi_out)
{
    extern __shared__ float sm[];
    float (*Ks)[256][36] = (float (*)[256][36])sm;   // [2][256][36], raw fp32
    float* Fs = sm + 2*256*36;                        // [32][72], tf32 * log2e, permuted cols

    int i = Ss - 1 - (int)blockIdx.x;
    int b = blockIdx.y;
    int row_g = b*Ss + i;
    size_t rowbase = (size_t)row_g * Ss;
    int tid = threadIdx.x;
    int warp = tid >> 5, lane = tid & 31;
    int gid = lane >> 2, tig = lane & 3;

    __shared__ float q_s[DV];
    __shared__ float gm_s[NV];
    __shared__ float wred[8][4];

    if (tid < DV) q_s[tid] = g_QK[(size_t)row_g*64 + tid];
    if (tid >= 64 && tid < 128) gm_s[tid-64] = g_gm[tid-64];
    __syncthreads();
    const float LOG2E = 1.4426950408889634f;
    for (int t = tid; t < 2048; t += 256) {
        int d = t >> 6, cc = t & 63;
        int v = ((cc & 7) >> 1) * 16 + (cc >> 3) * 2 + (cc & 1);
        Fs[d*72 + cc] = f2tf32(q_s[d] * LOG2E * g_emb2[v*DV + d]);
    }

    float gmr[16];
    #pragma unroll
    for (int q = 0; q < 16; q++) gmr[q] = gm_s[tig*16 + q];

    float bws = 0.f, bap = 0.f, bbd = 0.f, brs = 0.f;
    int ntiles = (i >> 8) + 1;
    int kr = tid >> 3, kq = (tid & 7) * 4;

    #pragma unroll
    for (int pp = 0; pp < 8; pp++) {
        int r = kr + pp*32;
        unsigned dst = smem_u32(&Ks[0][r][kq]);
        CP_ASYNC16(dst, g_QK + (size_t)(b*Ss + r)*64 + 32 + kq);
    }
    CP_COMMIT();

    for (int jt = 0; jt < ntiles; jt++) {
        int j0 = jt * 256;
        int cur = jt & 1;
        CP_WAIT0();
        __syncthreads();

        float c[2][8][4];
        #pragma unroll
        for (int mt = 0; mt < 2; mt++)
            #pragma unroll
            for (int nt = 0; nt < 8; nt++)
                #pragma unroll
                for (int e = 0; e < 4; e++) c[mt][nt][e] = 0.f;

        #pragma unroll
        for (int ks = 0; ks < 32; ks += 8) {
            unsigned a[2][4], bf[8][2];
            #pragma unroll
            for (int mt = 0; mt < 2; mt++) {
                int mr = warp*32 + mt*16 + gid;
                a[mt][0] = __float_as_uint(f2tf32(Ks[cur][mr  ][ks+tig]));
                a[mt][1] = __float_as_uint(f2tf32(Ks[cur][mr+8][ks+tig]));
                a[mt][2] = __float_as_uint(f2tf32(Ks[cur][mr  ][ks+tig+4]));
                a[mt][3] = __float_as_uint(f2tf32(Ks[cur][mr+8][ks+tig+4]));
            }
            #pragma unroll
            for (int nt = 0; nt < 8; nt++) {
                int nc = nt*8 + gid;
                bf[nt][0] = __float_as_uint(Fs[(ks+tig  )*72 + nc]);
                bf[nt][1] = __float_as_uint(Fs[(ks+tig+4)*72 + nc]);
            }
            #pragma unroll
            for (int mt = 0; mt < 2; mt++)
                #pragma unroll
                for (int nt = 0; nt < 8; nt++)
                    mma_tf32(c[mt][nt], a[mt], bf[nt]);
        }

        if (jt + 1 < ntiles) {
            int j0n = (jt + 1) * 256;
            int nx = cur ^ 1;
            #pragma unroll
            for (int pp = 0; pp < 8; pp++) {
                int r = kr + pp*32;
                unsigned dst = smem_u32(&Ks[nx][r][kq]);
                CP_ASYNC16(dst, g_QK + (size_t)(b*Ss + j0n + r)*64 + 32 + kq);
            }
            CP_COMMIT();
        }

        #pragma unroll
        for (int mt = 0; mt < 2; mt++)
        #pragma unroll
        for (int rh = 0; rh < 2; rh++) {
            int j = j0 + warp*32 + mt*16 + rh*8 + gid;
            size_t pair = rowbase + j;
            // lane's value q corresponds to vertex tig*16 + q
            float e[16];
            float sum = 0.f, sg = 0.f, sap = 0.f, sbd = 0.f, srs = 0.f;
            #pragma unroll
            for (int q = 0; q < 16; q++) {
                float ev = exp2f(c[mt][q>>1][rh*2 + (q&1)]);
                e[q] = ev;
                sum += ev;
                sg = fmaf(ev, gmr[q], sg);
                if (q & 1) sap += ev;
                if (q & 2) sbd += ev;
                if (q & 4) srs += ev;
            }
            sum += __shfl_xor_sync(0xffffffffu, sum, 1);
            sum += __shfl_xor_sync(0xffffffffu, sum, 2);
            sg  += __shfl_xor_sync(0xffffffffu, sg , 1);
            sg  += __shfl_xor_sync(0xffffffffu, sg , 2);
            sap += __shfl_xor_sync(0xffffffffu, sap, 1);
            sap += __shfl_xor_sync(0xffffffffu, sap, 2);
            sbd += __shfl_xor_sync(0xffffffffu, sbd, 1);
            sbd += __shfl_xor_sync(0xffffffffu, sbd, 2);
            srs += __shfl_xor_sync(0xffffffffu, srs, 1);
            srs += __shfl_xor_sync(0xffffffffu, srs, 2);

            float4* po4 = (float4*)(pi_out + pair*NV + tig*16);
            if (j > i) {
                float4 z = make_float4(0.f, 0.f, 0.f, 0.f);
                #pragma unroll
                for (int g = 0; g < 4; g++) __stcs(po4 + g, z);
                if (tig == 0) {
                    g_ws[pair] = 0.f; g_wap[pair] = 0.f;
                    g_wbd[pair] = 0.f; g_wrs[pair] = 0.f;
                }
            } else {
                float inv = 1.f / sum;
                #pragma unroll
                for (int g = 0; g < 4; g++)
                    __stcs(po4 + g, make_float4(e[g*4+0]*inv, e[g*4+1]*inv,
                                                e[g*4+2]*inv, e[g*4+3]*inv));
                if (tig == 0) {
                    float ws = sg*inv, ap = sap*inv, bd = sbd*inv, rs = srs*inv;
                    g_ws[pair] = ws; g_wap[pair] = ap; g_wbd[pair] = bd; g_wrs[pair] = rs;
                    bws += ws; bap += ap; bbd += bd; brs += rs;
                }
            }
        }
    }

    {
        int jz0 = ntiles * 256;
        if (jz0 < Ss) {
            float4 z4 = make_float4(0.f,0.f,0.f,0.f);
            float4* base = (float4*)(pi_out + (rowbase + jz0) * NV);
            int n4 = (Ss - jz0) * 16;
            for (int t = tid; t < n4; t += 256) __stcs(base + t, z4);
            for (int j = jz0 + tid; j < Ss; j += 256) {
                size_t p = rowbase + j;
                g_ws[p] = 0.f; g_wap[p] = 0.f; g_wbd[p] = 0.f; g_wrs[p] = 0.f;
            }
        }
    }

    #pragma unroll
    for (int off = 16; off; off >>= 1) {
        bws += __shfl_xor_sync(0xffffffffu, bws, off);
        bap += __shfl_xor_sync(0xffffffffu, bap, off);
        bbd += __shfl_xor_sync(0xffffffffu, bbd, off);
        brs += __shfl_xor_sync(0xffffffffu, brs, off);
    }
    if (lane == 0) {
        wred[warp][0] = bws; wred[warp][1] = bap;
        wred[warp][2] = bbd; wred[warp][3] = brs;
    }
    __syncthreads();
    if (tid < 4) {
        float s = 0.f;
        #pragma unroll
        for (int w = 0; w < 8; w++) s += wred[w][tid];
        if (tid == 0) {
            g_invden[row_g] = 1.f / (s + EPSV);
        } else {
            float d1 = s + EPSV, S2 = s / d1;
            g_invden[tid*BS + row_g] = 1.f / (d1 * (S2 + EPSV));
        }
    }
}

// ---------------- layernorm ----------------
__global__ void ln_kernel(const float* __restrict__ bo, const float* __restrict__ gamma,
                          const float* __restrict__ beta, float* __restrict__ out)
{
    int row = blockIdx.x, tid = threadIdx.x;
    const float* r = g_res + (size_t)row * Dd;
    float v[3];
    float s = 0.f;
    #pragma unroll
    for (int q = 0; q < 3; q++) { int c = tid + q*256; v[q] = r[c] + bo[c]; s += v[q]; }
    __shared__ float red[256];
    __shared__ float mu_s, inv_s;
    red[tid] = s; __syncthreads();
    for (int off = 128; off; off >>= 1) {
        if (tid < off) red[tid] += red[tid + off];
        __syncthreads();
    }
    if (tid == 0) mu_s = red[0] * (1.f / Dd);
    __syncthreads();
    float mu = mu_s;
    float s2 = 0.f;
    #pragma unroll
    for (int q = 0; q < 3; q++) { float d = v[q] - mu; s2 += d*d; }
    __syncthreads();
    red[tid] = s2; __syncthreads();
    for (int off = 128; off; off >>= 1) {
        if (tid < off) red[tid] += red[tid + off];
        __syncthreads();
    }
    if (tid == 0) inv_s = rsqrtf(red[0] * (1.f / Dd) + LNEPS);
    __syncthreads();
    float inv = inv_s;
    #pragma unroll
    for (int q = 0; q < 3; q++) {
        int c = tid + q*256;
        out[(size_t)row*Dd + c] = (v[q] - mu) * inv * gamma[c] + beta[c];
    }
}

// ---------------- launch ----------------
extern "C" void kernel_launch(void* const* d_in, const int* in_sizes, int n_in,
                              void* d_out, int out_size)
{
    const float* x      = (const float*)d_in[0];
    const float* Wq     = (const float*)d_in[2];
    const float* Wk     = (const float*)d_in[3];
    const float* vemb   = (const float*)d_in[4];
    const float* vgates = (const float*)d_in[5];
    const float* Wv     = (const float*)d_in[6];
    const float* Wspec  = (const float*)d_in[7];
    const float* Wa     = (const float*)d_in[8];
    const float* Wb     = (const float*)d_in[9];
    const float* Wr     = (const float*)d_in[10];
    const float* Wo     = (const float*)d_in[11];
    const float* bo     = (const float*)d_in[12];
    const float* gamma  = (const float*)d_in[13];
    const float* beta   = (const float*)d_in[14];
    const float* adj    = (const float*)d_in[15];
    const float* spec   = (const float*)d_in[16];

    float* out    = (float*)d_out;
    float* pi_out = out + NORMED_ELEMS;

    float *pQK, *pV, *pABR, *pComb, *pRes;
    cudaGetSymbolAddress((void**)&pQK,   g_QK);
    cudaGetSymbolAddress((void**)&pV,    g_V);
    cudaGetSymbolAddress((void**)&pABR,  g_ABR);
    cudaGetSymbolAddress((void**)&pComb, g_comb);
    cudaGetSymbolAddress((void**)&pRes,  g_res);

    const int COMBINE_SMEM = 2*2*32*72*4 * 2;          // 73728
    const int GEMM_SMEM    = (2*32*136 + 2*32*72) * 4; // 53248
    const int ATTN_SMEM    = (2*256*36 + 32*72) * 4;   // 82944

    static cudaStream_t s1 = nullptr;
    static cudaEvent_t ev_fork = nullptr, ev_join = nullptr;
    if (!s1) {
        cudaFuncSetAttribute(combine_tc3, cudaFuncAttributeMaxDynamicSharedMemorySize, COMBINE_SMEM);
        cudaFuncSetAttribute(gemm_fused,  cudaFuncAttributeMaxDynamicSharedMemorySize, GEMM_SMEM);
        cudaFuncSetAttribute(gemm_tc,     cudaFuncAttributeMaxDynamicSharedMemorySize, GEMM_SMEM);
        cudaFuncSetAttribute(attn_row,    cudaFuncAttributeMaxDynamicSharedMemorySize, ATTN_SMEM);
        cudaStreamCreateWithFlags(&s1, cudaStreamNonBlocking);
        cudaEventCreateWithFlags(&ev_fork, cudaEventDisableTiming);
        cudaEventCreateWithFlags(&ev_join, cudaEventDisableTiming);
    }

    dim3 thr(256);

    // fork: V/ABR projection on s1 (only needed by combine)
    cudaEventRecord(ev_fork, 0);
    cudaStreamWaitEvent(s1, ev_fork, 0);
    gemm_fused<<<dim3(24, 16), thr, GEMM_SMEM, s1>>>(x, Wq, Wk, Wv, Wa, Wb, Wr,
                                                     pQK, pV, pABR, /*n_off=*/1);
    cudaEventRecord(ev_join, s1);

    // main stream: setup + QK projection + attention
    setup_kernel<<<65, thr>>>(vemb, spec, Wspec, adj, vgates);
    gemm_fused<<<dim3(1, 16), thr, GEMM_SMEM>>>(x, Wq, Wk, Wv, Wa, Wb, Wr,
                                                pQK, pV, pABR, /*n_off=*/0);
    attn_row<<<dim3(Ss, Bb), thr, ATTN_SMEM>>>(pi_out);

    // join: combine needs V/ABR + attn outputs
    cudaStreamWaitEvent(0, ev_join, 0);
    combine_tc3<<<dim3(4, 16, 6), thr, COMBINE_SMEM>>>();

    gemm_tc<<<dim3(12, 16), thr, GEMM_SMEM>>>(pComb, Wo, pRes, Dd);
    ln_kernel<<<BS, 256>>>(bo, gamma, beta, out);
}

// round 14
// speedup vs baseline: 1.0817x; 1.0817x over previous
#include <cuda_runtime.h>

#define Bb 2
#define Ss 1024
#define Dd 768
#define DV 32
#define NV 64
#define D3 256
#define BS (Bb*Ss)
#define Kd 768
#define EPSV 1e-8f
#define LNEPS 1e-5f
#define NORMED_ELEMS ((size_t)Bb*Ss*Dd)

// ---------------- scratch ----------------
__device__ float g_QK[BS*64];
__device__ float g_V[BS*Dd];
__device__ float g_ABR[BS*Dd];
__device__ float g_emb2[NV*DV];
__device__ float g_gm[NV];
__device__ float g_ws [(size_t)BS*Ss];
__device__ float g_wap[(size_t)BS*Ss];
__device__ float g_wbd[(size_t)BS*Ss];
__device__ float g_wrs[(size_t)BS*Ss];
__device__ float g_invden[4*BS];
__device__ float g_comb[BS*Dd];
__device__ float g_res[BS*Dd];

// ---------------- helpers ----------------
__device__ __forceinline__ float f2tf32(float f) {
    unsigned r;
    asm("cvt.rna.tf32.f32 %0, %1;" : "=r"(r) : "f"(f));
    return __uint_as_float(r);
}
__device__ __forceinline__ void mma_tf32(float* c, const unsigned* a, const unsigned* b) {
    asm volatile("mma.sync.aligned.m16n8k8.row.col.f32.tf32.tf32.f32 "
                 "{%0,%1,%2,%3}, {%4,%5,%6,%7}, {%8,%9}, {%0,%1,%2,%3};"
                 : "+f"(c[0]), "+f"(c[1]), "+f"(c[2]), "+f"(c[3])
                 : "r"(a[0]), "r"(a[1]), "r"(a[2]), "r"(a[3]), "r"(b[0]), "r"(b[1]));
}
__device__ __forceinline__ unsigned smem_u32(const void* p) {
    return (unsigned)__cvta_generic_to_shared(p);
}
#define CP_ASYNC16(dst, src) \
    asm volatile("cp.async.ca.shared.global [%0], [%1], 16;" :: "r"(dst), "l"(src))
#define CP_COMMIT() asm volatile("cp.async.commit_group;" ::: "memory")
#define CP_WAIT0()  asm volatile("cp.async.wait_group 0;" ::: "memory")

// ======== zerofill: strict upper triangle of pi + w scalars (no deps) ========
__global__ __launch_bounds__(256)
void zerofill_kernel(float* __restrict__ pi_out)
{
    int i = blockIdx.x, b = blockIdx.y;
    size_t rowbase = (size_t)(b*Ss + i) * Ss;
    int tid = threadIdx.x;
    int j0 = i + 1;
    if (j0 >= Ss) return;
    float4 z4 = make_float4(0.f, 0.f, 0.f, 0.f);
    float4* base = (float4*)(pi_out + (rowbase + j0) * NV);
    int n4 = (Ss - j0) * 16;
    for (int t = tid; t < n4; t += 256) __stcs(base + t, z4);
    for (int j = j0 + tid; j < Ss; j += 256) {
        size_t p = rowbase + j;
        g_ws[p] = 0.f; g_wap[p] = 0.f; g_wbd[p] = 0.f; g_wrs[p] = 0.f;
    }
}

// ======== fused projection GEMM (BK=32, double-buffered, n-offset selectable) ========
__global__ __launch_bounds__(256)
void gemm_fused(const float* __restrict__ X,
                const float* __restrict__ Wq, const float* __restrict__ Wk,
                const float* __restrict__ Wv, const float* __restrict__ Wa,
                const float* __restrict__ Wb, const float* __restrict__ Wr,
                float* __restrict__ Cqk, float* __restrict__ Cv, float* __restrict__ Cabr,
                int n_off)
{
    extern __shared__ float sm[];
    float (*As)[32][136] = (float (*)[32][136])sm;
    float (*Bs)[32][72]  = (float (*)[32][72])(sm + 2*32*136);

    int tid = threadIdx.x;
    int lane = tid & 31, warp = tid >> 5;
    int wm = warp & 3, wn = warp >> 2;
    int gid = lane >> 2, tig = lane & 3;
    int m0 = blockIdx.y * 128, n0 = (blockIdx.x + n_off) * 64;

    float c[2][4][4];
    #pragma unroll
    for (int mt = 0; mt < 2; mt++)
        #pragma unroll
        for (int nt = 0; nt < 4; nt++)
            #pragma unroll
            for (int e = 0; e < 4; e++) c[mt][nt][e] = 0.f;

    int ra = tid >> 2;
    int ka = (tid & 3) * 4;
    int sw = 8 * (tid & 3);
    const float* xp0 = X + (size_t)(m0 + ra) * Kd + ka;
    const float* xp1 = X + (size_t)(m0 + ra + 64) * Kd + ka;
    int rW = n0 + ra;
    const float* wp;
    if      (rW <   32) wp = Wq + (size_t)rW * Kd;
    else if (rW <   64) wp = Wk + (size_t)(rW -   32) * Kd;
    else if (rW <  832) wp = Wv + (size_t)(rW -   64) * Kd;
    else if (rW < 1088) wp = Wa + (size_t)(rW -  832) * Kd;
    else if (rW < 1344) wp = Wb + (size_t)(rW - 1088) * Kd;
    else                wp = Wr + (size_t)(rW - 1344) * Kd;
    wp += ka;

    int ca = ra ^ sw, ca1 = (ra + 64) ^ sw;

    {
        float4 a00 = *(const float4*)(xp0);
        float4 a01 = *(const float4*)(xp0 + 16);
        float4 a10 = *(const float4*)(xp1);
        float4 a11 = *(const float4*)(xp1 + 16);
        float4 b0  = *(const float4*)(wp);
        float4 b1  = *(const float4*)(wp + 16);
        As[0][ka+0][ca]  = f2tf32(a00.x); As[0][ka+1][ca]  = f2tf32(a00.y);
        As[0][ka+2][ca]  = f2tf32(a00.z); As[0][ka+3][ca]  = f2tf32(a00.w);
        As[0][ka+16][ca] = f2tf32(a01.x); As[0][ka+17][ca] = f2tf32(a01.y);
        As[0][ka+18][ca] = f2tf32(a01.z); As[0][ka+19][ca] = f2tf32(a01.w);
        As[0][ka+0][ca1]  = f2tf32(a10.x); As[0][ka+1][ca1]  = f2tf32(a10.y);
        As[0][ka+2][ca1]  = f2tf32(a10.z); As[0][ka+3][ca1]  = f2tf32(a10.w);
        As[0][ka+16][ca1] = f2tf32(a11.x); As[0][ka+17][ca1] = f2tf32(a11.y);
        As[0][ka+18][ca1] = f2tf32(a11.z); As[0][ka+19][ca1] = f2tf32(a11.w);
        Bs[0][ka+0][ca]  = f2tf32(b0.x); Bs[0][ka+1][ca]  = f2tf32(b0.y);
        Bs[0][ka+2][ca]  = f2tf32(b0.z); Bs[0][ka+3][ca]  = f2tf32(b0.w);
        Bs[0][ka+16][ca] = f2tf32(b1.x); Bs[0][ka+17][ca] = f2tf32(b1.y);
        Bs[0][ka+18][ca] = f2tf32(b1.z); Bs[0][ka+19][ca] = f2tf32(b1.w);
    }
    __syncthreads();

    const int NIT = Kd / 32;
    for (int it = 0; it < NIT; it++) {
        int cur = it & 1;
        float4 a00, a01, a10, a11, b0, b1;
        if (it + 1 < NIT) {
            int k0 = (it + 1) * 32;
            a00 = *(const float4*)(xp0 + k0);
            a01 = *(const float4*)(xp0 + k0 + 16);
            a10 = *(const float4*)(xp1 + k0);
            a11 = *(const float4*)(xp1 + k0 + 16);
            b0  = *(const float4*)(wp  + k0);
            b1  = *(const float4*)(wp  + k0 + 16);
        }
        #pragma unroll
        for (int ks = 0; ks < 32; ks += 8) {
            int swl = 8 * ((ks >> 2) & 3);
            int swh = 8 * (((ks + 4) >> 2) & 3);
            int klo = ks + tig, khi = ks + tig + 4;
            unsigned a[2][4], b[4][2];
            #pragma unroll
            for (int mt = 0; mt < 2; mt++) {
                int mr = wm*32 + mt*16 + gid;
                a[mt][0] = __float_as_uint(As[cur][klo][ mr      ^ swl]);
                a[mt][1] = __float_as_uint(As[cur][klo][(mr + 8) ^ swl]);
                a[mt][2] = __float_as_uint(As[cur][khi][ mr      ^ swh]);
                a[mt][3] = __float_as_uint(As[cur][khi][(mr + 8) ^ swh]);
            }
            #pragma unroll
            for (int nt = 0; nt < 4; nt++) {
                int nc = wn*32 + nt*8 + gid;
                b[nt][0] = __float_as_uint(Bs[cur][klo][nc ^ swl]);
                b[nt][1] = __float_as_uint(Bs[cur][khi][nc ^ swh]);
            }
            #pragma unroll
            for (int mt = 0; mt < 2; mt++)
                #pragma unroll
                for (int nt = 0; nt < 4; nt++)
                    mma_tf32(c[mt][nt], a[mt], b[nt]);
        }
        if (it + 1 < NIT) {
            int nx = cur ^ 1;
            As[nx][ka+0][ca]  = f2tf32(a00.x); As[nx][ka+1][ca]  = f2tf32(a00.y);
            As[nx][ka+2][ca]  = f2tf32(a00.z); As[nx][ka+3][ca]  = f2tf32(a00.w);
            As[nx][ka+16][ca] = f2tf32(a01.x); As[nx][ka+17][ca] = f2tf32(a01.y);
            As[nx][ka+18][ca] = f2tf32(a01.z); As[nx][ka+19][ca] = f2tf32(a01.w);
            As[nx][ka+0][ca1]  = f2tf32(a10.x); As[nx][ka+1][ca1]  = f2tf32(a10.y);
            As[nx][ka+2][ca1]  = f2tf32(a10.z); As[nx][ka+3][ca1]  = f2tf32(a10.w);
            As[nx][ka+16][ca1] = f2tf32(a11.x); As[nx][ka+17][ca1] = f2tf32(a11.y);
            As[nx][ka+18][ca1] = f2tf32(a11.z); As[nx][ka+19][ca1] = f2tf32(a11.w);
            Bs[nx][ka+0][ca]  = f2tf32(b0.x); Bs[nx][ka+1][ca]  = f2tf32(b0.y);
            Bs[nx][ka+2][ca]  = f2tf32(b0.z); Bs[nx][ka+3][ca]  = f2tf32(b0.w);
            Bs[nx][ka+16][ca] = f2tf32(b1.x); Bs[nx][ka+17][ca] = f2tf32(b1.y);
            Bs[nx][ka+18][ca] = f2tf32(b1.z); Bs[nx][ka+19][ca] = f2tf32(b1.w);
        }
        __syncthreads();
    }

    float* Cd; int strideN, cbase;
    if (n0 == 0)       { Cd = Cqk;  strideN = 64;  cbase = 0; }
    else if (n0 < 832) { Cd = Cv;   strideN = Dd;  cbase = n0 - 64; }
    else               { Cd = Cabr; strideN = Dd;  cbase = n0 - 832; }

    #pragma unroll
    for (int mt = 0; mt < 2; mt++) {
        int r0 = m0 + wm*32 + mt*16 + gid;
        #pragma unroll
        for (int nt = 0; nt < 4; nt++) {
            int cc = cbase + wn*32 + nt*8 + tig*2;
            *(float2*)(Cd + (size_t)r0 * strideN + cc)     = make_float2(c[mt][nt][0], c[mt][nt][1]);
            *(float2*)(Cd + (size_t)(r0+8) * strideN + cc) = make_float2(c[mt][nt][2], c[mt][nt][3]);
        }
    }
}

// ======== generic GEMM (BK=32, used for Wo) ========
__global__ __launch_bounds__(256)
void gemm_tc(const float* __restrict__ X, const float* __restrict__ W0,
             float* __restrict__ C, int N)
{
    extern __shared__ float sm[];
    float (*As)[32][136] = (float (*)[32][136])sm;
    float (*Bs)[32][72]  = (float (*)[32][72])(sm + 2*32*136);

    int tid = threadIdx.x;
    int lane = tid & 31, warp = tid >> 5;
    int wm = warp & 3, wn = warp >> 2;
    int gid = lane >> 2, tig = lane & 3;
    int m0 = blockIdx.y * 128, n0 = blockIdx.x * 64;

    float c[2][4][4];
    #pragma unroll
    for (int mt = 0; mt < 2; mt++)
        #pragma unroll
        for (int nt = 0; nt < 4; nt++)
            #pragma unroll
            for (int e = 0; e < 4; e++) c[mt][nt][e] = 0.f;

    int ra = tid >> 2;
    int ka = (tid & 3) * 4;
    int sw = 8 * (tid & 3);
    const float* xp0 = X + (size_t)(m0 + ra) * Kd + ka;
    const float* xp1 = X + (size_t)(m0 + ra + 64) * Kd + ka;
    const float* wp  = W0 + (size_t)(n0 + ra) * Kd + ka;
    int ca = ra ^ sw, ca1 = (ra + 64) ^ sw;

    {
        float4 a00 = *(const float4*)(xp0);
        float4 a01 = *(const float4*)(xp0 + 16);
        float4 a10 = *(const float4*)(xp1);
        float4 a11 = *(const float4*)(xp1 + 16);
        float4 b0  = *(const float4*)(wp);
        float4 b1  = *(const float4*)(wp + 16);
        As[0][ka+0][ca]  = f2tf32(a00.x); As[0][ka+1][ca]  = f2tf32(a00.y);
        As[0][ka+2][ca]  = f2tf32(a00.z); As[0][ka+3][ca]  = f2tf32(a00.w);
        As[0][ka+16][ca] = f2tf32(a01.x); As[0][ka+17][ca] = f2tf32(a01.y);
        As[0][ka+18][ca] = f2tf32(a01.z); As[0][ka+19][ca] = f2tf32(a01.w);
        As[0][ka+0][ca1]  = f2tf32(a10.x); As[0][ka+1][ca1]  = f2tf32(a10.y);
        As[0][ka+2][ca1]  = f2tf32(a10.z); As[0][ka+3][ca1]  = f2tf32(a10.w);
        As[0][ka+16][ca1] = f2tf32(a11.x); As[0][ka+17][ca1] = f2tf32(a11.y);
        As[0][ka+18][ca1] = f2tf32(a11.z); As[0][ka+19][ca1] = f2tf32(a11.w);
        Bs[0][ka+0][ca]  = f2tf32(b0.x); Bs[0][ka+1][ca]  = f2tf32(b0.y);
        Bs[0][ka+2][ca]  = f2tf32(b0.z); Bs[0][ka+3][ca]  = f2tf32(b0.w);
        Bs[0][ka+16][ca] = f2tf32(b1.x); Bs[0][ka+17][ca] = f2tf32(b1.y);
        Bs[0][ka+18][ca] = f2tf32(b1.z); Bs[0][ka+19][ca] = f2tf32(b1.w);
    }
    __syncthreads();

    const int NIT = Kd / 32;
    for (int it = 0; it < NIT; it++) {
        int cur = it & 1;
        float4 a00, a01, a10, a11, b0, b1;
        if (it + 1 < NIT) {
            int k0 = (it + 1) * 32;
            a00 = *(const float4*)(xp0 + k0);
            a01 = *(const float4*)(xp0 + k0 + 16);
            a10 = *(const float4*)(xp1 + k0);
            a11 = *(const float4*)(xp1 + k0 + 16);
            b0  = *(const float4*)(wp  + k0);
            b1  = *(const float4*)(wp  + k0 + 16);
        }
        #pragma unroll
        for (int ks = 0; ks < 32; ks += 8) {
            int swl = 8 * ((ks >> 2) & 3);
            int swh = 8 * (((ks + 4) >> 2) & 3);
            int klo = ks + tig, khi = ks + tig + 4;
            unsigned a[2][4], b[4][2];
            #pragma unroll
            for (int mt = 0; mt < 2; mt++) {
                int mr = wm*32 + mt*16 + gid;
                a[mt][0] = __float_as_uint(As[cur][klo][ mr      ^ swl]);
                a[mt][1] = __float_as_uint(As[cur][klo][(mr + 8) ^ swl]);
                a[mt][2] = __float_as_uint(As[cur][khi][ mr      ^ swh]);
                a[mt][3] = __float_as_uint(As[cur][khi][(mr + 8) ^ swh]);
            }
            #pragma unroll
            for (int nt = 0; nt < 4; nt++) {
                int nc = wn*32 + nt*8 + gid;
                b[nt][0] = __float_as_uint(Bs[cur][klo][nc ^ swl]);
                b[nt][1] = __float_as_uint(Bs[cur][khi][nc ^ swh]);
            }
            #pragma unroll
            for (int mt = 0; mt < 2; mt++)
                #pragma unroll
                for (int nt = 0; nt < 4; nt++)
                    mma_tf32(c[mt][nt], a[mt], b[nt]);
        }
        if (it + 1 < NIT) {
            int nx = cur ^ 1;
            As[nx][ka+0][ca]  = f2tf32(a00.x); As[nx][ka+1][ca]  = f2tf32(a00.y);
            As[nx][ka+2][ca]  = f2tf32(a00.z); As[nx][ka+3][ca]  = f2tf32(a00.w);
            As[nx][ka+16][ca] = f2tf32(a01.x); As[nx][ka+17][ca] = f2tf32(a01.y);
            As[nx][ka+18][ca] = f2tf32(a01.z); As[nx][ka+19][ca] = f2tf32(a01.w);
            As[nx][ka+0][ca1]  = f2tf32(a10.x); As[nx][ka+1][ca1]  = f2tf32(a10.y);
            As[nx][ka+2][ca1]  = f2tf32(a10.z); As[nx][ka+3][ca1]  = f2tf32(a10.w);
            As[nx][ka+16][ca1] = f2tf32(a11.x); As[nx][ka+17][ca1] = f2tf32(a11.y);
            As[nx][ka+18][ca1] = f2tf32(a11.z); As[nx][ka+19][ca1] = f2tf32(a11.w);
            Bs[nx][ka+0][ca]  = f2tf32(b0.x); Bs[nx][ka+1][ca]  = f2tf32(b0.y);
            Bs[nx][ka+2][ca]  = f2tf32(b0.z); Bs[nx][ka+3][ca]  = f2tf32(b0.w);
            Bs[nx][ka+16][ca] = f2tf32(b1.x); Bs[nx][ka+17][ca] = f2tf32(b1.y);
            Bs[nx][ka+18][ca] = f2tf32(b1.z); Bs[nx][ka+19][ca] = f2tf32(b1.w);
        }
        __syncthreads();
    }
    #pragma unroll
    for (int mt = 0; mt < 2; mt++) {
        int r0 = m0 + wm*32 + mt*16 + gid;
        #pragma unroll
        for (int nt = 0; nt < 4; nt++) {
            int cc = n0 + wn*32 + nt*8 + tig*2;
            *(float2*)(C + (size_t)r0 * N + cc)     = make_float2(c[mt][nt][0], c[mt][nt][1]);
            *(float2*)(C + (size_t)(r0+8) * N + cc) = make_float2(c[mt][nt][2], c[mt][nt][3]);
        }
    }
}

// ======== combine v3 (unchanged) ========
__global__ __launch_bounds__(256)
void combine_tc3()
{
    extern __shared__ float dynsm[];
    float (*As)[2][32][72] = (float (*)[2][32][72])dynsm;
    float (*Bs)[2][32][72] = (float (*)[2][32][72])(dynsm + 2*2*32*72);

    int bz = blockIdx.z;
    int b = bz / 3, t = bz % 3;
    const float* Wt = (t == 0) ? g_wap : (t == 1) ? g_wbd : g_wrs;
    int m0 = (int)(gridDim.y - 1 - blockIdx.y) * 64;
    int n0 = blockIdx.x * 64;
    int colbase = t * D3 + n0;

    int tid = threadIdx.x;
    int lane = tid & 31, warp = tid >> 5;
    int wm = warp & 3, wn = warp >> 2;
    int gid = lane >> 2, tig = lane & 3;

    float c[2][4][4];
    #pragma unroll
    for (int p = 0; p < 2; p++)
        #pragma unroll
        for (int nt = 0; nt < 4; nt++)
            #pragma unroll
            for (int e = 0; e < 4; e++) c[p][nt][e] = 0.f;

    int ra = tid >> 2;
    int ka = (tid & 3) * 4;
    int cA = ra ^ (8 * (tid & 3));
    int kb = tid >> 4;
    int nb = (tid & 15) * 4;
    int swb = 8 * ((kb >> 2) & 3);
    int nbs = nb ^ swb;

    const float* aws = g_ws + (size_t)(b*Ss + m0 + ra) * Ss + ka;
    const float* awt = Wt   + (size_t)(b*Ss + m0 + ra) * Ss + ka;
    const float* bpv = g_V   + (size_t)(b*Ss + kb) * Dd + colbase + nb;
    const float* bpt = g_ABR + (size_t)(b*Ss + kb) * Dd + colbase + nb;

    const int NIT = m0/32 + 2;

    {
        float4 a00 = *(const float4*)(aws);
        float4 a01 = *(const float4*)(aws + 16);
        float4 a10 = *(const float4*)(awt);
        float4 a11 = *(const float4*)(awt + 16);
        float4 b00 = *(const float4*)(bpv);
        float4 b01 = *(const float4*)(bpv + (size_t)16 * Dd);
        float4 b10 = *(const float4*)(bpt);
        float4 b11 = *(const float4*)(bpt + (size_t)16 * Dd);
        As[0][0][ka+0][cA] = f2tf32(a00.x); As[0][0][ka+1][cA] = f2tf32(a00.y);
        As[0][0][ka+2][cA] = f2tf32(a00.z); As[0][0][ka+3][cA] = f2tf32(a00.w);
        As[0][0][ka+16][cA] = f2tf32(a01.x); As[0][0][ka+17][cA] = f2tf32(a01.y);
        As[0][0][ka+18][cA] = f2tf32(a01.z); As[0][0][ka+19][cA] = f2tf32(a01.w);
        As[0][1][ka+0][cA] = f2tf32(a10.x); As[0][1][ka+1][cA] = f2tf32(a10.y);
        As[0][1][ka+2][cA] = f2tf32(a10.z); As[0][1][ka+3][cA] = f2tf32(a10.w);
        As[0][1][ka+16][cA] = f2tf32(a11.x); As[0][1][ka+17][cA] = f2tf32(a11.y);
        As[0][1][ka+18][cA] = f2tf32(a11.z); As[0][1][ka+19][cA] = f2tf32(a11.w);
        *(float4*)&Bs[0][0][kb   ][nbs] = make_float4(f2tf32(b00.x), f2tf32(b00.y), f2tf32(b00.z), f2tf32(b00.w));
        *(float4*)&Bs[0][0][kb+16][nbs] = make_float4(f2tf32(b01.x), f2tf32(b01.y), f2tf32(b01.z), f2tf32(b01.w));
        *(float4*)&Bs[0][1][kb   ][nbs] = make_float4(f2tf32(b10.x), f2tf32(b10.y), f2tf32(b10.z), f2tf32(b10.w));
        *(float4*)&Bs[0][1][kb+16][nbs] = make_float4(f2tf32(b11.x), f2tf32(b11.y), f2tf32(b11.z), f2tf32(b11.w));
    }
    __syncthreads();

    for (int it = 0; it < NIT; it++) {
        int cur = it & 1;
        float4 a00, a01, a10, a11, b00, b01, b10, b11;
        if (it + 1 < NIT) {
            int k0 = (it + 1) * 32;
            a00 = *(const float4*)(aws + k0);
            a01 = *(const float4*)(aws + k0 + 16);
            a10 = *(const float4*)(awt + k0);
            a11 = *(const float4*)(awt + k0 + 16);
            b00 = *(const float4*)(bpv + (size_t)k0 * Dd);
            b01 = *(const float4*)(bpv + (size_t)(k0+16) * Dd);
            b10 = *(const float4*)(bpt + (size_t)k0 * Dd);
            b11 = *(const float4*)(bpt + (size_t)(k0+16) * Dd);
        }
        #pragma unroll
        for (int ks = 0; ks < 32; ks += 8) {
            int swl = 8 * ((ks >> 2) & 3);
            int swh = 8 * (((ks + 4) >> 2) & 3);
            int klo = ks + tig, khi = ks + tig + 4;
            int mr = wm*16 + gid;
            #pragma unroll
            for (int p = 0; p < 2; p++) {
                unsigned a[4], bfr[4][2];
                a[0] = __float_as_uint(As[cur][p][klo][ mr      ^ swl]);
                a[1] = __float_as_uint(As[cur][p][klo][(mr + 8) ^ swl]);
                a[2] = __float_as_uint(As[cur][p][khi][ mr      ^ swh]);
                a[3] = __float_as_uint(As[cur][p][khi][(mr + 8) ^ swh]);
                #pragma unroll
                for (int nt = 0; nt < 4; nt++) {
                    int nc = wn*32 + nt*8 + gid;
                    bfr[nt][0] = __float_as_uint(Bs[cur][p][klo][nc ^ swl]);
                    bfr[nt][1] = __float_as_uint(Bs[cur][p][khi][nc ^ swh]);
                }
                #pragma unroll
                for (int nt = 0; nt < 4; nt++)
                    mma_tf32(c[p][nt], a, bfr[nt]);
            }
        }
        if (it + 1 < NIT) {
            int nx = cur ^ 1;
            As[nx][0][ka+0][cA] = f2tf32(a00.x); As[nx][0][ka+1][cA] = f2tf32(a00.y);
            As[nx][0][ka+2][cA] = f2tf32(a00.z); As[nx][0][ka+3][cA] = f2tf32(a00.w);
            As[nx][0][ka+16][cA] = f2tf32(a01.x); As[nx][0][ka+17][cA] = f2tf32(a01.y);
            As[nx][0][ka+18][cA] = f2tf32(a01.z); As[nx][0][ka+19][cA] = f2tf32(a01.w);
            As[nx][1][ka+0][cA] = f2tf32(a10.x); As[nx][1][ka+1][cA] = f2tf32(a10.y);
            As[nx][1][ka+2][cA] = f2tf32(a10.z); As[nx][1][ka+3][cA] = f2tf32(a10.w);
            As[nx][1][ka+16][cA] = f2tf32(a11.x); As[nx][1][ka+17][cA] = f2tf32(a11.y);
            As[nx][1][ka+18][cA] = f2tf32(a11.z); As[nx][1][ka+19][cA] = f2tf32(a11.w);
            *(float4*)&Bs[nx][0][kb   ][nbs] = make_float4(f2tf32(b00.x), f2tf32(b00.y), f2tf32(b00.z), f2tf32(b00.w));
            *(float4*)&Bs[nx][0][kb+16][nbs] = make_float4(f2tf32(b01.x), f2tf32(b01.y), f2tf32(b01.z), f2tf32(b01.w));
            *(float4*)&Bs[nx][1][kb   ][nbs] = make_float4(f2tf32(b10.x), f2tf32(b10.y), f2tf32(b10.z), f2tf32(b10.w));
            *(float4*)&Bs[nx][1][kb+16][nbs] = make_float4(f2tf32(b11.x), f2tf32(b11.y), f2tf32(b11.z), f2tf32(b11.w));
        }
        __syncthreads();
    }

    int r0 = m0 + wm*16 + gid;
    float is0 = g_invden[b*Ss + r0],     it0 = g_invden[(t+1)*BS + b*Ss + r0];
    float is1 = g_invden[b*Ss + r0 + 8], it1 = g_invden[(t+1)*BS + b*Ss + r0 + 8];
    int rg = b*Ss + r0;
    #pragma unroll
    for (int nt = 0; nt < 4; nt++) {
        int cc = colbase + wn*32 + nt*8 + tig*2;
        *(float2*)(g_comb + (size_t)rg * Dd + cc) =
            make_float2(is0*c[0][nt][0] + it0*c[1][nt][0],
                        is0*c[0][nt][1] + it0*c[1][nt][1]);
        *(float2*)(g_comb + (size_t)(rg+8) * Dd + cc) =
            make_float2(is1*c[0][nt][2] + it1*c[1][nt][2],
                        is1*c[0][nt][3] + it1*c[1][nt][3]);
    }
}

// ---------------- merged setup ----------------
__global__ __launch_bounds__(256)
void setup_kernel(const float* __restrict__ vemb, const float* __restrict__ spec,
                  const float* __restrict__ Wspec, const float* __restrict__ adj,
                  const float* __restrict__ vg)
{
    int tid = threadIdx.x;
    if (blockIdx.x == 0) {
        __shared__ float eb[NV*DV];
        __shared__ float adj_s[NV*NV];
        for (int t = tid; t < NV*DV; t += 256) {
            int u = t / DV, d = t % DV;
            float s = vemb[t];
            #pragma unroll
            for (int h = 0; h < 6; h++) s += 0.1f * spec[u*6+h] * Wspec[d*6+h];
            eb[t] = s;
        }
        for (int t = tid; t < NV*NV; t += 256) adj_s[t] = adj[t];
        __syncthreads();
        for (int t = tid; t < NV*DV; t += 256) {
            int v = t / DV, d = t % DV;
            float s = eb[t];
            #pragma unroll 8
            for (int u = 0; u < NV; u++) s += 0.1f * adj_s[u*NV + v] * eb[u*DV + d];
            g_emb2[t] = s;
        }
    } else {
        int v = blockIdx.x - 1;
        float s = 0.f;
        for (int c = tid; c < Dd; c += 256) {
            float x = vg[(size_t)v*Dd + c];
            s += 1.f / (1.f + __expf(-x));
        }
        __shared__ float red[256];
        red[tid] = s; __syncthreads();
        for (int off = 128; off; off >>= 1) {
            if (tid < off) red[tid] += red[tid + off];
            __syncthreads();
        }
        if (tid == 0) g_gm[v] = red[0] * (1.f / Dd);
    }
}

// ---------------- row-persistent attention (round-11 body; causal-only stores) ----------------
__global__ __launch_bounds__(256)
void attn_row(float* __restrict__ pi_out)
{
    extern __shared__ float sm[];
    float (*Ks)[256][36] = (float (*)[256][36])sm;
    float* Fs = sm + 2*256*36;

    int i = Ss - 1 - (int)blockIdx.x;
    int b = blockIdx.y;
    int row_g = b*Ss + i;
    size_t rowbase = (size_t)row_g * Ss;
    int tid = threadIdx.x;
    int warp = tid >> 5, lane = tid & 31;
    int gid = lane >> 2, tig = lane & 3;

    __shared__ float q_s[DV];
    __shared__ float gm_s[NV];
    __shared__ float wred[8][4];

    if (tid < DV) q_s[tid] = g_QK[(size_t)row_g*64 + tid];
    if (tid >= 64 && tid < 128) gm_s[tid-64] = g_gm[tid-64];
    __syncthreads();
    const float LOG2E = 1.4426950408889634f;
    for (int t = tid; t < 2048; t += 256) {
        int d = t >> 6, v = t & 63;
        Fs[d*72 + v] = f2tf32(q_s[d] * LOG2E * g_emb2[v*DV + d]);
    }

    float gmr[16];
    #pragma unroll
    for (int nt = 0; nt < 8; nt++) {
        gmr[nt*2]   = gm_s[nt*8 + tig*2];
        gmr[nt*2+1] = gm_s[nt*8 + tig*2 + 1];
    }

    float bws = 0.f, bap = 0.f, bbd = 0.f, brs = 0.f;
    int ntiles = (i >> 8) + 1;
    int kr = tid >> 3, kq = (tid & 7) * 4;

    #pragma unroll
    for (int pp = 0; pp < 8; pp++) {
        int r = kr + pp*32;
        unsigned dst = smem_u32(&Ks[0][r][kq]);
        CP_ASYNC16(dst, g_QK + (size_t)(b*Ss + r)*64 + 32 + kq);
    }
    CP_COMMIT();

    for (int jt = 0; jt < ntiles; jt++) {
        int j0 = jt * 256;
        int cur = jt & 1;
        CP_WAIT0();
        __syncthreads();

        float c[2][8][4];
        #pragma unroll
        for (int mt = 0; mt < 2; mt++)
            #pragma unroll
            for (int nt = 0; nt < 8; nt++)
                #pragma unroll
                for (int e = 0; e < 4; e++) c[mt][nt][e] = 0.f;

        #pragma unroll
        for (int ks = 0; ks < 32; ks += 8) {
            unsigned a[2][4], bf[8][2];
            #pragma unroll
            for (int mt = 0; mt < 2; mt++) {
                int mr = warp*32 + mt*16 + gid;
                a[mt][0] = __float_as_uint(f2tf32(Ks[cur][mr  ][ks+tig]));
                a[mt][1] = __float_as_uint(f2tf32(Ks[cur][mr+8][ks+tig]));
                a[mt][2] = __float_as_uint(f2tf32(Ks[cur][mr  ][ks+tig+4]));
                a[mt][3] = __float_as_uint(f2tf32(Ks[cur][mr+8][ks+tig+4]));
            }
            #pragma unroll
            for (int nt = 0; nt < 8; nt++) {
                int nc = nt*8 + gid;
                bf[nt][0] = __float_as_uint(Fs[(ks+tig  )*72 + nc]);
                bf[nt][1] = __float_as_uint(Fs[(ks+tig+4)*72 + nc]);
            }
            #pragma unroll
            for (int mt = 0; mt < 2; mt++)
                #pragma unroll
                for (int nt = 0; nt < 8; nt++)
                    mma_tf32(c[mt][nt], a[mt], bf[nt]);
        }

        if (jt + 1 < ntiles) {
            int j0n = (jt + 1) * 256;
            int nx = cur ^ 1;
            #pragma unroll
            for (int pp = 0; pp < 8; pp++) {
                int r = kr + pp*32;
                unsigned dst = smem_u32(&Ks[nx][r][kq]);
                CP_ASYNC16(dst, g_QK + (size_t)(b*Ss + j0n + r)*64 + 32 + kq);
            }
            CP_COMMIT();
        }

        #pragma unroll
        for (int mt = 0; mt < 2; mt++)
        #pragma unroll
        for (int rh = 0; rh < 2; rh++) {
            int j = j0 + warp*32 + mt*16 + rh*8 + gid;
            size_t pair = rowbase + j;
            float e[16];
            float sum = 0.f, sg = 0.f, sap = 0.f;
            #pragma unroll
            for (int q = 0; q < 16; q++) {
                float ev = exp2f(c[mt][q>>1][rh*2 + (q&1)]);
                e[q] = ev;
                sum += ev;
                sg = fmaf(ev, gmr[q], sg);
                if (q & 1) sap += ev;
            }
            float sbd = (tig & 1) ? sum : 0.f;
            float srs = (tig & 2) ? sum : 0.f;
            sum += __shfl_xor_sync(0xffffffffu, sum, 1);
            sum += __shfl_xor_sync(0xffffffffu, sum, 2);
            sg  += __shfl_xor_sync(0xffffffffu, sg , 1);
            sg  += __shfl_xor_sync(0xffffffffu, sg , 2);
            sap += __shfl_xor_sync(0xffffffffu, sap, 1);
            sap += __shfl_xor_sync(0xffffffffu, sap, 2);
            sbd += __shfl_xor_sync(0xffffffffu, sbd, 1);
            sbd += __shfl_xor_sync(0xffffffffu, sbd, 2);
            srs += __shfl_xor_sync(0xffffffffu, srs, 1);
            srs += __shfl_xor_sync(0xffffffffu, srs, 2);

            if (j <= i) {
                float inv = 1.f / sum;
                float* po = pi_out + pair*NV + tig*2;
                #pragma unroll
                for (int nt = 0; nt < 8; nt++)
                    __stcs((float2*)(po + nt*8), make_float2(e[nt*2]*inv, e[nt*2+1]*inv));
                if (tig == 0) {
                    float ws = sg*inv, ap = sap*inv, bd = sbd*inv, rs = srs*inv;
                    g_ws[pair] = ws; g_wap[pair] = ap; g_wbd[pair] = bd; g_wrs[pair] = rs;
                    bws += ws; bap += ap; bbd += bd; brs += rs;
                }
            }
            // j > i handled by zerofill_kernel (disjoint addresses)
        }
    }

    #pragma unroll
    for (int off = 16; off; off >>= 1) {
        bws += __shfl_xor_sync(0xffffffffu, bws, off);
        bap += __shfl_xor_sync(0xffffffffu, bap, off);
        bbd += __shfl_xor_sync(0xffffffffu, bbd, off);
        brs += __shfl_xor_sync(0xffffffffu, brs, off);
    }
    if (lane == 0) {
        wred[warp][0] = bws; wred[warp][1] = bap;
        wred[warp][2] = bbd; wred[warp][3] = brs;
    }
    __syncthreads();
    if (tid < 4) {
        float s = 0.f;
        #pragma unroll
        for (int w = 0; w < 8; w++) s += wred[w][tid];
        if (tid == 0) {
            g_invden[row_g] = 1.f / (s + EPSV);
        } else {
            float d1 = s + EPSV, S2 = s / d1;
            g_invden[tid*BS + row_g] = 1.f / (d1 * (S2 + EPSV));
        }
    }
}

// ---------------- layernorm ----------------
__global__ void ln_kernel(const float* __restrict__ bo, const float* __restrict__ gamma,
                          const float* __restrict__ beta, float* __restrict__ out)
{
    int row = blockIdx.x, tid = threadIdx.x;
    const float* r = g_res + (size_t)row * Dd;
    float v[3];
    float s = 0.f;
    #pragma unroll
    for (int q = 0; q < 3; q++) { int c = tid + q*256; v[q] = r[c] + bo[c]; s += v[q]; }
    __shared__ float red[256];
    __shared__ float mu_s, inv_s;
    red[tid] = s; __syncthreads();
    for (int off = 128; off; off >>= 1) {
        if (tid < off) red[tid] += red[tid + off];
        __syncthreads();
    }
    if (tid == 0) mu_s = red[0] * (1.f / Dd);
    __syncthreads();
    float mu = mu_s;
    float s2 = 0.f;
    #pragma unroll
    for (int q = 0; q < 3; q++) { float d = v[q] - mu; s2 += d*d; }
    __syncthreads();
    red[tid] = s2; __syncthreads();
    for (int off = 128; off; off >>= 1) {
        if (tid < off) red[tid] += red[tid + off];
        __syncthreads();
    }
    if (tid == 0) inv_s = rsqrtf(red[0] * (1.f / Dd) + LNEPS);
    __syncthreads();
    float inv = inv_s;
    #pragma unroll
    for (int q = 0; q < 3; q++) {
        int c = tid + q*256;
        out[(size_t)row*Dd + c] = (v[q] - mu) * inv * gamma[c] + beta[c];
    }
}

// ---------------- launch ----------------
extern "C" void kernel_launch(void* const* d_in, const int* in_sizes, int n_in,
                              void* d_out, int out_size)
{
    const float* x      = (const float*)d_in[0];
    const float* Wq     = (const float*)d_in[2];
    const float* Wk     = (const float*)d_in[3];
    const float* vemb   = (const float*)d_in[4];
    const float* vgates = (const float*)d_in[5];
    const float* Wv     = (const float*)d_in[6];
    const float* Wspec  = (const float*)d_in[7];
    const float* Wa     = (const float*)d_in[8];
    const float* Wb     = (const float*)d_in[9];
    const float* Wr     = (const float*)d_in[10];
    const float* Wo     = (const float*)d_in[11];
    const float* bo     = (const float*)d_in[12];
    const float* gamma  = (const float*)d_in[13];
    const float* beta   = (const float*)d_in[14];
    const float* adj    = (const float*)d_in[15];
    const float* spec   = (const float*)d_in[16];

    float* out    = (float*)d_out;
    float* pi_out = out + NORMED_ELEMS;

    float *pQK, *pV, *pABR, *pComb, *pRes;
    cudaGetSymbolAddress((void**)&pQK,   g_QK);
    cudaGetSymbolAddress((void**)&pV,    g_V);
    cudaGetSymbolAddress((void**)&pABR,  g_ABR);
    cudaGetSymbolAddress((void**)&pComb, g_comb);
    cudaGetSymbolAddress((void**)&pRes,  g_res);

    const int COMBINE_SMEM = 2*2*32*72*4 * 2;          // 73728
    const int GEMM_SMEM    = (2*32*136 + 2*32*72) * 4; // 53248
    const int ATTN_SMEM    = (2*256*36 + 32*72) * 4;   // 82944

    static cudaStream_t s1 = nullptr;
    static cudaEvent_t ev_fork = nullptr, ev_join = nullptr;
    if (!s1) {
        cudaFuncSetAttribute(combine_tc3, cudaFuncAttributeMaxDynamicSharedMemorySize, COMBINE_SMEM);
        cudaFuncSetAttribute(gemm_fused,  cudaFuncAttributeMaxDynamicSharedMemorySize, GEMM_SMEM);
        cudaFuncSetAttribute(gemm_tc,     cudaFuncAttributeMaxDynamicSharedMemorySize, GEMM_SMEM);
        cudaFuncSetAttribute(attn_row,    cudaFuncAttributeMaxDynamicSharedMemorySize, ATTN_SMEM);
        cudaStreamCreateWithFlags(&s1, cudaStreamNonBlocking);
        cudaEventCreateWithFlags(&ev_fork, cudaEventDisableTiming);
        cudaEventCreateWithFlags(&ev_join, cudaEventDisableTiming);
    }

    dim3 thr(256);

    // fork: zerofill (no deps) + V/ABR projection on s1
    cudaEventRecord(ev_fork, 0);
    cudaStreamWaitEvent(s1, ev_fork, 0);
    zerofill_kernel<<<dim3(Ss, Bb), thr, 0, s1>>>(pi_out);
    gemm_fused<<<dim3(24, 16), thr, GEMM_SMEM, s1>>>(x, Wq, Wk, Wv, Wa, Wb, Wr,
                                                     pQK, pV, pABR, /*n_off=*/1);
    cudaEventRecord(ev_join, s1);

    // main stream: setup + QK projection + attention (causal stores only)
    setup_kernel<<<65, thr>>>(vemb, spec, Wspec, adj, vgates);
    gemm_fused<<<dim3(1, 16), thr, GEMM_SMEM>>>(x, Wq, Wk, Wv, Wa, Wb, Wr,
                                                pQK, pV, pABR, /*n_off=*/0);
    attn_row<<<dim3(Ss, Bb), thr, ATTN_SMEM>>>(pi_out);

    // join: combine needs V/ABR + attn outputs + zerofilled w-scalars
    cudaStreamWaitEvent(0, ev_join, 0);
    combine_tc3<<<dim3(4, 16, 6), thr, COMBINE_SMEM>>>();

    gemm_tc<<<dim3(12, 16), thr, GEMM_SMEM>>>(pComb, Wo, pRes, Dd);
    ln_kernel<<<BS, 256>>>(bo, gamma, beta, out);
}

// round 15
// speedup vs baseline: 1.0858x; 1.0038x over previous
#include <cuda_runtime.h>

#define Bb 2
#define Ss 1024
#define Dd 768
#define DV 32
#define NV 64
#define D3 256
#define BS (Bb*Ss)
#define Kd 768
#define EPSV 1e-8f
#define LNEPS 1e-5f
#define NORMED_ELEMS ((size_t)Bb*Ss*Dd)

// ---------------- scratch ----------------
__device__ float g_QK[BS*64];
__device__ float g_QKpart[6][BS*64];
__device__ float g_V[BS*Dd];
__device__ float g_ABR[BS*Dd];
__device__ float g_emb2[NV*DV];
__device__ float g_gm[NV];
__device__ float g_ws [(size_t)BS*Ss];
__device__ float g_wap[(size_t)BS*Ss];
__device__ float g_wbd[(size_t)BS*Ss];
__device__ float g_wrs[(size_t)BS*Ss];
__device__ float g_invden[4*BS];
__device__ float g_comb[BS*Dd];
__device__ float g_res[BS*Dd];

// ---------------- helpers ----------------
__device__ __forceinline__ float f2tf32(float f) {
    unsigned r;
    asm("cvt.rna.tf32.f32 %0, %1;" : "=r"(r) : "f"(f));
    return __uint_as_float(r);
}
__device__ __forceinline__ void mma_tf32(float* c, const unsigned* a, const unsigned* b) {
    asm volatile("mma.sync.aligned.m16n8k8.row.col.f32.tf32.tf32.f32 "
                 "{%0,%1,%2,%3}, {%4,%5,%6,%7}, {%8,%9}, {%0,%1,%2,%3};"
                 : "+f"(c[0]), "+f"(c[1]), "+f"(c[2]), "+f"(c[3])
                 : "r"(a[0]), "r"(a[1]), "r"(a[2]), "r"(a[3]), "r"(b[0]), "r"(b[1]));
}
__device__ __forceinline__ unsigned smem_u32(const void* p) {
    return (unsigned)__cvta_generic_to_shared(p);
}
#define CP_ASYNC16(dst, src) \
    asm volatile("cp.async.ca.shared.global [%0], [%1], 16;" :: "r"(dst), "l"(src))
#define CP_COMMIT() asm volatile("cp.async.commit_group;" ::: "memory")
#define CP_WAIT0()  asm volatile("cp.async.wait_group 0;" ::: "memory")

// ======== zerofill: strict upper triangle of pi + w scalars (no deps) ========
__global__ __launch_bounds__(256)
void zerofill_kernel(float* __restrict__ pi_out)
{
    int i = blockIdx.x, b = blockIdx.y;
    size_t rowbase = (size_t)(b*Ss + i) * Ss;
    int tid = threadIdx.x;
    int j0 = i + 1;
    if (j0 >= Ss) return;
    float4 z4 = make_float4(0.f, 0.f, 0.f, 0.f);
    float4* base = (float4*)(pi_out + (rowbase + j0) * NV);
    int n4 = (Ss - j0) * 16;
    for (int t = tid; t < n4; t += 256) __stcs(base + t, z4);
    for (int j = j0 + tid; j < Ss; j += 256) {
        size_t p = rowbase + j;
        g_ws[p] = 0.f; g_wap[p] = 0.f; g_wbd[p] = 0.f; g_wrs[p] = 0.f;
    }
}

// ======== split-K QK projection: grid (6 kslices, 16 mtiles) ========
__global__ __launch_bounds__(256)
void gemm_qk(const float* __restrict__ X,
             const float* __restrict__ Wq, const float* __restrict__ Wk)
{
    extern __shared__ float sm[];
    float (*As)[32][136] = (float (*)[32][136])sm;
    float (*Bs)[32][72]  = (float (*)[32][72])(sm + 2*32*136);

    int tid = threadIdx.x;
    int lane = tid & 31, warp = tid >> 5;
    int wm = warp & 3, wn = warp >> 2;
    int gid = lane >> 2, tig = lane & 3;
    int m0 = blockIdx.y * 128;
    int kslice = blockIdx.x;
    int kbase = kslice * 128;

    float c[2][4][4];
    #pragma unroll
    for (int mt = 0; mt < 2; mt++)
        #pragma unroll
        for (int nt = 0; nt < 4; nt++)
            #pragma unroll
            for (int e = 0; e < 4; e++) c[mt][nt][e] = 0.f;

    int ra = tid >> 2;
    int ka = (tid & 3) * 4;
    int sw = 8 * (tid & 3);
    const float* xp0 = X + (size_t)(m0 + ra) * Kd + kbase + ka;
    const float* xp1 = X + (size_t)(m0 + ra + 64) * Kd + kbase + ka;
    const float* wp  = (ra < 32) ? (Wq + (size_t)ra * Kd)
                                 : (Wk + (size_t)(ra - 32) * Kd);
    wp += kbase + ka;
    int ca = ra ^ sw, ca1 = (ra + 64) ^ sw;

    {
        float4 a00 = *(const float4*)(xp0);
        float4 a01 = *(const float4*)(xp0 + 16);
        float4 a10 = *(const float4*)(xp1);
        float4 a11 = *(const float4*)(xp1 + 16);
        float4 b0  = *(const float4*)(wp);
        float4 b1  = *(const float4*)(wp + 16);
        As[0][ka+0][ca]  = f2tf32(a00.x); As[0][ka+1][ca]  = f2tf32(a00.y);
        As[0][ka+2][ca]  = f2tf32(a00.z); As[0][ka+3][ca]  = f2tf32(a00.w);
        As[0][ka+16][ca] = f2tf32(a01.x); As[0][ka+17][ca] = f2tf32(a01.y);
        As[0][ka+18][ca] = f2tf32(a01.z); As[0][ka+19][ca] = f2tf32(a01.w);
        As[0][ka+0][ca1]  = f2tf32(a10.x); As[0][ka+1][ca1]  = f2tf32(a10.y);
        As[0][ka+2][ca1]  = f2tf32(a10.z); As[0][ka+3][ca1]  = f2tf32(a10.w);
        As[0][ka+16][ca1] = f2tf32(a11.x); As[0][ka+17][ca1] = f2tf32(a11.y);
        As[0][ka+18][ca1] = f2tf32(a11.z); As[0][ka+19][ca1] = f2tf32(a11.w);
        Bs[0][ka+0][ca]  = f2tf32(b0.x); Bs[0][ka+1][ca]  = f2tf32(b0.y);
        Bs[0][ka+2][ca]  = f2tf32(b0.z); Bs[0][ka+3][ca]  = f2tf32(b0.w);
        Bs[0][ka+16][ca] = f2tf32(b1.x); Bs[0][ka+17][ca] = f2tf32(b1.y);
        Bs[0][ka+18][ca] = f2tf32(b1.z); Bs[0][ka+19][ca] = f2tf32(b1.w);
    }
    __syncthreads();

    const int NIT = 4;   // 128 / 32
    for (int it = 0; it < NIT; it++) {
        int cur = it & 1;
        float4 a00, a01, a10, a11, b0, b1;
        if (it + 1 < NIT) {
            int k0 = (it + 1) * 32;
            a00 = *(const float4*)(xp0 + k0);
            a01 = *(const float4*)(xp0 + k0 + 16);
            a10 = *(const float4*)(xp1 + k0);
            a11 = *(const float4*)(xp1 + k0 + 16);
            b0  = *(const float4*)(wp  + k0);
            b1  = *(const float4*)(wp  + k0 + 16);
        }
        #pragma unroll
        for (int ks = 0; ks < 32; ks += 8) {
            int swl = 8 * ((ks >> 2) & 3);
            int swh = 8 * (((ks + 4) >> 2) & 3);
            int klo = ks + tig, khi = ks + tig + 4;
            unsigned a[2][4], b[4][2];
            #pragma unroll
            for (int mt = 0; mt < 2; mt++) {
                int mr = wm*32 + mt*16 + gid;
                a[mt][0] = __float_as_uint(As[cur][klo][ mr      ^ swl]);
                a[mt][1] = __float_as_uint(As[cur][klo][(mr + 8) ^ swl]);
                a[mt][2] = __float_as_uint(As[cur][khi][ mr      ^ swh]);
                a[mt][3] = __float_as_uint(As[cur][khi][(mr + 8) ^ swh]);
            }
            #pragma unroll
            for (int nt = 0; nt < 4; nt++) {
                int nc = wn*32 + nt*8 + gid;
                b[nt][0] = __float_as_uint(Bs[cur][klo][nc ^ swl]);
                b[nt][1] = __float_as_uint(Bs[cur][khi][nc ^ swh]);
            }
            #pragma unroll
            for (int mt = 0; mt < 2; mt++)
                #pragma unroll
                for (int nt = 0; nt < 4; nt++)
                    mma_tf32(c[mt][nt], a[mt], b[nt]);
        }
        if (it + 1 < NIT) {
            int nx = cur ^ 1;
            As[nx][ka+0][ca]  = f2tf32(a00.x); As[nx][ka+1][ca]  = f2tf32(a00.y);
            As[nx][ka+2][ca]  = f2tf32(a00.z); As[nx][ka+3][ca]  = f2tf32(a00.w);
            As[nx][ka+16][ca] = f2tf32(a01.x); As[nx][ka+17][ca] = f2tf32(a01.y);
            As[nx][ka+18][ca] = f2tf32(a01.z); As[nx][ka+19][ca] = f2tf32(a01.w);
            As[nx][ka+0][ca1]  = f2tf32(a10.x); As[nx][ka+1][ca1]  = f2tf32(a10.y);
            As[nx][ka+2][ca1]  = f2tf32(a10.z); As[nx][ka+3][ca1]  = f2tf32(a10.w);
            As[nx][ka+16][ca1] = f2tf32(a11.x); As[nx][ka+17][ca1] = f2tf32(a11.y);
            As[nx][ka+18][ca1] = f2tf32(a11.z); As[nx][ka+19][ca1] = f2tf32(a11.w);
            Bs[nx][ka+0][ca]  = f2tf32(b0.x); Bs[nx][ka+1][ca]  = f2tf32(b0.y);
            Bs[nx][ka+2][ca]  = f2tf32(b0.z); Bs[nx][ka+3][ca]  = f2tf32(b0.w);
            Bs[nx][ka+16][ca] = f2tf32(b1.x); Bs[nx][ka+17][ca] = f2tf32(b1.y);
            Bs[nx][ka+18][ca] = f2tf32(b1.z); Bs[nx][ka+19][ca] = f2tf32(b1.w);
        }
        __syncthreads();
    }

    float* Cd = g_QKpart[kslice];
    #pragma unroll
    for (int mt = 0; mt < 2; mt++) {
        int r0 = m0 + wm*32 + mt*16 + gid;
        #pragma unroll
        for (int nt = 0; nt < 4; nt++) {
            int cc = wn*32 + nt*8 + tig*2;
            *(float2*)(Cd + (size_t)r0 * 64 + cc)     = make_float2(c[mt][nt][0], c[mt][nt][1]);
            *(float2*)(Cd + (size_t)(r0+8) * 64 + cc) = make_float2(c[mt][nt][2], c[mt][nt][3]);
        }
    }
}

// ======== QK split-K reduce ========
__global__ __launch_bounds__(256)
void qk_reduce()
{
    int t = blockIdx.x * 256 + threadIdx.x;   // float4 index, total BS*64/4 = 32768
    float4 s = ((const float4*)g_QKpart[0])[t];
    #pragma unroll
    for (int p = 1; p < 6; p++) {
        float4 v = ((const float4*)g_QKpart[p])[t];
        s.x += v.x; s.y += v.y; s.z += v.z; s.w += v.w;
    }
    ((float4*)g_QK)[t] = s;
}

// ======== fused projection GEMM (BK=32, double-buffered; V/ABR only now) ========
__global__ __launch_bounds__(256)
void gemm_fused(const float* __restrict__ X,
                const float* __restrict__ Wq, const float* __restrict__ Wk,
                const float* __restrict__ Wv, const float* __restrict__ Wa,
                const float* __restrict__ Wb, const float* __restrict__ Wr,
                float* __restrict__ Cqk, float* __restrict__ Cv, float* __restrict__ Cabr,
                int n_off)
{
    extern __shared__ float sm[];
    float (*As)[32][136] = (float (*)[32][136])sm;
    float (*Bs)[32][72]  = (float (*)[32][72])(sm + 2*32*136);

    int tid = threadIdx.x;
    int lane = tid & 31, warp = tid >> 5;
    int wm = warp & 3, wn = warp >> 2;
    int gid = lane >> 2, tig = lane & 3;
    int m0 = blockIdx.y * 128, n0 = (blockIdx.x + n_off) * 64;

    float c[2][4][4];
    #pragma unroll
    for (int mt = 0; mt < 2; mt++)
        #pragma unroll
        for (int nt = 0; nt < 4; nt++)
            #pragma unroll
            for (int e = 0; e < 4; e++) c[mt][nt][e] = 0.f;

    int ra = tid >> 2;
    int ka = (tid & 3) * 4;
    int sw = 8 * (tid & 3);
    const float* xp0 = X + (size_t)(m0 + ra) * Kd + ka;
    const float* xp1 = X + (size_t)(m0 + ra + 64) * Kd + ka;
    int rW = n0 + ra;
    const float* wp;
    if      (rW <   32) wp = Wq + (size_t)rW * Kd;
    else if (rW <   64) wp = Wk + (size_t)(rW -   32) * Kd;
    else if (rW <  832) wp = Wv + (size_t)(rW -   64) * Kd;
    else if (rW < 1088) wp = Wa + (size_t)(rW -  832) * Kd;
    else if (rW < 1344) wp = Wb + (size_t)(rW - 1088) * Kd;
    else                wp = Wr + (size_t)(rW - 1344) * Kd;
    wp += ka;

    int ca = ra ^ sw, ca1 = (ra + 64) ^ sw;

    {
        float4 a00 = *(const float4*)(xp0);
        float4 a01 = *(const float4*)(xp0 + 16);
        float4 a10 = *(const float4*)(xp1);
        float4 a11 = *(const float4*)(xp1 + 16);
        float4 b0  = *(const float4*)(wp);
        float4 b1  = *(const float4*)(wp + 16);
        As[0][ka+0][ca]  = f2tf32(a00.x); As[0][ka+1][ca]  = f2tf32(a00.y);
        As[0][ka+2][ca]  = f2tf32(a00.z); As[0][ka+3][ca]  = f2tf32(a00.w);
        As[0][ka+16][ca] = f2tf32(a01.x); As[0][ka+17][ca] = f2tf32(a01.y);
        As[0][ka+18][ca] = f2tf32(a01.z); As[0][ka+19][ca] = f2tf32(a01.w);
        As[0][ka+0][ca1]  = f2tf32(a10.x); As[0][ka+1][ca1]  = f2tf32(a10.y);
        As[0][ka+2][ca1]  = f2tf32(a10.z); As[0][ka+3][ca1]  = f2tf32(a10.w);
        As[0][ka+16][ca1] = f2tf32(a11.x); As[0][ka+17][ca1] = f2tf32(a11.y);
        As[0][ka+18][ca1] = f2tf32(a11.z); As[0][ka+19][ca1] = f2tf32(a11.w);
        Bs[0][ka+0][ca]  = f2tf32(b0.x); Bs[0][ka+1][ca]  = f2tf32(b0.y);
        Bs[0][ka+2][ca]  = f2tf32(b0.z); Bs[0][ka+3][ca]  = f2tf32(b0.w);
        Bs[0][ka+16][ca] = f2tf32(b1.x); Bs[0][ka+17][ca] = f2tf32(b1.y);
        Bs[0][ka+18][ca] = f2tf32(b1.z); Bs[0][ka+19][ca] = f2tf32(b1.w);
    }
    __syncthreads();

    const int NIT = Kd / 32;
    for (int it = 0; it < NIT; it++) {
        int cur = it & 1;
        float4 a00, a01, a10, a11, b0, b1;
        if (it + 1 < NIT) {
            int k0 = (it + 1) * 32;
            a00 = *(const float4*)(xp0 + k0);
            a01 = *(const float4*)(xp0 + k0 + 16);
            a10 = *(const float4*)(xp1 + k0);
            a11 = *(const float4*)(xp1 + k0 + 16);
            b0  = *(const float4*)(wp  + k0);
            b1  = *(const float4*)(wp  + k0 + 16);
        }
        #pragma unroll
        for (int ks = 0; ks < 32; ks += 8) {
            int swl = 8 * ((ks >> 2) & 3);
            int swh = 8 * (((ks + 4) >> 2) & 3);
            int klo = ks + tig, khi = ks + tig + 4;
            unsigned a[2][4], b[4][2];
            #pragma unroll
            for (int mt = 0; mt < 2; mt++) {
                int mr = wm*32 + mt*16 + gid;
                a[mt][0] = __float_as_uint(As[cur][klo][ mr      ^ swl]);
                a[mt][1] = __float_as_uint(As[cur][klo][(mr + 8) ^ swl]);
                a[mt][2] = __float_as_uint(As[cur][khi][ mr      ^ swh]);
                a[mt][3] = __float_as_uint(As[cur][khi][(mr + 8) ^ swh]);
            }
            #pragma unroll
            for (int nt = 0; nt < 4; nt++) {
                int nc = wn*32 + nt*8 + gid;
                b[nt][0] = __float_as_uint(Bs[cur][klo][nc ^ swl]);
                b[nt][1] = __float_as_uint(Bs[cur][khi][nc ^ swh]);
            }
            #pragma unroll
            for (int mt = 0; mt < 2; mt++)
                #pragma unroll
                for (int nt = 0; nt < 4; nt++)
                    mma_tf32(c[mt][nt], a[mt], b[nt]);
        }
        if (it + 1 < NIT) {
            int nx = cur ^ 1;
            As[nx][ka+0][ca]  = f2tf32(a00.x); As[nx][ka+1][ca]  = f2tf32(a00.y);
            As[nx][ka+2][ca]  = f2tf32(a00.z); As[nx][ka+3][ca]  = f2tf32(a00.w);
            As[nx][ka+16][ca] = f2tf32(a01.x); As[nx][ka+17][ca] = f2tf32(a01.y);
            As[nx][ka+18][ca] = f2tf32(a01.z); As[nx][ka+19][ca] = f2tf32(a01.w);
            As[nx][ka+0][ca1]  = f2tf32(a10.x); As[nx][ka+1][ca1]  = f2tf32(a10.y);
            As[nx][ka+2][ca1]  = f2tf32(a10.z); As[nx][ka+3][ca1]  = f2tf32(a10.w);
            As[nx][ka+16][ca1] = f2tf32(a11.x); As[nx][ka+17][ca1] = f2tf32(a11.y);
            As[nx][ka+18][ca1] = f2tf32(a11.z); As[nx][ka+19][ca1] = f2tf32(a11.w);
            Bs[nx][ka+0][ca]  = f2tf32(b0.x); Bs[nx][ka+1][ca]  = f2tf32(b0.y);
            Bs[nx][ka+2][ca]  = f2tf32(b0.z); Bs[nx][ka+3][ca]  = f2tf32(b0.w);
            Bs[nx][ka+16][ca] = f2tf32(b1.x); Bs[nx][ka+17][ca] = f2tf32(b1.y);
            Bs[nx][ka+18][ca] = f2tf32(b1.z); Bs[nx][ka+19][ca] = f2tf32(b1.w);
        }
        __syncthreads();
    }

    float* Cd; int strideN, cbase;
    if (n0 == 0)       { Cd = Cqk;  strideN = 64;  cbase = 0; }
    else if (n0 < 832) { Cd = Cv;   strideN = Dd;  cbase = n0 - 64; }
    else               { Cd = Cabr; strideN = Dd;  cbase = n0 - 832; }

    #pragma unroll
    for (int mt = 0; mt < 2; mt++) {
        int r0 = m0 + wm*32 + mt*16 + gid;
        #pragma unroll
        for (int nt = 0; nt < 4; nt++) {
            int cc = cbase + wn*32 + nt*8 + tig*2;
            *(float2*)(Cd + (size_t)r0 * strideN + cc)     = make_float2(c[mt][nt][0], c[mt][nt][1]);
            *(float2*)(Cd + (size_t)(r0+8) * strideN + cc) = make_float2(c[mt][nt][2], c[mt][nt][3]);
        }
    }
}

// ======== generic GEMM (BK=32, used for Wo) ========
__global__ __launch_bounds__(256)
void gemm_tc(const float* __restrict__ X, const float* __restrict__ W0,
             float* __restrict__ C, int N)
{
    extern __shared__ float sm[];
    float (*As)[32][136] = (float (*)[32][136])sm;
    float (*Bs)[32][72]  = (float (*)[32][72])(sm + 2*32*136);

    int tid = threadIdx.x;
    int lane = tid & 31, warp = tid >> 5;
    int wm = warp & 3, wn = warp >> 2;
    int gid = lane >> 2, tig = lane & 3;
    int m0 = blockIdx.y * 128, n0 = blockIdx.x * 64;

    float c[2][4][4];
    #pragma unroll
    for (int mt = 0; mt < 2; mt++)
        #pragma unroll
        for (int nt = 0; nt < 4; nt++)
            #pragma unroll
            for (int e = 0; e < 4; e++) c[mt][nt][e] = 0.f;

    int ra = tid >> 2;
    int ka = (tid & 3) * 4;
    int sw = 8 * (tid & 3);
    const float* xp0 = X + (size_t)(m0 + ra) * Kd + ka;
    const float* xp1 = X + (size_t)(m0 + ra + 64) * Kd + ka;
    const float* wp  = W0 + (size_t)(n0 + ra) * Kd + ka;
    int ca = ra ^ sw, ca1 = (ra + 64) ^ sw;

    {
        float4 a00 = *(const float4*)(xp0);
        float4 a01 = *(const float4*)(xp0 + 16);
        float4 a10 = *(const float4*)(xp1);
        float4 a11 = *(const float4*)(xp1 + 16);
        float4 b0  = *(const float4*)(wp);
        float4 b1  = *(const float4*)(wp + 16);
        As[0][ka+0][ca]  = f2tf32(a00.x); As[0][ka+1][ca]  = f2tf32(a00.y);
        As[0][ka+2][ca]  = f2tf32(a00.z); As[0][ka+3][ca]  = f2tf32(a00.w);
        As[0][ka+16][ca] = f2tf32(a01.x); As[0][ka+17][ca] = f2tf32(a01.y);
        As[0][ka+18][ca] = f2tf32(a01.z); As[0][ka+19][ca] = f2tf32(a01.w);
        As[0][ka+0][ca1]  = f2tf32(a10.x); As[0][ka+1][ca1]  = f2tf32(a10.y);
        As[0][ka+2][ca1]  = f2tf32(a10.z); As[0][ka+3][ca1]  = f2tf32(a10.w);
        As[0][ka+16][ca1] = f2tf32(a11.x); As[0][ka+17][ca1] = f2tf32(a11.y);
        As[0][ka+18][ca1] = f2tf32(a11.z); As[0][ka+19][ca1] = f2tf32(a11.w);
        Bs[0][ka+0][ca]  = f2tf32(b0.x); Bs[0][ka+1][ca]  = f2tf32(b0.y);
        Bs[0][ka+2][ca]  = f2tf32(b0.z); Bs[0][ka+3][ca]  = f2tf32(b0.w);
        Bs[0][ka+16][ca] = f2tf32(b1.x); Bs[0][ka+17][ca] = f2tf32(b1.y);
        Bs[0][ka+18][ca] = f2tf32(b1.z); Bs[0][ka+19][ca] = f2tf32(b1.w);
    }
    __syncthreads();

    const int NIT = Kd / 32;
    for (int it = 0; it < NIT; it++) {
        int cur = it & 1;
        float4 a00, a01, a10, a11, b0, b1;
        if (it + 1 < NIT) {
            int k0 = (it + 1) * 32;
            a00 = *(const float4*)(xp0 + k0);
            a01 = *(const float4*)(xp0 + k0 + 16);
            a10 = *(const float4*)(xp1 + k0);
            a11 = *(const float4*)(xp1 + k0 + 16);
            b0  = *(const float4*)(wp  + k0);
            b1  = *(const float4*)(wp  + k0 + 16);
        }
        #pragma unroll
        for (int ks = 0; ks < 32; ks += 8) {
            int swl = 8 * ((ks >> 2) & 3);
            int swh = 8 * (((ks + 4) >> 2) & 3);
            int klo = ks + tig, khi = ks + tig + 4;
            unsigned a[2][4], b[4][2];
            #pragma unroll
            for (int mt = 0; mt < 2; mt++) {
                int mr = wm*32 + mt*16 + gid;
                a[mt][0] = __float_as_uint(As[cur][klo][ mr      ^ swl]);
                a[mt][1] = __float_as_uint(As[cur][klo][(mr + 8) ^ swl]);
                a[mt][2] = __float_as_uint(As[cur][khi][ mr      ^ swh]);
                a[mt][3] = __float_as_uint(As[cur][khi][(mr + 8) ^ swh]);
            }
            #pragma unroll
            for (int nt = 0; nt < 4; nt++) {
                int nc = wn*32 + nt*8 + gid;
                b[nt][0] = __float_as_uint(Bs[cur][klo][nc ^ swl]);
                b[nt][1] = __float_as_uint(Bs[cur][khi][nc ^ swh]);
            }
            #pragma unroll
            for (int mt = 0; mt < 2; mt++)
                #pragma unroll
                for (int nt = 0; nt < 4; nt++)
                    mma_tf32(c[mt][nt], a[mt], b[nt]);
        }
        if (it + 1 < NIT) {
            int nx = cur ^ 1;
            As[nx][ka+0][ca]  = f2tf32(a00.x); As[nx][ka+1][ca]  = f2tf32(a00.y);
            As[nx][ka+2][ca]  = f2tf32(a00.z); As[nx][ka+3][ca]  = f2tf32(a00.w);
            As[nx][ka+16][ca] = f2tf32(a01.x); As[nx][ka+17][ca] = f2tf32(a01.y);
            As[nx][ka+18][ca] = f2tf32(a01.z); As[nx][ka+19][ca] = f2tf32(a01.w);
            As[nx][ka+0][ca1]  = f2tf32(a10.x); As[nx][ka+1][ca1]  = f2tf32(a10.y);
            As[nx][ka+2][ca1]  = f2tf32(a10.z); As[nx][ka+3][ca1]  = f2tf32(a10.w);
            As[nx][ka+16][ca1] = f2tf32(a11.x); As[nx][ka+17][ca1] = f2tf32(a11.y);
            As[nx][ka+18][ca1] = f2tf32(a11.z); As[nx][ka+19][ca1] = f2tf32(a11.w);
            Bs[nx][ka+0][ca]  = f2tf32(b0.x); Bs[nx][ka+1][ca]  = f2tf32(b0.y);
            Bs[nx][ka+2][ca]  = f2tf32(b0.z); Bs[nx][ka+3][ca]  = f2tf32(b0.w);
            Bs[nx][ka+16][ca] = f2tf32(b1.x); Bs[nx][ka+17][ca] = f2tf32(b1.y);
            Bs[nx][ka+18][ca] = f2tf32(b1.z); Bs[nx][ka+19][ca] = f2tf32(b1.w);
        }
        __syncthreads();
    }
    #pragma unroll
    for (int mt = 0; mt < 2; mt++) {
        int r0 = m0 + wm*32 + mt*16 + gid;
        #pragma unroll
        for (int nt = 0; nt < 4; nt++) {
            int cc = n0 + wn*32 + nt*8 + tig*2;
            *(float2*)(C + (size_t)r0 * N + cc)     = make_float2(c[mt][nt][0], c[mt][nt][1]);
            *(float2*)(C + (size_t)(r0+8) * N + cc) = make_float2(c[mt][nt][2], c[mt][nt][3]);
        }
    }
}

// ======== combine v3 (unchanged) ========
__global__ __launch_bounds__(256)
void combine_tc3()
{
    extern __shared__ float dynsm[];
    float (*As)[2][32][72] = (float (*)[2][32][72])dynsm;
    float (*Bs)[2][32][72] = (float (*)[2][32][72])(dynsm + 2*2*32*72);

    int bz = blockIdx.z;
    int b = bz / 3, t = bz % 3;
    const float* Wt = (t == 0) ? g_wap : (t == 1) ? g_wbd : g_wrs;
    int m0 = (int)(gridDim.y - 1 - blockIdx.y) * 64;
    int n0 = blockIdx.x * 64;
    int colbase = t * D3 + n0;

    int tid = threadIdx.x;
    int lane = tid & 31, warp = tid >> 5;
    int wm = warp & 3, wn = warp >> 2;
    int gid = lane >> 2, tig = lane & 3;

    float c[2][4][4];
    #pragma unroll
    for (int p = 0; p < 2; p++)
        #pragma unroll
        for (int nt = 0; nt < 4; nt++)
            #pragma unroll
            for (int e = 0; e < 4; e++) c[p][nt][e] = 0.f;

    int ra = tid >> 2;
    int ka = (tid & 3) * 4;
    int cA = ra ^ (8 * (tid & 3));
    int kb = tid >> 4;
    int nb = (tid & 15) * 4;
    int swb = 8 * ((kb >> 2) & 3);
    int nbs = nb ^ swb;

    const float* aws = g_ws + (size_t)(b*Ss + m0 + ra) * Ss + ka;
    const float* awt = Wt   + (size_t)(b*Ss + m0 + ra) * Ss + ka;
    const float* bpv = g_V   + (size_t)(b*Ss + kb) * Dd + colbase + nb;
    const float* bpt = g_ABR + (size_t)(b*Ss + kb) * Dd + colbase + nb;

    const int NIT = m0/32 + 2;

    {
        float4 a00 = *(const float4*)(aws);
        float4 a01 = *(const float4*)(aws + 16);
        float4 a10 = *(const float4*)(awt);
        float4 a11 = *(const float4*)(awt + 16);
        float4 b00 = *(const float4*)(bpv);
        float4 b01 = *(const float4*)(bpv + (size_t)16 * Dd);
        float4 b10 = *(const float4*)(bpt);
        float4 b11 = *(const float4*)(bpt + (size_t)16 * Dd);
        As[0][0][ka+0][cA] = f2tf32(a00.x); As[0][0][ka+1][cA] = f2tf32(a00.y);
        As[0][0][ka+2][cA] = f2tf32(a00.z); As[0][0][ka+3][cA] = f2tf32(a00.w);
        As[0][0][ka+16][cA] = f2tf32(a01.x); As[0][0][ka+17][cA] = f2tf32(a01.y);
        As[0][0][ka+18][cA] = f2tf32(a01.z); As[0][0][ka+19][cA] = f2tf32(a01.w);
        As[0][1][ka+0][cA] = f2tf32(a10.x); As[0][1][ka+1][cA] = f2tf32(a10.y);
        As[0][1][ka+2][cA] = f2tf32(a10.z); As[0][1][ka+3][cA] = f2tf32(a10.w);
        As[0][1][ka+16][cA] = f2tf32(a11.x); As[0][1][ka+17][cA] = f2tf32(a11.y);
        As[0][1][ka+18][cA] = f2tf32(a11.z); As[0][1][ka+19][cA] = f2tf32(a11.w);
        *(float4*)&Bs[0][0][kb   ][nbs] = make_float4(f2tf32(b00.x), f2tf32(b00.y), f2tf32(b00.z), f2tf32(b00.w));
        *(float4*)&Bs[0][0][kb+16][nbs] = make_float4(f2tf32(b01.x), f2tf32(b01.y), f2tf32(b01.z), f2tf32(b01.w));
        *(float4*)&Bs[0][1][kb   ][nbs] = make_float4(f2tf32(b10.x), f2tf32(b10.y), f2tf32(b10.z), f2tf32(b10.w));
        *(float4*)&Bs[0][1][kb+16][nbs] = make_float4(f2tf32(b11.x), f2tf32(b11.y), f2tf32(b11.z), f2tf32(b11.w));
    }
    __syncthreads();

    for (int it = 0; it < NIT; it++) {
        int cur = it & 1;
        float4 a00, a01, a10, a11, b00, b01, b10, b11;
        if (it + 1 < NIT) {
            int k0 = (it + 1) * 32;
            a00 = *(const float4*)(aws + k0);
            a01 = *(const float4*)(aws + k0 + 16);
            a10 = *(const float4*)(awt + k0);
            a11 = *(const float4*)(awt + k0 + 16);
            b00 = *(const float4*)(bpv + (size_t)k0 * Dd);
            b01 = *(const float4*)(bpv + (size_t)(k0+16) * Dd);
            b10 = *(const float4*)(bpt + (size_t)k0 * Dd);
            b11 = *(const float4*)(bpt + (size_t)(k0+16) * Dd);
        }
        #pragma unroll
        for (int ks = 0; ks < 32; ks += 8) {
            int swl = 8 * ((ks >> 2) & 3);
            int swh = 8 * (((ks + 4) >> 2) & 3);
            int klo = ks + tig, khi = ks + tig + 4;
            int mr = wm*16 + gid;
            #pragma unroll
            for (int p = 0; p < 2; p++) {
                unsigned a[4], bfr[4][2];
                a[0] = __float_as_uint(As[cur][p][klo][ mr      ^ swl]);
                a[1] = __float_as_uint(As[cur][p][klo][(mr + 8) ^ swl]);
                a[2] = __float_as_uint(As[cur][p][khi][ mr      ^ swh]);
                a[3] = __float_as_uint(As[cur][p][khi][(mr + 8) ^ swh]);
                #pragma unroll
                for (int nt = 0; nt < 4; nt++) {
                    int nc = wn*32 + nt*8 + gid;
                    bfr[nt][0] = __float_as_uint(Bs[cur][p][klo][nc ^ swl]);
                    bfr[nt][1] = __float_as_uint(Bs[cur][p][khi][nc ^ swh]);
                }
                #pragma unroll
                for (int nt = 0; nt < 4; nt++)
                    mma_tf32(c[p][nt], a, bfr[nt]);
            }
        }
        if (it + 1 < NIT) {
            int nx = cur ^ 1;
            As[nx][0][ka+0][cA] = f2tf32(a00.x); As[nx][0][ka+1][cA] = f2tf32(a00.y);
            As[nx][0][ka+2][cA] = f2tf32(a00.z); As[nx][0][ka+3][cA] = f2tf32(a00.w);
            As[nx][0][ka+16][cA] = f2tf32(a01.x); As[nx][0][ka+17][cA] = f2tf32(a01.y);
            As[nx][0][ka+18][cA] = f2tf32(a01.z); As[nx][0][ka+19][cA] = f2tf32(a01.w);
            As[nx][1][ka+0][cA] = f2tf32(a10.x); As[nx][1][ka+1][cA] = f2tf32(a10.y);
            As[nx][1][ka+2][cA] = f2tf32(a10.z); As[nx][1][ka+3][cA] = f2tf32(a10.w);
            As[nx][1][ka+16][cA] = f2tf32(a11.x); As[nx][1][ka+17][cA] = f2tf32(a11.y);
            As[nx][1][ka+18][cA] = f2tf32(a11.z); As[nx][1][ka+19][cA] = f2tf32(a11.w);
            *(float4*)&Bs[nx][0][kb   ][nbs] = make_float4(f2tf32(b00.x), f2tf32(b00.y), f2tf32(b00.z), f2tf32(b00.w));
            *(float4*)&Bs[nx][0][kb+16][nbs] = make_float4(f2tf32(b01.x), f2tf32(b01.y), f2tf32(b01.z), f2tf32(b01.w));
            *(float4*)&Bs[nx][1][kb   ][nbs] = make_float4(f2tf32(b10.x), f2tf32(b10.y), f2tf32(b10.z), f2tf32(b10.w));
            *(float4*)&Bs[nx][1][kb+16][nbs] = make_float4(f2tf32(b11.x), f2tf32(b11.y), f2tf32(b11.z), f2tf32(b11.w));
        }
        __syncthreads();
    }

    int r0 = m0 + wm*16 + gid;
    float is0 = g_invden[b*Ss + r0],     it0 = g_invden[(t+1)*BS + b*Ss + r0];
    float is1 = g_invden[b*Ss + r0 + 8], it1 = g_invden[(t+1)*BS + b*Ss + r0 + 8];
    int rg = b*Ss + r0;
    #pragma unroll
    for (int nt = 0; nt < 4; nt++) {
        int cc = colbase + wn*32 + nt*8 + tig*2;
        *(float2*)(g_comb + (size_t)rg * Dd + cc) =
            make_float2(is0*c[0][nt][0] + it0*c[1][nt][0],
                        is0*c[0][nt][1] + it0*c[1][nt][1]);
        *(float2*)(g_comb + (size_t)(rg+8) * Dd + cc) =
            make_float2(is1*c[0][nt][2] + it1*c[1][nt][2],
                        is1*c[0][nt][3] + it1*c[1][nt][3]);
    }
}

// ---------------- merged setup ----------------
__global__ __launch_bounds__(256)
void setup_kernel(const float* __restrict__ vemb, const float* __restrict__ spec,
                  const float* __restrict__ Wspec, const float* __restrict__ adj,
                  const float* __restrict__ vg)
{
    int tid = threadIdx.x;
    if (blockIdx.x == 0) {
        __shared__ float eb[NV*DV];
        __shared__ float adj_s[NV*NV];
        for (int t = tid; t < NV*DV; t += 256) {
            int u = t / DV, d = t % DV;
            float s = vemb[t];
            #pragma unroll
            for (int h = 0; h < 6; h++) s += 0.1f * spec[u*6+h] * Wspec[d*6+h];
            eb[t] = s;
        }
        for (int t = tid; t < NV*NV; t += 256) adj_s[t] = adj[t];
        __syncthreads();
        for (int t = tid; t < NV*DV; t += 256) {
            int v = t / DV, d = t % DV;
            float s = eb[t];
            #pragma unroll 8
            for (int u = 0; u < NV; u++) s += 0.1f * adj_s[u*NV + v] * eb[u*DV + d];
            g_emb2[t] = s;
        }
    } else {
        int v = blockIdx.x - 1;
        float s = 0.f;
        for (int c = tid; c < Dd; c += 256) {
            float x = vg[(size_t)v*Dd + c];
            s += 1.f / (1.f + __expf(-x));
        }
        __shared__ float red[256];
        red[tid] = s; __syncthreads();
        for (int off = 128; off; off >>= 1) {
            if (tid < off) red[tid] += red[tid + off];
            __syncthreads();
        }
        if (tid == 0) g_gm[v] = red[0] * (1.f / Dd);
    }
}

// ---------------- row-persistent attention (causal-only stores) ----------------
__global__ __launch_bounds__(256)
void attn_row(float* __restrict__ pi_out)
{
    extern __shared__ float sm[];
    float (*Ks)[256][36] = (float (*)[256][36])sm;
    float* Fs = sm + 2*256*36;

    int i = Ss - 1 - (int)blockIdx.x;
    int b = blockIdx.y;
    int row_g = b*Ss + i;
    size_t rowbase = (size_t)row_g * Ss;
    int tid = threadIdx.x;
    int warp = tid >> 5, lane = tid & 31;
    int gid = lane >> 2, tig = lane & 3;

    __shared__ float q_s[DV];
    __shared__ float gm_s[NV];
    __shared__ float wred[8][4];

    if (tid < DV) q_s[tid] = g_QK[(size_t)row_g*64 + tid];
    if (tid >= 64 && tid < 128) gm_s[tid-64] = g_gm[tid-64];
    __syncthreads();
    const float LOG2E = 1.4426950408889634f;
    for (int t = tid; t < 2048; t += 256) {
        int d = t >> 6, v = t & 63;
        Fs[d*72 + v] = f2tf32(q_s[d] * LOG2E * g_emb2[v*DV + d]);
    }

    float gmr[16];
    #pragma unroll
    for (int nt = 0; nt < 8; nt++) {
        gmr[nt*2]   = gm_s[nt*8 + tig*2];
        gmr[nt*2+1] = gm_s[nt*8 + tig*2 + 1];
    }

    float bws = 0.f, bap = 0.f, bbd = 0.f, brs = 0.f;
    int ntiles = (i >> 8) + 1;
    int kr = tid >> 3, kq = (tid & 7) * 4;

    #pragma unroll
    for (int pp = 0; pp < 8; pp++) {
        int r = kr + pp*32;
        unsigned dst = smem_u32(&Ks[0][r][kq]);
        CP_ASYNC16(dst, g_QK + (size_t)(b*Ss + r)*64 + 32 + kq);
    }
    CP_COMMIT();

    for (int jt = 0; jt < ntiles; jt++) {
        int j0 = jt * 256;
        int cur = jt & 1;
        CP_WAIT0();
        __syncthreads();

        float c[2][8][4];
        #pragma unroll
        for (int mt = 0; mt < 2; mt++)
            #pragma unroll
            for (int nt = 0; nt < 8; nt++)
                #pragma unroll
                for (int e = 0; e < 4; e++) c[mt][nt][e] = 0.f;

        #pragma unroll
        for (int ks = 0; ks < 32; ks += 8) {
            unsigned a[2][4], bf[8][2];
            #pragma unroll
            for (int mt = 0; mt < 2; mt++) {
                int mr = warp*32 + mt*16 + gid;
                a[mt][0] = __float_as_uint(f2tf32(Ks[cur][mr  ][ks+tig]));
                a[mt][1] = __float_as_uint(f2tf32(Ks[cur][mr+8][ks+tig]));
                a[mt][2] = __float_as_uint(f2tf32(Ks[cur][mr  ][ks+tig+4]));
                a[mt][3] = __float_as_uint(f2tf32(Ks[cur][mr+8][ks+tig+4]));
            }
            #pragma unroll
            for (int nt = 0; nt < 8; nt++) {
                int nc = nt*8 + gid;
                bf[nt][0] = __float_as_uint(Fs[(ks+tig  )*72 + nc]);
                bf[nt][1] = __float_as_uint(Fs[(ks+tig+4)*72 + nc]);
            }
            #pragma unroll
            for (int mt = 0; mt < 2; mt++)
                #pragma unroll
                for (int nt = 0; nt < 8; nt++)
                    mma_tf32(c[mt][nt], a[mt], bf[nt]);
        }

        if (jt + 1 < ntiles) {
            int j0n = (jt + 1) * 256;
            int nx = cur ^ 1;
            #pragma unroll
            for (int pp = 0; pp < 8; pp++) {
                int r = kr + pp*32;
                unsigned dst = smem_u32(&Ks[nx][r][kq]);
                CP_ASYNC16(dst, g_QK + (size_t)(b*Ss + j0n + r)*64 + 32 + kq);
            }
            CP_COMMIT();
        }

        #pragma unroll
        for (int mt = 0; mt < 2; mt++)
        #pragma unroll
        for (int rh = 0; rh < 2; rh++) {
            int j = j0 + warp*32 + mt*16 + rh*8 + gid;
            size_t pair = rowbase + j;
            float e[16];
            float sum = 0.f, sg = 0.f, sap = 0.f;
            #pragma unroll
            for (int q = 0; q < 16; q++) {
                float ev = exp2f(c[mt][q>>1][rh*2 + (q&1)]);
                e[q] = ev;
                sum += ev;
                sg = fmaf(ev, gmr[q], sg);
                if (q & 1) sap += ev;
            }
            float sbd = (tig & 1) ? sum : 0.f;
            float srs = (tig & 2) ? sum : 0.f;
            sum += __shfl_xor_sync(0xffffffffu, sum, 1);
            sum += __shfl_xor_sync(0xffffffffu, sum, 2);
            sg  += __shfl_xor_sync(0xffffffffu, sg , 1);
            sg  += __shfl_xor_sync(0xffffffffu, sg , 2);
            sap += __shfl_xor_sync(0xffffffffu, sap, 1);
            sap += __shfl_xor_sync(0xffffffffu, sap, 2);
            sbd += __shfl_xor_sync(0xffffffffu, sbd, 1);
            sbd += __shfl_xor_sync(0xffffffffu, sbd, 2);
            srs += __shfl_xor_sync(0xffffffffu, srs, 1);
            srs += __shfl_xor_sync(0xffffffffu, srs, 2);

            if (j <= i) {
                float inv = 1.f / sum;
                float* po = pi_out + pair*NV + tig*2;
                #pragma unroll
                for (int nt = 0; nt < 8; nt++)
                    __stcs((float2*)(po + nt*8), make_float2(e[nt*2]*inv, e[nt*2+1]*inv));
                if (tig == 0) {
                    float ws = sg*inv, ap = sap*inv, bd = sbd*inv, rs = srs*inv;
                    g_ws[pair] = ws; g_wap[pair] = ap; g_wbd[pair] = bd; g_wrs[pair] = rs;
                    bws += ws; bap += ap; bbd += bd; brs += rs;
                }
            }
        }
    }

    #pragma unroll
    for (int off = 16; off; off >>= 1) {
        bws += __shfl_xor_sync(0xffffffffu, bws, off);
        bap += __shfl_xor_sync(0xffffffffu, bap, off);
        bbd += __shfl_xor_sync(0xffffffffu, bbd, off);
        brs += __shfl_xor_sync(0xffffffffu, brs, off);
    }
    if (lane == 0) {
        wred[warp][0] = bws; wred[warp][1] = bap;
        wred[warp][2] = bbd; wred[warp][3] = brs;
    }
    __syncthreads();
    if (tid < 4) {
        float s = 0.f;
        #pragma unroll
        for (int w = 0; w < 8; w++) s += wred[w][tid];
        if (tid == 0) {
            g_invden[row_g] = 1.f / (s + EPSV);
        } else {
            float d1 = s + EPSV, S2 = s / d1;
            g_invden[tid*BS + row_g] = 1.f / (d1 * (S2 + EPSV));
        }
    }
}

// ---------------- layernorm ----------------
__global__ void ln_kernel(const float* __restrict__ bo, const float* __restrict__ gamma,
                          const float* __restrict__ beta, float* __restrict__ out)
{
    int row = blockIdx.x, tid = threadIdx.x;
    const float* r = g_res + (size_t)row * Dd;
    float v[3];
    float s = 0.f;
    #pragma unroll
    for (int q = 0; q < 3; q++) { int c = tid + q*256; v[q] = r[c] + bo[c]; s += v[q]; }
    __shared__ float red[256];
    __shared__ float mu_s, inv_s;
    red[tid] = s; __syncthreads();
    for (int off = 128; off; off >>= 1) {
        if (tid < off) red[tid] += red[tid + off];
        __syncthreads();
    }
    if (tid == 0) mu_s = red[0] * (1.f / Dd);
    __syncthreads();
    float mu = mu_s;
    float s2 = 0.f;
    #pragma unroll
    for (int q = 0; q < 3; q++) { float d = v[q] - mu; s2 += d*d; }
    __syncthreads();
    red[tid] = s2; __syncthreads();
    for (int off = 128; off; off >>= 1) {
        if (tid < off) red[tid] += red[tid + off];
        __syncthreads();
    }
    if (tid == 0) inv_s = rsqrtf(red[0] * (1.f / Dd) + LNEPS);
    __syncthreads();
    float inv = inv_s;
    #pragma unroll
    for (int q = 0; q < 3; q++) {
        int c = tid + q*256;
        out[(size_t)row*Dd + c] = (v[q] - mu) * inv * gamma[c] + beta[c];
    }
}

// ---------------- launch ----------------
extern "C" void kernel_launch(void* const* d_in, const int* in_sizes, int n_in,
                              void* d_out, int out_size)
{
    const float* x      = (const float*)d_in[0];
    const float* Wq     = (const float*)d_in[2];
    const float* Wk     = (const float*)d_in[3];
    const float* vemb   = (const float*)d_in[4];
    const float* vgates = (const float*)d_in[5];
    const float* Wv     = (const float*)d_in[6];
    const float* Wspec  = (const float*)d_in[7];
    const float* Wa     = (const float*)d_in[8];
    const float* Wb     = (const float*)d_in[9];
    const float* Wr     = (const float*)d_in[10];
    const float* Wo     = (const float*)d_in[11];
    const float* bo     = (const float*)d_in[12];
    const float* gamma  = (const float*)d_in[13];
    const float* beta   = (const float*)d_in[14];
    const float* adj    = (const float*)d_in[15];
    const float* spec   = (const float*)d_in[16];

    float* out    = (float*)d_out;
    float* pi_out = out + NORMED_ELEMS;

    float *pQK, *pV, *pABR, *pComb, *pRes;
    cudaGetSymbolAddress((void**)&pQK,   g_QK);
    cudaGetSymbolAddress((void**)&pV,    g_V);
    cudaGetSymbolAddress((void**)&pABR,  g_ABR);
    cudaGetSymbolAddress((void**)&pComb, g_comb);
    cudaGetSymbolAddress((void**)&pRes,  g_res);

    const int COMBINE_SMEM = 2*2*32*72*4 * 2;          // 73728
    const int GEMM_SMEM    = (2*32*136 + 2*32*72) * 4; // 53248
    const int ATTN_SMEM    = (2*256*36 + 32*72) * 4;   // 82944

    static cudaStream_t s1 = nullptr;
    static cudaEvent_t ev_fork = nullptr, ev_join = nullptr;
    if (!s1) {
        cudaFuncSetAttribute(combine_tc3, cudaFuncAttributeMaxDynamicSharedMemorySize, COMBINE_SMEM);
        cudaFuncSetAttribute(gemm_fused,  cudaFuncAttributeMaxDynamicSharedMemorySize, GEMM_SMEM);
        cudaFuncSetAttribute(gemm_qk,     cudaFuncAttributeMaxDynamicSharedMemorySize, GEMM_SMEM);
        cudaFuncSetAttribute(gemm_tc,     cudaFuncAttributeMaxDynamicSharedMemorySize, GEMM_SMEM);
        cudaFuncSetAttribute(attn_row,    cudaFuncAttributeMaxDynamicSharedMemorySize, ATTN_SMEM);
        cudaStreamCreateWithFlags(&s1, cudaStreamNonBlocking);
        cudaEventCreateWithFlags(&ev_fork, cudaEventDisableTiming);
        cudaEventCreateWithFlags(&ev_join, cudaEventDisableTiming);
    }

    dim3 thr(256);

    // fork: zerofill (no deps) + V/ABR projection on s1
    cudaEventRecord(ev_fork, 0);
    cudaStreamWaitEvent(s1, ev_fork, 0);
    zerofill_kernel<<<dim3(Ss, Bb), thr, 0, s1>>>(pi_out);
    gemm_fused<<<dim3(24, 16), thr, GEMM_SMEM, s1>>>(x, Wq, Wk, Wv, Wa, Wb, Wr,
                                                     pQK, pV, pABR, /*n_off=*/1);
    cudaEventRecord(ev_join, s1);

    // main stream: split-K QK projection + setup + reduce + attention
    gemm_qk<<<dim3(6, 16), thr, GEMM_SMEM>>>(x, Wq, Wk);
    setup_kernel<<<65, thr>>>(vemb, spec, Wspec, adj, vgates);
    qk_reduce<<<128, thr>>>();
    attn_row<<<dim3(Ss, Bb), thr, ATTN_SMEM>>>(pi_out);

    // join: combine needs V/ABR + attn outputs + zerofilled w-scalars
    cudaStreamWaitEvent(0, ev_join, 0);
    combine_tc3<<<dim3(4, 16, 6), thr, COMBINE_SMEM>>>();

    gemm_tc<<<dim3(12, 16), thr, GEMM_SMEM>>>(pComb, Wo, pRes, Dd);
    ln_kernel<<<BS, 256>>>(bo, gamma, beta, out);
}

// round 16
// speedup vs baseline: 1.0999x; 1.0130x over previous
#include <cuda_runtime.h>

#define Bb 2
#define Ss 1024
#define Dd 768
#define DV 32
#define NV 64
#define D3 256
#define BS (Bb*Ss)
#define Kd 768
#define EPSV 1e-8f
#define LNEPS 1e-5f
#define NORMED_ELEMS ((size_t)Bb*Ss*Dd)

// ---------------- scratch ----------------
__device__ float g_QK[BS*64];
__device__ float g_QKpart[6][BS*64];
__device__ float g_V[BS*Dd];
__device__ float g_ABR[BS*Dd];
__device__ float g_emb2[NV*DV];
__device__ float g_gm[NV];
__device__ float g_ws [(size_t)BS*Ss];
__device__ float g_wap[(size_t)BS*Ss];
__device__ float g_wbd[(size_t)BS*Ss];
__device__ float g_wrs[(size_t)BS*Ss];
__device__ float g_invden[4*BS];
__device__ float g_comb[BS*Dd];
__device__ float g_res[BS*Dd];

// ---------------- helpers ----------------
__device__ __forceinline__ float f2tf32(float f) {
    unsigned r;
    asm("cvt.rna.tf32.f32 %0, %1;" : "=r"(r) : "f"(f));
    return __uint_as_float(r);
}
__device__ __forceinline__ void mma_tf32(float* c, const unsigned* a, const unsigned* b) {
    asm volatile("mma.sync.aligned.m16n8k8.row.col.f32.tf32.tf32.f32 "
                 "{%0,%1,%2,%3}, {%4,%5,%6,%7}, {%8,%9}, {%0,%1,%2,%3};"
                 : "+f"(c[0]), "+f"(c[1]), "+f"(c[2]), "+f"(c[3])
                 : "r"(a[0]), "r"(a[1]), "r"(a[2]), "r"(a[3]), "r"(b[0]), "r"(b[1]));
}
__device__ __forceinline__ unsigned smem_u32(const void* p) {
    return (unsigned)__cvta_generic_to_shared(p);
}
#define CP_ASYNC16(dst, src) \
    asm volatile("cp.async.ca.shared.global [%0], [%1], 16;" :: "r"(dst), "l"(src))
#define CP_COMMIT() asm volatile("cp.async.commit_group;" ::: "memory")
#define CP_WAIT0()  asm volatile("cp.async.wait_group 0;" ::: "memory")

// ======== zerofill: strict upper triangle of pi + w scalars (no deps) ========
__global__ __launch_bounds__(256)
void zerofill_kernel(float* __restrict__ pi_out)
{
    int i = blockIdx.x, b = blockIdx.y;
    size_t rowbase = (size_t)(b*Ss + i) * Ss;
    int tid = threadIdx.x;
    int j0 = i + 1;
    if (j0 >= Ss) return;
    float4 z4 = make_float4(0.f, 0.f, 0.f, 0.f);
    float4* base = (float4*)(pi_out + (rowbase + j0) * NV);
    int n4 = (Ss - j0) * 16;
    for (int t = tid; t < n4; t += 256) __stcs(base + t, z4);
    for (int j = j0 + tid; j < Ss; j += 256) {
        size_t p = rowbase + j;
        g_ws[p] = 0.f; g_wap[p] = 0.f; g_wbd[p] = 0.f; g_wrs[p] = 0.f;
    }
}

// ======== split-K QK projection: grid (6 kslices, 16 mtiles) ========
__global__ __launch_bounds__(256)
void gemm_qk(const float* __restrict__ X,
             const float* __restrict__ Wq, const float* __restrict__ Wk)
{
    extern __shared__ float sm[];
    float (*As)[32][136] = (float (*)[32][136])sm;
    float (*Bs)[32][72]  = (float (*)[32][72])(sm + 2*32*136);

    int tid = threadIdx.x;
    int lane = tid & 31, warp = tid >> 5;
    int wm = warp & 3, wn = warp >> 2;
    int gid = lane >> 2, tig = lane & 3;
    int m0 = blockIdx.y * 128;
    int kslice = blockIdx.x;
    int kbase = kslice * 128;

    float c[2][4][4];
    #pragma unroll
    for (int mt = 0; mt < 2; mt++)
        #pragma unroll
        for (int nt = 0; nt < 4; nt++)
            #pragma unroll
            for (int e = 0; e < 4; e++) c[mt][nt][e] = 0.f;

    int ra = tid >> 2;
    int ka = (tid & 3) * 4;
    int sw = 8 * (tid & 3);
    const float* xp0 = X + (size_t)(m0 + ra) * Kd + kbase + ka;
    const float* xp1 = X + (size_t)(m0 + ra + 64) * Kd + kbase + ka;
    const float* wp  = (ra < 32) ? (Wq + (size_t)ra * Kd)
                                 : (Wk + (size_t)(ra - 32) * Kd);
    wp += kbase + ka;
    int ca = ra ^ sw, ca1 = (ra + 64) ^ sw;

    {
        float4 a00 = *(const float4*)(xp0);
        float4 a01 = *(const float4*)(xp0 + 16);
        float4 a10 = *(const float4*)(xp1);
        float4 a11 = *(const float4*)(xp1 + 16);
        float4 b0  = *(const float4*)(wp);
        float4 b1  = *(const float4*)(wp + 16);
        As[0][ka+0][ca]  = f2tf32(a00.x); As[0][ka+1][ca]  = f2tf32(a00.y);
        As[0][ka+2][ca]  = f2tf32(a00.z); As[0][ka+3][ca]  = f2tf32(a00.w);
        As[0][ka+16][ca] = f2tf32(a01.x); As[0][ka+17][ca] = f2tf32(a01.y);
        As[0][ka+18][ca] = f2tf32(a01.z); As[0][ka+19][ca] = f2tf32(a01.w);
        As[0][ka+0][ca1]  = f2tf32(a10.x); As[0][ka+1][ca1]  = f2tf32(a10.y);
        As[0][ka+2][ca1]  = f2tf32(a10.z); As[0][ka+3][ca1]  = f2tf32(a10.w);
        As[0][ka+16][ca1] = f2tf32(a11.x); As[0][ka+17][ca1] = f2tf32(a11.y);
        As[0][ka+18][ca1] = f2tf32(a11.z); As[0][ka+19][ca1] = f2tf32(a11.w);
        Bs[0][ka+0][ca]  = f2tf32(b0.x); Bs[0][ka+1][ca]  = f2tf32(b0.y);
        Bs[0][ka+2][ca]  = f2tf32(b0.z); Bs[0][ka+3][ca]  = f2tf32(b0.w);
        Bs[0][ka+16][ca] = f2tf32(b1.x); Bs[0][ka+17][ca] = f2tf32(b1.y);
        Bs[0][ka+18][ca] = f2tf32(b1.z); Bs[0][ka+19][ca] = f2tf32(b1.w);
    }
    __syncthreads();

    const int NIT = 4;
    for (int it = 0; it < NIT; it++) {
        int cur = it & 1;
        float4 a00, a01, a10, a11, b0, b1;
        if (it + 1 < NIT) {
            int k0 = (it + 1) * 32;
            a00 = *(const float4*)(xp0 + k0);
            a01 = *(const float4*)(xp0 + k0 + 16);
            a10 = *(const float4*)(xp1 + k0);
            a11 = *(const float4*)(xp1 + k0 + 16);
            b0  = *(const float4*)(wp  + k0);
            b1  = *(const float4*)(wp  + k0 + 16);
        }
        #pragma unroll
        for (int ks = 0; ks < 32; ks += 8) {
            int swl = 8 * ((ks >> 2) & 3);
            int swh = 8 * (((ks + 4) >> 2) & 3);
            int klo = ks + tig, khi = ks + tig + 4;
            unsigned a[2][4], b[4][2];
            #pragma unroll
            for (int mt = 0; mt < 2; mt++) {
                int mr = wm*32 + mt*16 + gid;
                a[mt][0] = __float_as_uint(As[cur][klo][ mr      ^ swl]);
                a[mt][1] = __float_as_uint(As[cur][klo][(mr + 8) ^ swl]);
                a[mt][2] = __float_as_uint(As[cur][khi][ mr      ^ swh]);
                a[mt][3] = __float_as_uint(As[cur][khi][(mr + 8) ^ swh]);
            }
            #pragma unroll
            for (int nt = 0; nt < 4; nt++) {
                int nc = wn*32 + nt*8 + gid;
                b[nt][0] = __float_as_uint(Bs[cur][klo][nc ^ swl]);
                b[nt][1] = __float_as_uint(Bs[cur][khi][nc ^ swh]);
            }
            #pragma unroll
            for (int mt = 0; mt < 2; mt++)
                #pragma unroll
                for (int nt = 0; nt < 4; nt++)
                    mma_tf32(c[mt][nt], a[mt], b[nt]);
        }
        if (it + 1 < NIT) {
            int nx = cur ^ 1;
            As[nx][ka+0][ca]  = f2tf32(a00.x); As[nx][ka+1][ca]  = f2tf32(a00.y);
            As[nx][ka+2][ca]  = f2tf32(a00.z); As[nx][ka+3][ca]  = f2tf32(a00.w);
            As[nx][ka+16][ca] = f2tf32(a01.x); As[nx][ka+17][ca] = f2tf32(a01.y);
            As[nx][ka+18][ca] = f2tf32(a01.z); As[nx][ka+19][ca] = f2tf32(a01.w);
            As[nx][ka+0][ca1]  = f2tf32(a10.x); As[nx][ka+1][ca1]  = f2tf32(a10.y);
            As[nx][ka+2][ca1]  = f2tf32(a10.z); As[nx][ka+3][ca1]  = f2tf32(a10.w);
            As[nx][ka+16][ca1] = f2tf32(a11.x); As[nx][ka+17][ca1] = f2tf32(a11.y);
            As[nx][ka+18][ca1] = f2tf32(a11.z); As[nx][ka+19][ca1] = f2tf32(a11.w);
            Bs[nx][ka+0][ca]  = f2tf32(b0.x); Bs[nx][ka+1][ca]  = f2tf32(b0.y);
            Bs[nx][ka+2][ca]  = f2tf32(b0.z); Bs[nx][ka+3][ca]  = f2tf32(b0.w);
            Bs[nx][ka+16][ca] = f2tf32(b1.x); Bs[nx][ka+17][ca] = f2tf32(b1.y);
            Bs[nx][ka+18][ca] = f2tf32(b1.z); Bs[nx][ka+19][ca] = f2tf32(b1.w);
        }
        __syncthreads();
    }

    float* Cd = g_QKpart[kslice];
    #pragma unroll
    for (int mt = 0; mt < 2; mt++) {
        int r0 = m0 + wm*32 + mt*16 + gid;
        #pragma unroll
        for (int nt = 0; nt < 4; nt++) {
            int cc = wn*32 + nt*8 + tig*2;
            *(float2*)(Cd + (size_t)r0 * 64 + cc)     = make_float2(c[mt][nt][0], c[mt][nt][1]);
            *(float2*)(Cd + (size_t)(r0+8) * 64 + cc) = make_float2(c[mt][nt][2], c[mt][nt][3]);
        }
    }
}

// ======== QK split-K reduce ========
__global__ __launch_bounds__(256)
void qk_reduce()
{
    int t = blockIdx.x * 256 + threadIdx.x;
    float4 s = ((const float4*)g_QKpart[0])[t];
    #pragma unroll
    for (int p = 1; p < 6; p++) {
        float4 v = ((const float4*)g_QKpart[p])[t];
        s.x += v.x; s.y += v.y; s.z += v.z; s.w += v.w;
    }
    ((float4*)g_QK)[t] = s;
}

// ======== fused projection GEMM (BK=32, double-buffered; V/ABR only) ========
__global__ __launch_bounds__(256)
void gemm_fused(const float* __restrict__ X,
                const float* __restrict__ Wq, const float* __restrict__ Wk,
                const float* __restrict__ Wv, const float* __restrict__ Wa,
                const float* __restrict__ Wb, const float* __restrict__ Wr,
                float* __restrict__ Cqk, float* __restrict__ Cv, float* __restrict__ Cabr,
                int n_off)
{
    extern __shared__ float sm[];
    float (*As)[32][136] = (float (*)[32][136])sm;
    float (*Bs)[32][72]  = (float (*)[32][72])(sm + 2*32*136);

    int tid = threadIdx.x;
    int lane = tid & 31, warp = tid >> 5;
    int wm = warp & 3, wn = warp >> 2;
    int gid = lane >> 2, tig = lane & 3;
    int m0 = blockIdx.y * 128, n0 = (blockIdx.x + n_off) * 64;

    float c[2][4][4];
    #pragma unroll
    for (int mt = 0; mt < 2; mt++)
        #pragma unroll
        for (int nt = 0; nt < 4; nt++)
            #pragma unroll
            for (int e = 0; e < 4; e++) c[mt][nt][e] = 0.f;

    int ra = tid >> 2;
    int ka = (tid & 3) * 4;
    int sw = 8 * (tid & 3);
    const float* xp0 = X + (size_t)(m0 + ra) * Kd + ka;
    const float* xp1 = X + (size_t)(m0 + ra + 64) * Kd + ka;
    int rW = n0 + ra;
    const float* wp;
    if      (rW <   32) wp = Wq + (size_t)rW * Kd;
    else if (rW <   64) wp = Wk + (size_t)(rW -   32) * Kd;
    else if (rW <  832) wp = Wv + (size_t)(rW -   64) * Kd;
    else if (rW < 1088) wp = Wa + (size_t)(rW -  832) * Kd;
    else if (rW < 1344) wp = Wb + (size_t)(rW - 1088) * Kd;
    else                wp = Wr + (size_t)(rW - 1344) * Kd;
    wp += ka;

    int ca = ra ^ sw, ca1 = (ra + 64) ^ sw;

    {
        float4 a00 = *(const float4*)(xp0);
        float4 a01 = *(const float4*)(xp0 + 16);
        float4 a10 = *(const float4*)(xp1);
        float4 a11 = *(const float4*)(xp1 + 16);
        float4 b0  = *(const float4*)(wp);
        float4 b1  = *(const float4*)(wp + 16);
        As[0][ka+0][ca]  = f2tf32(a00.x); As[0][ka+1][ca]  = f2tf32(a00.y);
        As[0][ka+2][ca]  = f2tf32(a00.z); As[0][ka+3][ca]  = f2tf32(a00.w);
        As[0][ka+16][ca] = f2tf32(a01.x); As[0][ka+17][ca] = f2tf32(a01.y);
        As[0][ka+18][ca] = f2tf32(a01.z); As[0][ka+19][ca] = f2tf32(a01.w);
        As[0][ka+0][ca1]  = f2tf32(a10.x); As[0][ka+1][ca1]  = f2tf32(a10.y);
        As[0][ka+2][ca1]  = f2tf32(a10.z); As[0][ka+3][ca1]  = f2tf32(a10.w);
        As[0][ka+16][ca1] = f2tf32(a11.x); As[0][ka+17][ca1] = f2tf32(a11.y);
        As[0][ka+18][ca1] = f2tf32(a11.z); As[0][ka+19][ca1] = f2tf32(a11.w);
        Bs[0][ka+0][ca]  = f2tf32(b0.x); Bs[0][ka+1][ca]  = f2tf32(b0.y);
        Bs[0][ka+2][ca]  = f2tf32(b0.z); Bs[0][ka+3][ca]  = f2tf32(b0.w);
        Bs[0][ka+16][ca] = f2tf32(b1.x); Bs[0][ka+17][ca] = f2tf32(b1.y);
        Bs[0][ka+18][ca] = f2tf32(b1.z); Bs[0][ka+19][ca] = f2tf32(b1.w);
    }
    __syncthreads();

    const int NIT = Kd / 32;
    for (int it = 0; it < NIT; it++) {
        int cur = it & 1;
        float4 a00, a01, a10, a11, b0, b1;
        if (it + 1 < NIT) {
            int k0 = (it + 1) * 32;
            a00 = *(const float4*)(xp0 + k0);
            a01 = *(const float4*)(xp0 + k0 + 16);
            a10 = *(const float4*)(xp1 + k0);
            a11 = *(const float4*)(xp1 + k0 + 16);
            b0  = *(const float4*)(wp  + k0);
            b1  = *(const float4*)(wp  + k0 + 16);
        }
        #pragma unroll
        for (int ks = 0; ks < 32; ks += 8) {
            int swl = 8 * ((ks >> 2) & 3);
            int swh = 8 * (((ks + 4) >> 2) & 3);
            int klo = ks + tig, khi = ks + tig + 4;
            unsigned a[2][4], b[4][2];
            #pragma unroll
            for (int mt = 0; mt < 2; mt++) {
                int mr = wm*32 + mt*16 + gid;
                a[mt][0] = __float_as_uint(As[cur][klo][ mr      ^ swl]);
                a[mt][1] = __float_as_uint(As[cur][klo][(mr + 8) ^ swl]);
                a[mt][2] = __float_as_uint(As[cur][khi][ mr      ^ swh]);
                a[mt][3] = __float_as_uint(As[cur][khi][(mr + 8) ^ swh]);
            }
            #pragma unroll
            for (int nt = 0; nt < 4; nt++) {
                int nc = wn*32 + nt*8 + gid;
                b[nt][0] = __float_as_uint(Bs[cur][klo][nc ^ swl]);
                b[nt][1] = __float_as_uint(Bs[cur][khi][nc ^ swh]);
            }
            #pragma unroll
            for (int mt = 0; mt < 2; mt++)
                #pragma unroll
                for (int nt = 0; nt < 4; nt++)
                    mma_tf32(c[mt][nt], a[mt], b[nt]);
        }
        if (it + 1 < NIT) {
            int nx = cur ^ 1;
            As[nx][ka+0][ca]  = f2tf32(a00.x); As[nx][ka+1][ca]  = f2tf32(a00.y);
            As[nx][ka+2][ca]  = f2tf32(a00.z); As[nx][ka+3][ca]  = f2tf32(a00.w);
            As[nx][ka+16][ca] = f2tf32(a01.x); As[nx][ka+17][ca] = f2tf32(a01.y);
            As[nx][ka+18][ca] = f2tf32(a01.z); As[nx][ka+19][ca] = f2tf32(a01.w);
            As[nx][ka+0][ca1]  = f2tf32(a10.x); As[nx][ka+1][ca1]  = f2tf32(a10.y);
            As[nx][ka+2][ca1]  = f2tf32(a10.z); As[nx][ka+3][ca1]  = f2tf32(a10.w);
            As[nx][ka+16][ca1] = f2tf32(a11.x); As[nx][ka+17][ca1] = f2tf32(a11.y);
            As[nx][ka+18][ca1] = f2tf32(a11.z); As[nx][ka+19][ca1] = f2tf32(a11.w);
            Bs[nx][ka+0][ca]  = f2tf32(b0.x); Bs[nx][ka+1][ca]  = f2tf32(b0.y);
            Bs[nx][ka+2][ca]  = f2tf32(b0.z); Bs[nx][ka+3][ca]  = f2tf32(b0.w);
            Bs[nx][ka+16][ca] = f2tf32(b1.x); Bs[nx][ka+17][ca] = f2tf32(b1.y);
            Bs[nx][ka+18][ca] = f2tf32(b1.z); Bs[nx][ka+19][ca] = f2tf32(b1.w);
        }
        __syncthreads();
    }

    float* Cd; int strideN, cbase;
    if (n0 == 0)       { Cd = Cqk;  strideN = 64;  cbase = 0; }
    else if (n0 < 832) { Cd = Cv;   strideN = Dd;  cbase = n0 - 64; }
    else               { Cd = Cabr; strideN = Dd;  cbase = n0 - 832; }

    #pragma unroll
    for (int mt = 0; mt < 2; mt++) {
        int r0 = m0 + wm*32 + mt*16 + gid;
        #pragma unroll
        for (int nt = 0; nt < 4; nt++) {
            int cc = cbase + wn*32 + nt*8 + tig*2;
            *(float2*)(Cd + (size_t)r0 * strideN + cc)     = make_float2(c[mt][nt][0], c[mt][nt][1]);
            *(float2*)(Cd + (size_t)(r0+8) * strideN + cc) = make_float2(c[mt][nt][2], c[mt][nt][3]);
        }
    }
}

// ======== generic GEMM (BK=32, used for Wo) ========
__global__ __launch_bounds__(256)
void gemm_tc(const float* __restrict__ X, const float* __restrict__ W0,
             float* __restrict__ C, int N)
{
    extern __shared__ float sm[];
    float (*As)[32][136] = (float (*)[32][136])sm;
    float (*Bs)[32][72]  = (float (*)[32][72])(sm + 2*32*136);

    int tid = threadIdx.x;
    int lane = tid & 31, warp = tid >> 5;
    int wm = warp & 3, wn = warp >> 2;
    int gid = lane >> 2, tig = lane & 3;
    int m0 = blockIdx.y * 128, n0 = blockIdx.x * 64;

    float c[2][4][4];
    #pragma unroll
    for (int mt = 0; mt < 2; mt++)
        #pragma unroll
        for (int nt = 0; nt < 4; nt++)
            #pragma unroll
            for (int e = 0; e < 4; e++) c[mt][nt][e] = 0.f;

    int ra = tid >> 2;
    int ka = (tid & 3) * 4;
    int sw = 8 * (tid & 3);
    const float* xp0 = X + (size_t)(m0 + ra) * Kd + ka;
    const float* xp1 = X + (size_t)(m0 + ra + 64) * Kd + ka;
    const float* wp  = W0 + (size_t)(n0 + ra) * Kd + ka;
    int ca = ra ^ sw, ca1 = (ra + 64) ^ sw;

    {
        float4 a00 = *(const float4*)(xp0);
        float4 a01 = *(const float4*)(xp0 + 16);
        float4 a10 = *(const float4*)(xp1);
        float4 a11 = *(const float4*)(xp1 + 16);
        float4 b0  = *(const float4*)(wp);
        float4 b1  = *(const float4*)(wp + 16);
        As[0][ka+0][ca]  = f2tf32(a00.x); As[0][ka+1][ca]  = f2tf32(a00.y);
        As[0][ka+2][ca]  = f2tf32(a00.z); As[0][ka+3][ca]  = f2tf32(a00.w);
        As[0][ka+16][ca] = f2tf32(a01.x); As[0][ka+17][ca] = f2tf32(a01.y);
        As[0][ka+18][ca] = f2tf32(a01.z); As[0][ka+19][ca] = f2tf32(a01.w);
        As[0][ka+0][ca1]  = f2tf32(a10.x); As[0][ka+1][ca1]  = f2tf32(a10.y);
        As[0][ka+2][ca1]  = f2tf32(a10.z); As[0][ka+3][ca1]  = f2tf32(a10.w);
        As[0][ka+16][ca1] = f2tf32(a11.x); As[0][ka+17][ca1] = f2tf32(a11.y);
        As[0][ka+18][ca1] = f2tf32(a11.z); As[0][ka+19][ca1] = f2tf32(a11.w);
        Bs[0][ka+0][ca]  = f2tf32(b0.x); Bs[0][ka+1][ca]  = f2tf32(b0.y);
        Bs[0][ka+2][ca]  = f2tf32(b0.z); Bs[0][ka+3][ca]  = f2tf32(b0.w);
        Bs[0][ka+16][ca] = f2tf32(b1.x); Bs[0][ka+17][ca] = f2tf32(b1.y);
        Bs[0][ka+18][ca] = f2tf32(b1.z); Bs[0][ka+19][ca] = f2tf32(b1.w);
    }
    __syncthreads();

    const int NIT = Kd / 32;
    for (int it = 0; it < NIT; it++) {
        int cur = it & 1;
        float4 a00, a01, a10, a11, b0, b1;
        if (it + 1 < NIT) {
            int k0 = (it + 1) * 32;
            a00 = *(const float4*)(xp0 + k0);
            a01 = *(const float4*)(xp0 + k0 + 16);
            a10 = *(const float4*)(xp1 + k0);
            a11 = *(const float4*)(xp1 + k0 + 16);
            b0  = *(const float4*)(wp  + k0);
            b1  = *(const float4*)(wp  + k0 + 16);
        }
        #pragma unroll
        for (int ks = 0; ks < 32; ks += 8) {
            int swl = 8 * ((ks >> 2) & 3);
            int swh = 8 * (((ks + 4) >> 2) & 3);
            int klo = ks + tig, khi = ks + tig + 4;
            unsigned a[2][4], b[4][2];
            #pragma unroll
            for (int mt = 0; mt < 2; mt++) {
                int mr = wm*32 + mt*16 + gid;
                a[mt][0] = __float_as_uint(As[cur][klo][ mr      ^ swl]);
                a[mt][1] = __float_as_uint(As[cur][klo][(mr + 8) ^ swl]);
                a[mt][2] = __float_as_uint(As[cur][khi][ mr      ^ swh]);
                a[mt][3] = __float_as_uint(As[cur][khi][(mr + 8) ^ swh]);
            }
            #pragma unroll
            for (int nt = 0; nt < 4; nt++) {
                int nc = wn*32 + nt*8 + gid;
                b[nt][0] = __float_as_uint(Bs[cur][klo][nc ^ swl]);
                b[nt][1] = __float_as_uint(Bs[cur][khi][nc ^ swh]);
            }
            #pragma unroll
            for (int mt = 0; mt < 2; mt++)
                #pragma unroll
                for (int nt = 0; nt < 4; nt++)
                    mma_tf32(c[mt][nt], a[mt], b[nt]);
        }
        if (it + 1 < NIT) {
            int nx = cur ^ 1;
            As[nx][ka+0][ca]  = f2tf32(a00.x); As[nx][ka+1][ca]  = f2tf32(a00.y);
            As[nx][ka+2][ca]  = f2tf32(a00.z); As[nx][ka+3][ca]  = f2tf32(a00.w);
            As[nx][ka+16][ca] = f2tf32(a01.x); As[nx][ka+17][ca] = f2tf32(a01.y);
            As[nx][ka+18][ca] = f2tf32(a01.z); As[nx][ka+19][ca] = f2tf32(a01.w);
            As[nx][ka+0][ca1]  = f2tf32(a10.x); As[nx][ka+1][ca1]  = f2tf32(a10.y);
            As[nx][ka+2][ca1]  = f2tf32(a10.z); As[nx][ka+3][ca1]  = f2tf32(a10.w);
            As[nx][ka+16][ca1] = f2tf32(a11.x); As[nx][ka+17][ca1] = f2tf32(a11.y);
            As[nx][ka+18][ca1] = f2tf32(a11.z); As[nx][ka+19][ca1] = f2tf32(a11.w);
            Bs[nx][ka+0][ca]  = f2tf32(b0.x); Bs[nx][ka+1][ca]  = f2tf32(b0.y);
            Bs[nx][ka+2][ca]  = f2tf32(b0.z); Bs[nx][ka+3][ca]  = f2tf32(b0.w);
            Bs[nx][ka+16][ca] = f2tf32(b1.x); Bs[nx][ka+17][ca] = f2tf32(b1.y);
            Bs[nx][ka+18][ca] = f2tf32(b1.z); Bs[nx][ka+19][ca] = f2tf32(b1.w);
        }
        __syncthreads();
    }
    #pragma unroll
    for (int mt = 0; mt < 2; mt++) {
        int r0 = m0 + wm*32 + mt*16 + gid;
        #pragma unroll
        for (int nt = 0; nt < 4; nt++) {
            int cc = n0 + wn*32 + nt*8 + tig*2;
            *(float2*)(C + (size_t)r0 * N + cc)     = make_float2(c[mt][nt][0], c[mt][nt][1]);
            *(float2*)(C + (size_t)(r0+8) * N + cc) = make_float2(c[mt][nt][2], c[mt][nt][3]);
        }
    }
}

// ======== combine v3 (unchanged) ========
__global__ __launch_bounds__(256)
void combine_tc3()
{
    extern __shared__ float dynsm[];
    float (*As)[2][32][72] = (float (*)[2][32][72])dynsm;
    float (*Bs)[2][32][72] = (float (*)[2][32][72])(dynsm + 2*2*32*72);

    int bz = blockIdx.z;
    int b = bz / 3, t = bz % 3;
    const float* Wt = (t == 0) ? g_wap : (t == 1) ? g_wbd : g_wrs;
    int m0 = (int)(gridDim.y - 1 - blockIdx.y) * 64;
    int n0 = blockIdx.x * 64;
    int colbase = t * D3 + n0;

    int tid = threadIdx.x;
    int lane = tid & 31, warp = tid >> 5;
    int wm = warp & 3, wn = warp >> 2;
    int gid = lane >> 2, tig = lane & 3;

    float c[2][4][4];
    #pragma unroll
    for (int p = 0; p < 2; p++)
        #pragma unroll
        for (int nt = 0; nt < 4; nt++)
            #pragma unroll
            for (int e = 0; e < 4; e++) c[p][nt][e] = 0.f;

    int ra = tid >> 2;
    int ka = (tid & 3) * 4;
    int cA = ra ^ (8 * (tid & 3));
    int kb = tid >> 4;
    int nb = (tid & 15) * 4;
    int swb = 8 * ((kb >> 2) & 3);
    int nbs = nb ^ swb;

    const float* aws = g_ws + (size_t)(b*Ss + m0 + ra) * Ss + ka;
    const float* awt = Wt   + (size_t)(b*Ss + m0 + ra) * Ss + ka;
    const float* bpv = g_V   + (size_t)(b*Ss + kb) * Dd + colbase + nb;
    const float* bpt = g_ABR + (size_t)(b*Ss + kb) * Dd + colbase + nb;

    const int NIT = m0/32 + 2;

    {
        float4 a00 = *(const float4*)(aws);
        float4 a01 = *(const float4*)(aws + 16);
        float4 a10 = *(const float4*)(awt);
        float4 a11 = *(const float4*)(awt + 16);
        float4 b00 = *(const float4*)(bpv);
        float4 b01 = *(const float4*)(bpv + (size_t)16 * Dd);
        float4 b10 = *(const float4*)(bpt);
        float4 b11 = *(const float4*)(bpt + (size_t)16 * Dd);
        As[0][0][ka+0][cA] = f2tf32(a00.x); As[0][0][ka+1][cA] = f2tf32(a00.y);
        As[0][0][ka+2][cA] = f2tf32(a00.z); As[0][0][ka+3][cA] = f2tf32(a00.w);
        As[0][0][ka+16][cA] = f2tf32(a01.x); As[0][0][ka+17][cA] = f2tf32(a01.y);
        As[0][0][ka+18][cA] = f2tf32(a01.z); As[0][0][ka+19][cA] = f2tf32(a01.w);
        As[0][1][ka+0][cA] = f2tf32(a10.x); As[0][1][ka+1][cA] = f2tf32(a10.y);
        As[0][1][ka+2][cA] = f2tf32(a10.z); As[0][1][ka+3][cA] = f2tf32(a10.w);
        As[0][1][ka+16][cA] = f2tf32(a11.x); As[0][1][ka+17][cA] = f2tf32(a11.y);
        As[0][1][ka+18][cA] = f2tf32(a11.z); As[0][1][ka+19][cA] = f2tf32(a11.w);
        *(float4*)&Bs[0][0][kb   ][nbs] = make_float4(f2tf32(b00.x), f2tf32(b00.y), f2tf32(b00.z), f2tf32(b00.w));
        *(float4*)&Bs[0][0][kb+16][nbs] = make_float4(f2tf32(b01.x), f2tf32(b01.y), f2tf32(b01.z), f2tf32(b01.w));
        *(float4*)&Bs[0][1][kb   ][nbs] = make_float4(f2tf32(b10.x), f2tf32(b10.y), f2tf32(b10.z), f2tf32(b10.w));
        *(float4*)&Bs[0][1][kb+16][nbs] = make_float4(f2tf32(b11.x), f2tf32(b11.y), f2tf32(b11.z), f2tf32(b11.w));
    }
    __syncthreads();

    for (int it = 0; it < NIT; it++) {
        int cur = it & 1;
        float4 a00, a01, a10, a11, b00, b01, b10, b11;
        if (it + 1 < NIT) {
            int k0 = (it + 1) * 32;
            a00 = *(const float4*)(aws + k0);
            a01 = *(const float4*)(aws + k0 + 16);
            a10 = *(const float4*)(awt + k0);
            a11 = *(const float4*)(awt + k0 + 16);
            b00 = *(const float4*)(bpv + (size_t)k0 * Dd);
            b01 = *(const float4*)(bpv + (size_t)(k0+16) * Dd);
            b10 = *(const float4*)(bpt + (size_t)k0 * Dd);
            b11 = *(const float4*)(bpt + (size_t)(k0+16) * Dd);
        }
        #pragma unroll
        for (int ks = 0; ks < 32; ks += 8) {
            int swl = 8 * ((ks >> 2) & 3);
            int swh = 8 * (((ks + 4) >> 2) & 3);
            int klo = ks + tig, khi = ks + tig + 4;
            int mr = wm*16 + gid;
            #pragma unroll
            for (int p = 0; p < 2; p++) {
                unsigned a[4], bfr[4][2];
                a[0] = __float_as_uint(As[cur][p][klo][ mr      ^ swl]);
                a[1] = __float_as_uint(As[cur][p][klo][(mr + 8) ^ swl]);
                a[2] = __float_as_uint(As[cur][p][khi][ mr      ^ swh]);
                a[3] = __float_as_uint(As[cur][p][khi][(mr + 8) ^ swh]);
                #pragma unroll
                for (int nt = 0; nt < 4; nt++) {
                    int nc = wn*32 + nt*8 + gid;
                    bfr[nt][0] = __float_as_uint(Bs[cur][p][klo][nc ^ swl]);
                    bfr[nt][1] = __float_as_uint(Bs[cur][p][khi][nc ^ swh]);
                }
                #pragma unroll
                for (int nt = 0; nt < 4; nt++)
                    mma_tf32(c[p][nt], a, bfr[nt]);
            }
        }
        if (it + 1 < NIT) {
            int nx = cur ^ 1;
            As[nx][0][ka+0][cA] = f2tf32(a00.x); As[nx][0][ka+1][cA] = f2tf32(a00.y);
            As[nx][0][ka+2][cA] = f2tf32(a00.z); As[nx][0][ka+3][cA] = f2tf32(a00.w);
            As[nx][0][ka+16][cA] = f2tf32(a01.x); As[nx][0][ka+17][cA] = f2tf32(a01.y);
            As[nx][0][ka+18][cA] = f2tf32(a01.z); As[nx][0][ka+19][cA] = f2tf32(a01.w);
            As[nx][1][ka+0][cA] = f2tf32(a10.x); As[nx][1][ka+1][cA] = f2tf32(a10.y);
            As[nx][1][ka+2][cA] = f2tf32(a10.z); As[nx][1][ka+3][cA] = f2tf32(a10.w);
            As[nx][1][ka+16][cA] = f2tf32(a11.x); As[nx][1][ka+17][cA] = f2tf32(a11.y);
            As[nx][1][ka+18][cA] = f2tf32(a11.z); As[nx][1][ka+19][cA] = f2tf32(a11.w);
            *(float4*)&Bs[nx][0][kb   ][nbs] = make_float4(f2tf32(b00.x), f2tf32(b00.y), f2tf32(b00.z), f2tf32(b00.w));
            *(float4*)&Bs[nx][0][kb+16][nbs] = make_float4(f2tf32(b01.x), f2tf32(b01.y), f2tf32(b01.z), f2tf32(b01.w));
            *(float4*)&Bs[nx][1][kb   ][nbs] = make_float4(f2tf32(b10.x), f2tf32(b10.y), f2tf32(b10.z), f2tf32(b10.w));
            *(float4*)&Bs[nx][1][kb+16][nbs] = make_float4(f2tf32(b11.x), f2tf32(b11.y), f2tf32(b11.z), f2tf32(b11.w));
        }
        __syncthreads();
    }

    int r0 = m0 + wm*16 + gid;
    float is0 = g_invden[b*Ss + r0],     it0 = g_invden[(t+1)*BS + b*Ss + r0];
    float is1 = g_invden[b*Ss + r0 + 8], it1 = g_invden[(t+1)*BS + b*Ss + r0 + 8];
    int rg = b*Ss + r0;
    #pragma unroll
    for (int nt = 0; nt < 4; nt++) {
        int cc = colbase + wn*32 + nt*8 + tig*2;
        *(float2*)(g_comb + (size_t)rg * Dd + cc) =
            make_float2(is0*c[0][nt][0] + it0*c[1][nt][0],
                        is0*c[0][nt][1] + it0*c[1][nt][1]);
        *(float2*)(g_comb + (size_t)(rg+8) * Dd + cc) =
            make_float2(is1*c[0][nt][2] + it1*c[1][nt][2],
                        is1*c[0][nt][3] + it1*c[1][nt][3]);
    }
}

// ---------------- merged setup (runs on its own stream) ----------------
__global__ __launch_bounds__(256)
void setup_kernel(const float* __restrict__ vemb, const float* __restrict__ spec,
                  const float* __restrict__ Wspec, const float* __restrict__ adj,
                  const float* __restrict__ vg)
{
    int tid = threadIdx.x;
    if (blockIdx.x == 0) {
        __shared__ float eb[NV*DV];
        __shared__ float adj_s[NV*NV];
        for (int t = tid; t < NV*DV; t += 256) {
            int u = t / DV, d = t % DV;
            float s = vemb[t];
            #pragma unroll
            for (int h = 0; h < 6; h++) s += 0.1f * spec[u*6+h] * Wspec[d*6+h];
            eb[t] = s;
        }
        for (int t = tid; t < NV*NV; t += 256) adj_s[t] = adj[t];
        __syncthreads();
        for (int t = tid; t < NV*DV; t += 256) {
            int v = t / DV, d = t % DV;
            float s = eb[t];
            #pragma unroll 8
            for (int u = 0; u < NV; u++) s += 0.1f * adj_s[u*NV + v] * eb[u*DV + d];
            g_emb2[t] = s;
        }
    } else {
        int v = blockIdx.x - 1;
        int lane = tid & 31, warp = tid >> 5;
        // 768 floats = 192 float4; 256 threads: first 192 take one each
        float s = 0.f;
        if (tid < 192) {
            float4 x4 = ((const float4*)(vg + (size_t)v*Dd))[tid];
            s = 1.f/(1.f + __expf(-x4.x)) + 1.f/(1.f + __expf(-x4.y))
              + 1.f/(1.f + __expf(-x4.z)) + 1.f/(1.f + __expf(-x4.w));
        }
        #pragma unroll
        for (int off = 16; off; off >>= 1) s += __shfl_xor_sync(0xffffffffu, s, off);
        __shared__ float red[8];
        if (lane == 0) red[warp] = s;
        __syncthreads();
        if (tid == 0) {
            float tot = 0.f;
            #pragma unroll
            for (int w = 0; w < 8; w++) tot += red[w];
            g_gm[v] = tot * (1.f / Dd);
        }
    }
}

// ---------------- row-persistent attention (causal-only stores) ----------------
__global__ __launch_bounds__(256)
void attn_row(float* __restrict__ pi_out)
{
    extern __shared__ float sm[];
    float (*Ks)[256][36] = (float (*)[256][36])sm;
    float* Fs = sm + 2*256*36;

    int i = Ss - 1 - (int)blockIdx.x;
    int b = blockIdx.y;
    int row_g = b*Ss + i;
    size_t rowbase = (size_t)row_g * Ss;
    int tid = threadIdx.x;
    int warp = tid >> 5, lane = tid & 31;
    int gid = lane >> 2, tig = lane & 3;

    __shared__ float q_s[DV];
    __shared__ float gm_s[NV];
    __shared__ float wred[8][4];

    if (tid < DV) q_s[tid] = g_QK[(size_t)row_g*64 + tid];
    if (tid >= 64 && tid < 128) gm_s[tid-64] = g_gm[tid-64];
    __syncthreads();
    const float LOG2E = 1.4426950408889634f;
    for (int t = tid; t < 2048; t += 256) {
        int d = t >> 6, v = t & 63;
        Fs[d*72 + v] = f2tf32(q_s[d] * LOG2E * g_emb2[v*DV + d]);
    }

    float gmr[16];
    #pragma unroll
    for (int nt = 0; nt < 8; nt++) {
        gmr[nt*2]   = gm_s[nt*8 + tig*2];
        gmr[nt*2+1] = gm_s[nt*8 + tig*2 + 1];
    }

    float bws = 0.f, bap = 0.f, bbd = 0.f, brs = 0.f;
    int ntiles = (i >> 8) + 1;
    int kr = tid >> 3, kq = (tid & 7) * 4;

    #pragma unroll
    for (int pp = 0; pp < 8; pp++) {
        int r = kr + pp*32;
        unsigned dst = smem_u32(&Ks[0][r][kq]);
        CP_ASYNC16(dst, g_QK + (size_t)(b*Ss + r)*64 + 32 + kq);
    }
    CP_COMMIT();

    for (int jt = 0; jt < ntiles; jt++) {
        int j0 = jt * 256;
        int cur = jt & 1;
        CP_WAIT0();
        __syncthreads();

        float c[2][8][4];
        #pragma unroll
        for (int mt = 0; mt < 2; mt++)
            #pragma unroll
            for (int nt = 0; nt < 8; nt++)
                #pragma unroll
                for (int e = 0; e < 4; e++) c[mt][nt][e] = 0.f;

        #pragma unroll
        for (int ks = 0; ks < 32; ks += 8) {
            unsigned a[2][4], bf[8][2];
            #pragma unroll
            for (int mt = 0; mt < 2; mt++) {
                int mr = warp*32 + mt*16 + gid;
                a[mt][0] = __float_as_uint(f2tf32(Ks[cur][mr  ][ks+tig]));
                a[mt][1] = __float_as_uint(f2tf32(Ks[cur][mr+8][ks+tig]));
                a[mt][2] = __float_as_uint(f2tf32(Ks[cur][mr  ][ks+tig+4]));
                a[mt][3] = __float_as_uint(f2tf32(Ks[cur][mr+8][ks+tig+4]));
            }
            #pragma unroll
            for (int nt = 0; nt < 8; nt++) {
                int nc = nt*8 + gid;
                bf[nt][0] = __float_as_uint(Fs[(ks+tig  )*72 + nc]);
                bf[nt][1] = __float_as_uint(Fs[(ks+tig+4)*72 + nc]);
            }
            #pragma unroll
            for (int mt = 0; mt < 2; mt++)
                #pragma unroll
                for (int nt = 0; nt < 8; nt++)
                    mma_tf32(c[mt][nt], a[mt], bf[nt]);
        }

        if (jt + 1 < ntiles) {
            int j0n = (jt + 1) * 256;
            int nx = cur ^ 1;
            #pragma unroll
            for (int pp = 0; pp < 8; pp++) {
                int r = kr + pp*32;
                unsigned dst = smem_u32(&Ks[nx][r][kq]);
                CP_ASYNC16(dst, g_QK + (size_t)(b*Ss + j0n + r)*64 + 32 + kq);
            }
            CP_COMMIT();
        }

        #pragma unroll
        for (int mt = 0; mt < 2; mt++)
        #pragma unroll
        for (int rh = 0; rh < 2; rh++) {
            int j = j0 + warp*32 + mt*16 + rh*8 + gid;
            size_t pair = rowbase + j;
            float e[16];
            float sum = 0.f, sg = 0.f, sap = 0.f;
            #pragma unroll
            for (int q = 0; q < 16; q++) {
                float ev = exp2f(c[mt][q>>1][rh*2 + (q&1)]);
                e[q] = ev;
                sum += ev;
                sg = fmaf(ev, gmr[q], sg);
                if (q & 1) sap += ev;
            }
            float sbd = (tig & 1) ? sum : 0.f;
            float srs = (tig & 2) ? sum : 0.f;
            sum += __shfl_xor_sync(0xffffffffu, sum, 1);
            sum += __shfl_xor_sync(0xffffffffu, sum, 2);
            sg  += __shfl_xor_sync(0xffffffffu, sg , 1);
            sg  += __shfl_xor_sync(0xffffffffu, sg , 2);
            sap += __shfl_xor_sync(0xffffffffu, sap, 1);
            sap += __shfl_xor_sync(0xffffffffu, sap, 2);
            sbd += __shfl_xor_sync(0xffffffffu, sbd, 1);
            sbd += __shfl_xor_sync(0xffffffffu, sbd, 2);
            srs += __shfl_xor_sync(0xffffffffu, srs, 1);
            srs += __shfl_xor_sync(0xffffffffu, srs, 2);

            if (j <= i) {
                float inv = 1.f / sum;
                float* po = pi_out + pair*NV + tig*2;
                #pragma unroll
                for (int nt = 0; nt < 8; nt++)
                    __stcs((float2*)(po + nt*8), make_float2(e[nt*2]*inv, e[nt*2+1]*inv));
                if (tig == 0) {
                    float ws = sg*inv, ap = sap*inv, bd = sbd*inv, rs = srs*inv;
                    g_ws[pair] = ws; g_wap[pair] = ap; g_wbd[pair] = bd; g_wrs[pair] = rs;
                    bws += ws; bap += ap; bbd += bd; brs += rs;
                }
            }
        }
    }

    #pragma unroll
    for (int off = 16; off; off >>= 1) {
        bws += __shfl_xor_sync(0xffffffffu, bws, off);
        bap += __shfl_xor_sync(0xffffffffu, bap, off);
        bbd += __shfl_xor_sync(0xffffffffu, bbd, off);
        brs += __shfl_xor_sync(0xffffffffu, brs, off);
    }
    if (lane == 0) {
        wred[warp][0] = bws; wred[warp][1] = bap;
        wred[warp][2] = bbd; wred[warp][3] = brs;
    }
    __syncthreads();
    if (tid < 4) {
        float s = 0.f;
        #pragma unroll
        for (int w = 0; w < 8; w++) s += wred[w][tid];
        if (tid == 0) {
            g_invden[row_g] = 1.f / (s + EPSV);
        } else {
            float d1 = s + EPSV, S2 = s / d1;
            g_invden[tid*BS + row_g] = 1.f / (d1 * (S2 + EPSV));
        }
    }
}

// ---------------- layernorm ----------------
__global__ void ln_kernel(const float* __restrict__ bo, const float* __restrict__ gamma,
                          const float* __restrict__ beta, float* __restrict__ out)
{
    int row = blockIdx.x, tid = threadIdx.x;
    const float* r = g_res + (size_t)row * Dd;
    float v[3];
    float s = 0.f;
    #pragma unroll
    for (int q = 0; q < 3; q++) { int c = tid + q*256; v[q] = r[c] + bo[c]; s += v[q]; }
    __shared__ float red[256];
    __shared__ float mu_s, inv_s;
    red[tid] = s; __syncthreads();
    for (int off = 128; off; off >>= 1) {
        if (tid < off) red[tid] += red[tid + off];
        __syncthreads();
    }
    if (tid == 0) mu_s = red[0] * (1.f / Dd);
    __syncthreads();
    float mu = mu_s;
    float s2 = 0.f;
    #pragma unroll
    for (int q = 0; q < 3; q++) { float d = v[q] - mu; s2 += d*d; }
    __syncthreads();
    red[tid] = s2; __syncthreads();
    for (int off = 128; off; off >>= 1) {
        if (tid < off) red[tid] += red[tid + off];
        __syncthreads();
    }
    if (tid == 0) inv_s = rsqrtf(red[0] * (1.f / Dd) + LNEPS);
    __syncthreads();
    float inv = inv_s;
    #pragma unroll
    for (int q = 0; q < 3; q++) {
        int c = tid + q*256;
        out[(size_t)row*Dd + c] = (v[q] - mu) * inv * gamma[c] + beta[c];
    }
}

// ---------------- launch ----------------
extern "C" void kernel_launch(void* const* d_in, const int* in_sizes, int n_in,
                              void* d_out, int out_size)
{
    const float* x      = (const float*)d_in[0];
    const float* Wq     = (const float*)d_in[2];
    const float* Wk     = (const float*)d_in[3];
    const float* vemb   = (const float*)d_in[4];
    const float* vgates = (const float*)d_in[5];
    const float* Wv     = (const float*)d_in[6];
    const float* Wspec  = (const float*)d_in[7];
    const float* Wa     = (const float*)d_in[8];
    const float* Wb     = (const float*)d_in[9];
    const float* Wr     = (const float*)d_in[10];
    const float* Wo     = (const float*)d_in[11];
    const float* bo     = (const float*)d_in[12];
    const float* gamma  = (const float*)d_in[13];
    const float* beta   = (const float*)d_in[14];
    const float* adj    = (const float*)d_in[15];
    const float* spec   = (const float*)d_in[16];

    float* out    = (float*)d_out;
    float* pi_out = out + NORMED_ELEMS;

    float *pQK, *pV, *pABR, *pComb, *pRes;
    cudaGetSymbolAddress((void**)&pQK,   g_QK);
    cudaGetSymbolAddress((void**)&pV,    g_V);
    cudaGetSymbolAddress((void**)&pABR,  g_ABR);
    cudaGetSymbolAddress((void**)&pComb, g_comb);
    cudaGetSymbolAddress((void**)&pRes,  g_res);

    const int COMBINE_SMEM = 2*2*32*72*4 * 2;          // 73728
    const int GEMM_SMEM    = (2*32*136 + 2*32*72) * 4; // 53248
    const int ATTN_SMEM    = (2*256*36 + 32*72) * 4;   // 82944

    static cudaStream_t s1 = nullptr, s2 = nullptr;
    static cudaEvent_t ev_fork = nullptr, ev_join = nullptr, ev_setup = nullptr;
    if (!s1) {
        cudaFuncSetAttribute(combine_tc3, cudaFuncAttributeMaxDynamicSharedMemorySize, COMBINE_SMEM);
        cudaFuncSetAttribute(gemm_fused,  cudaFuncAttributeMaxDynamicSharedMemorySize, GEMM_SMEM);
        cudaFuncSetAttribute(gemm_qk,     cudaFuncAttributeMaxDynamicSharedMemorySize, GEMM_SMEM);
        cudaFuncSetAttribute(gemm_tc,     cudaFuncAttributeMaxDynamicSharedMemorySize, GEMM_SMEM);
        cudaFuncSetAttribute(attn_row,    cudaFuncAttributeMaxDynamicSharedMemorySize, ATTN_SMEM);
        cudaStreamCreateWithFlags(&s1, cudaStreamNonBlocking);
        cudaStreamCreateWithFlags(&s2, cudaStreamNonBlocking);
        cudaEventCreateWithFlags(&ev_fork,  cudaEventDisableTiming);
        cudaEventCreateWithFlags(&ev_join,  cudaEventDisableTiming);
        cudaEventCreateWithFlags(&ev_setup, cudaEventDisableTiming);
    }

    dim3 thr(256);

    // fork everything independent
    cudaEventRecord(ev_fork, 0);
    cudaStreamWaitEvent(s1, ev_fork, 0);
    cudaStreamWaitEvent(s2, ev_fork, 0);

    // s2: setup (emb2 + gate means) — needed only by attn
    setup_kernel<<<65, thr, 0, s2>>>(vemb, spec, Wspec, adj, vgates);
    cudaEventRecord(ev_setup, s2);

    // s1: zerofill (no deps) + V/ABR projection — needed only by combine
    zerofill_kernel<<<dim3(Ss, Bb), thr, 0, s1>>>(pi_out);
    gemm_fused<<<dim3(24, 16), thr, GEMM_SMEM, s1>>>(x, Wq, Wk, Wv, Wa, Wb, Wr,
                                                     pQK, pV, pABR, /*n_off=*/1);
    cudaEventRecord(ev_join, s1);

    // main stream: split-K QK projection + reduce, then attention
    gemm_qk<<<dim3(6, 16), thr, GEMM_SMEM>>>(x, Wq, Wk);
    qk_reduce<<<128, thr>>>();
    cudaStreamWaitEvent(0, ev_setup, 0);
    attn_row<<<dim3(Ss, Bb), thr, ATTN_SMEM>>>(pi_out);

    // join: combine needs V/ABR + attn outputs + zerofilled w-scalars
    cudaStreamWaitEvent(0, ev_join, 0);
    combine_tc3<<<dim3(4, 16, 6), thr, COMBINE_SMEM>>>();

    gemm_tc<<<dim3(12, 16), thr, GEMM_SMEM>>>(pComb, Wo, pRes, Dd);
    ln_kernel<<<BS, 256>>>(bo, gamma, beta, out);
}

// round 17
// speedup vs baseline: 1.1074x; 1.0068x over previous
#include <cuda_runtime.h>

#define Bb 2
#define Ss 1024
#define Dd 768
#define DV 32
#define NV 64
#define D3 256
#define BS (Bb*Ss)
#define Kd 768
#define EPSV 1e-8f
#define LNEPS 1e-5f
#define NORMED_ELEMS ((size_t)Bb*Ss*Dd)

// ---------------- scratch ----------------
__device__ float g_QK[BS*64];
__device__ float g_QKpart[6][BS*64];
__device__ float g_V[BS*Dd];       // tf32-rounded at producer
__device__ float g_ABR[BS*Dd];     // tf32-rounded at producer
__device__ float g_emb2[NV*DV];
__device__ float g_gm[NV];
__device__ float g_ws [(size_t)BS*Ss];   // tf32-rounded at producer
__device__ float g_wap[(size_t)BS*Ss];
__device__ float g_wbd[(size_t)BS*Ss];
__device__ float g_wrs[(size_t)BS*Ss];
__device__ float g_invden[4*BS];
__device__ float g_comb[BS*Dd];
__device__ float g_res[BS*Dd];

// ---------------- helpers ----------------
__device__ __forceinline__ float f2tf32(float f) {
    unsigned r;
    asm("cvt.rna.tf32.f32 %0, %1;" : "=r"(r) : "f"(f));
    return __uint_as_float(r);
}
__device__ __forceinline__ void mma_tf32(float* c, const unsigned* a, const unsigned* b) {
    asm volatile("mma.sync.aligned.m16n8k8.row.col.f32.tf32.tf32.f32 "
                 "{%0,%1,%2,%3}, {%4,%5,%6,%7}, {%8,%9}, {%0,%1,%2,%3};"
                 : "+f"(c[0]), "+f"(c[1]), "+f"(c[2]), "+f"(c[3])
                 : "r"(a[0]), "r"(a[1]), "r"(a[2]), "r"(a[3]), "r"(b[0]), "r"(b[1]));
}
__device__ __forceinline__ unsigned smem_u32(const void* p) {
    return (unsigned)__cvta_generic_to_shared(p);
}
#define CP_ASYNC16(dst, src) \
    asm volatile("cp.async.ca.shared.global [%0], [%1], 16;" :: "r"(dst), "l"(src))
#define CP_COMMIT() asm volatile("cp.async.commit_group;" ::: "memory")
#define CP_WAIT0()  asm volatile("cp.async.wait_group 0;" ::: "memory")

// ======== zerofill: strict upper triangle of pi + w scalars (no deps) ========
__global__ __launch_bounds__(256)
void zerofill_kernel(float* __restrict__ pi_out)
{
    int i = blockIdx.x, b = blockIdx.y;
    size_t rowbase = (size_t)(b*Ss + i) * Ss;
    int tid = threadIdx.x;
    int j0 = i + 1;
    if (j0 >= Ss) return;
    float4 z4 = make_float4(0.f, 0.f, 0.f, 0.f);
    float4* base = (float4*)(pi_out + (rowbase + j0) * NV);
    int n4 = (Ss - j0) * 16;
    for (int t = tid; t < n4; t += 256) __stcs(base + t, z4);
    for (int j = j0 + tid; j < Ss; j += 256) {
        size_t p = rowbase + j;
        g_ws[p] = 0.f; g_wap[p] = 0.f; g_wbd[p] = 0.f; g_wrs[p] = 0.f;
    }
}

// ======== split-K QK projection: grid (6 kslices, 16 mtiles) ========
__global__ __launch_bounds__(256)
void gemm_qk(const float* __restrict__ X,
             const float* __restrict__ Wq, const float* __restrict__ Wk)
{
    extern __shared__ float sm[];
    float (*As)[32][136] = (float (*)[32][136])sm;
    float (*Bs)[32][72]  = (float (*)[32][72])(sm + 2*32*136);

    int tid = threadIdx.x;
    int lane = tid & 31, warp = tid >> 5;
    int wm = warp & 3, wn = warp >> 2;
    int gid = lane >> 2, tig = lane & 3;
    int m0 = blockIdx.y * 128;
    int kslice = blockIdx.x;
    int kbase = kslice * 128;

    float c[2][4][4];
    #pragma unroll
    for (int mt = 0; mt < 2; mt++)
        #pragma unroll
        for (int nt = 0; nt < 4; nt++)
            #pragma unroll
            for (int e = 0; e < 4; e++) c[mt][nt][e] = 0.f;

    int ra = tid >> 2;
    int ka = (tid & 3) * 4;
    int sw = 8 * (tid & 3);
    const float* xp0 = X + (size_t)(m0 + ra) * Kd + kbase + ka;
    const float* xp1 = X + (size_t)(m0 + ra + 64) * Kd + kbase + ka;
    const float* wp  = (ra < 32) ? (Wq + (size_t)ra * Kd)
                                 : (Wk + (size_t)(ra - 32) * Kd);
    wp += kbase + ka;
    int ca = ra ^ sw, ca1 = (ra + 64) ^ sw;

    {
        float4 a00 = *(const float4*)(xp0);
        float4 a01 = *(const float4*)(xp0 + 16);
        float4 a10 = *(const float4*)(xp1);
        float4 a11 = *(const float4*)(xp1 + 16);
        float4 b0  = *(const float4*)(wp);
        float4 b1  = *(const float4*)(wp + 16);
        As[0][ka+0][ca]  = f2tf32(a00.x); As[0][ka+1][ca]  = f2tf32(a00.y);
        As[0][ka+2][ca]  = f2tf32(a00.z); As[0][ka+3][ca]  = f2tf32(a00.w);
        As[0][ka+16][ca] = f2tf32(a01.x); As[0][ka+17][ca] = f2tf32(a01.y);
        As[0][ka+18][ca] = f2tf32(a01.z); As[0][ka+19][ca] = f2tf32(a01.w);
        As[0][ka+0][ca1]  = f2tf32(a10.x); As[0][ka+1][ca1]  = f2tf32(a10.y);
        As[0][ka+2][ca1]  = f2tf32(a10.z); As[0][ka+3][ca1]  = f2tf32(a10.w);
        As[0][ka+16][ca1] = f2tf32(a11.x); As[0][ka+17][ca1] = f2tf32(a11.y);
        As[0][ka+18][ca1] = f2tf32(a11.z); As[0][ka+19][ca1] = f2tf32(a11.w);
        Bs[0][ka+0][ca]  = f2tf32(b0.x); Bs[0][ka+1][ca]  = f2tf32(b0.y);
        Bs[0][ka+2][ca]  = f2tf32(b0.z); Bs[0][ka+3][ca]  = f2tf32(b0.w);
        Bs[0][ka+16][ca] = f2tf32(b1.x); Bs[0][ka+17][ca] = f2tf32(b1.y);
        Bs[0][ka+18][ca] = f2tf32(b1.z); Bs[0][ka+19][ca] = f2tf32(b1.w);
    }
    __syncthreads();

    const int NIT = 4;
    for (int it = 0; it < NIT; it++) {
        int cur = it & 1;
        float4 a00, a01, a10, a11, b0, b1;
        if (it + 1 < NIT) {
            int k0 = (it + 1) * 32;
            a00 = *(const float4*)(xp0 + k0);
            a01 = *(const float4*)(xp0 + k0 + 16);
            a10 = *(const float4*)(xp1 + k0);
            a11 = *(const float4*)(xp1 + k0 + 16);
            b0  = *(const float4*)(wp  + k0);
            b1  = *(const float4*)(wp  + k0 + 16);
        }
        #pragma unroll
        for (int ks = 0; ks < 32; ks += 8) {
            int swl = 8 * ((ks >> 2) & 3);
            int swh = 8 * (((ks + 4) >> 2) & 3);
            int klo = ks + tig, khi = ks + tig + 4;
            unsigned a[2][4], b[4][2];
            #pragma unroll
            for (int mt = 0; mt < 2; mt++) {
                int mr = wm*32 + mt*16 + gid;
                a[mt][0] = __float_as_uint(As[cur][klo][ mr      ^ swl]);
                a[mt][1] = __float_as_uint(As[cur][klo][(mr + 8) ^ swl]);
                a[mt][2] = __float_as_uint(As[cur][khi][ mr      ^ swh]);
                a[mt][3] = __float_as_uint(As[cur][khi][(mr + 8) ^ swh]);
            }
            #pragma unroll
            for (int nt = 0; nt < 4; nt++) {
                int nc = wn*32 + nt*8 + gid;
                b[nt][0] = __float_as_uint(Bs[cur][klo][nc ^ swl]);
                b[nt][1] = __float_as_uint(Bs[cur][khi][nc ^ swh]);
            }
            #pragma unroll
            for (int mt = 0; mt < 2; mt++)
                #pragma unroll
                for (int nt = 0; nt < 4; nt++)
                    mma_tf32(c[mt][nt], a[mt], b[nt]);
        }
        if (it + 1 < NIT) {
            int nx = cur ^ 1;
            As[nx][ka+0][ca]  = f2tf32(a00.x); As[nx][ka+1][ca]  = f2tf32(a00.y);
            As[nx][ka+2][ca]  = f2tf32(a00.z); As[nx][ka+3][ca]  = f2tf32(a00.w);
            As[nx][ka+16][ca] = f2tf32(a01.x); As[nx][ka+17][ca] = f2tf32(a01.y);
            As[nx][ka+18][ca] = f2tf32(a01.z); As[nx][ka+19][ca] = f2tf32(a01.w);
            As[nx][ka+0][ca1]  = f2tf32(a10.x); As[nx][ka+1][ca1]  = f2tf32(a10.y);
            As[nx][ka+2][ca1]  = f2tf32(a10.z); As[nx][ka+3][ca1]  = f2tf32(a10.w);
            As[nx][ka+16][ca1] = f2tf32(a11.x); As[nx][ka+17][ca1] = f2tf32(a11.y);
            As[nx][ka+18][ca1] = f2tf32(a11.z); As[nx][ka+19][ca1] = f2tf32(a11.w);
            Bs[nx][ka+0][ca]  = f2tf32(b0.x); Bs[nx][ka+1][ca]  = f2tf32(b0.y);
            Bs[nx][ka+2][ca]  = f2tf32(b0.z); Bs[nx][ka+3][ca]  = f2tf32(b0.w);
            Bs[nx][ka+16][ca] = f2tf32(b1.x); Bs[nx][ka+17][ca] = f2tf32(b1.y);
            Bs[nx][ka+18][ca] = f2tf32(b1.z); Bs[nx][ka+19][ca] = f2tf32(b1.w);
        }
        __syncthreads();
    }

    float* Cd = g_QKpart[kslice];
    #pragma unroll
    for (int mt = 0; mt < 2; mt++) {
        int r0 = m0 + wm*32 + mt*16 + gid;
        #pragma unroll
        for (int nt = 0; nt < 4; nt++) {
            int cc = wn*32 + nt*8 + tig*2;
            *(float2*)(Cd + (size_t)r0 * 64 + cc)     = make_float2(c[mt][nt][0], c[mt][nt][1]);
            *(float2*)(Cd + (size_t)(r0+8) * 64 + cc) = make_float2(c[mt][nt][2], c[mt][nt][3]);
        }
    }
}

// ======== QK split-K reduce ========
__global__ __launch_bounds__(256)
void qk_reduce()
{
    int t = blockIdx.x * 256 + threadIdx.x;
    float4 s = ((const float4*)g_QKpart[0])[t];
    #pragma unroll
    for (int p = 1; p < 6; p++) {
        float4 v = ((const float4*)g_QKpart[p])[t];
        s.x += v.x; s.y += v.y; s.z += v.z; s.w += v.w;
    }
    ((float4*)g_QK)[t] = s;
}

// ======== fused projection GEMM (V/ABR only; outputs tf32-rounded) ========
__global__ __launch_bounds__(256)
void gemm_fused(const float* __restrict__ X,
                const float* __restrict__ Wq, const float* __restrict__ Wk,
                const float* __restrict__ Wv, const float* __restrict__ Wa,
                const float* __restrict__ Wb, const float* __restrict__ Wr,
                float* __restrict__ Cqk, float* __restrict__ Cv, float* __restrict__ Cabr,
                int n_off)
{
    extern __shared__ float sm[];
    float (*As)[32][136] = (float (*)[32][136])sm;
    float (*Bs)[32][72]  = (float (*)[32][72])(sm + 2*32*136);

    int tid = threadIdx.x;
    int lane = tid & 31, warp = tid >> 5;
    int wm = warp & 3, wn = warp >> 2;
    int gid = lane >> 2, tig = lane & 3;
    int m0 = blockIdx.y * 128, n0 = (blockIdx.x + n_off) * 64;

    float c[2][4][4];
    #pragma unroll
    for (int mt = 0; mt < 2; mt++)
        #pragma unroll
        for (int nt = 0; nt < 4; nt++)
            #pragma unroll
            for (int e = 0; e < 4; e++) c[mt][nt][e] = 0.f;

    int ra = tid >> 2;
    int ka = (tid & 3) * 4;
    int sw = 8 * (tid & 3);
    const float* xp0 = X + (size_t)(m0 + ra) * Kd + ka;
    const float* xp1 = X + (size_t)(m0 + ra + 64) * Kd + ka;
    int rW = n0 + ra;
    const float* wp;
    if      (rW <   32) wp = Wq + (size_t)rW * Kd;
    else if (rW <   64) wp = Wk + (size_t)(rW -   32) * Kd;
    else if (rW <  832) wp = Wv + (size_t)(rW -   64) * Kd;
    else if (rW < 1088) wp = Wa + (size_t)(rW -  832) * Kd;
    else if (rW < 1344) wp = Wb + (size_t)(rW - 1088) * Kd;
    else                wp = Wr + (size_t)(rW - 1344) * Kd;
    wp += ka;

    int ca = ra ^ sw, ca1 = (ra + 64) ^ sw;

    {
        float4 a00 = *(const float4*)(xp0);
        float4 a01 = *(const float4*)(xp0 + 16);
        float4 a10 = *(const float4*)(xp1);
        float4 a11 = *(const float4*)(xp1 + 16);
        float4 b0  = *(const float4*)(wp);
        float4 b1  = *(const float4*)(wp + 16);
        As[0][ka+0][ca]  = f2tf32(a00.x); As[0][ka+1][ca]  = f2tf32(a00.y);
        As[0][ka+2][ca]  = f2tf32(a00.z); As[0][ka+3][ca]  = f2tf32(a00.w);
        As[0][ka+16][ca] = f2tf32(a01.x); As[0][ka+17][ca] = f2tf32(a01.y);
        As[0][ka+18][ca] = f2tf32(a01.z); As[0][ka+19][ca] = f2tf32(a01.w);
        As[0][ka+0][ca1]  = f2tf32(a10.x); As[0][ka+1][ca1]  = f2tf32(a10.y);
        As[0][ka+2][ca1]  = f2tf32(a10.z); As[0][ka+3][ca1]  = f2tf32(a10.w);
        As[0][ka+16][ca1] = f2tf32(a11.x); As[0][ka+17][ca1] = f2tf32(a11.y);
        As[0][ka+18][ca1] = f2tf32(a11.z); As[0][ka+19][ca1] = f2tf32(a11.w);
        Bs[0][ka+0][ca]  = f2tf32(b0.x); Bs[0][ka+1][ca]  = f2tf32(b0.y);
        Bs[0][ka+2][ca]  = f2tf32(b0.z); Bs[0][ka+3][ca]  = f2tf32(b0.w);
        Bs[0][ka+16][ca] = f2tf32(b1.x); Bs[0][ka+17][ca] = f2tf32(b1.y);
        Bs[0][ka+18][ca] = f2tf32(b1.z); Bs[0][ka+19][ca] = f2tf32(b1.w);
    }
    __syncthreads();

    const int NIT = Kd / 32;
    for (int it = 0; it < NIT; it++) {
        int cur = it & 1;
        float4 a00, a01, a10, a11, b0, b1;
        if (it + 1 < NIT) {
            int k0 = (it + 1) * 32;
            a00 = *(const float4*)(xp0 + k0);
            a01 = *(const float4*)(xp0 + k0 + 16);
            a10 = *(const float4*)(xp1 + k0);
            a11 = *(const float4*)(xp1 + k0 + 16);
            b0  = *(const float4*)(wp  + k0);
            b1  = *(const float4*)(wp  + k0 + 16);
        }
        #pragma unroll
        for (int ks = 0; ks < 32; ks += 8) {
            int swl = 8 * ((ks >> 2) & 3);
            int swh = 8 * (((ks + 4) >> 2) & 3);
            int klo = ks + tig, khi = ks + tig + 4;
            unsigned a[2][4], b[4][2];
            #pragma unroll
            for (int mt = 0; mt < 2; mt++) {
                int mr = wm*32 + mt*16 + gid;
                a[mt][0] = __float_as_uint(As[cur][klo][ mr      ^ swl]);
                a[mt][1] = __float_as_uint(As[cur][klo][(mr + 8) ^ swl]);
                a[mt][2] = __float_as_uint(As[cur][khi][ mr      ^ swh]);
                a[mt][3] = __float_as_uint(As[cur][khi][(mr + 8) ^ swh]);
            }
            #pragma unroll
            for (int nt = 0; nt < 4; nt++) {
                int nc = wn*32 + nt*8 + gid;
                b[nt][0] = __float_as_uint(Bs[cur][klo][nc ^ swl]);
                b[nt][1] = __float_as_uint(Bs[cur][khi][nc ^ swh]);
            }
            #pragma unroll
            for (int mt = 0; mt < 2; mt++)
                #pragma unroll
                for (int nt = 0; nt < 4; nt++)
                    mma_tf32(c[mt][nt], a[mt], b[nt]);
        }
        if (it + 1 < NIT) {
            int nx = cur ^ 1;
            As[nx][ka+0][ca]  = f2tf32(a00.x); As[nx][ka+1][ca]  = f2tf32(a00.y);
            As[nx][ka+2][ca]  = f2tf32(a00.z); As[nx][ka+3][ca]  = f2tf32(a00.w);
            As[nx][ka+16][ca] = f2tf32(a01.x); As[nx][ka+17][ca] = f2tf32(a01.y);
            As[nx][ka+18][ca] = f2tf32(a01.z); As[nx][ka+19][ca] = f2tf32(a01.w);
            As[nx][ka+0][ca1]  = f2tf32(a10.x); As[nx][ka+1][ca1]  = f2tf32(a10.y);
            As[nx][ka+2][ca1]  = f2tf32(a10.z); As[nx][ka+3][ca1]  = f2tf32(a10.w);
            As[nx][ka+16][ca1] = f2tf32(a11.x); As[nx][ka+17][ca1] = f2tf32(a11.y);
            As[nx][ka+18][ca1] = f2tf32(a11.z); As[nx][ka+19][ca1] = f2tf32(a11.w);
            Bs[nx][ka+0][ca]  = f2tf32(b0.x); Bs[nx][ka+1][ca]  = f2tf32(b0.y);
            Bs[nx][ka+2][ca]  = f2tf32(b0.z); Bs[nx][ka+3][ca]  = f2tf32(b0.w);
            Bs[nx][ka+16][ca] = f2tf32(b1.x); Bs[nx][ka+17][ca] = f2tf32(b1.y);
            Bs[nx][ka+18][ca] = f2tf32(b1.z); Bs[nx][ka+19][ca] = f2tf32(b1.w);
        }
        __syncthreads();
    }

    float* Cd; int strideN, cbase;
    if (n0 == 0)       { Cd = Cqk;  strideN = 64;  cbase = 0; }
    else if (n0 < 832) { Cd = Cv;   strideN = Dd;  cbase = n0 - 64; }
    else               { Cd = Cabr; strideN = Dd;  cbase = n0 - 832; }

    #pragma unroll
    for (int mt = 0; mt < 2; mt++) {
        int r0 = m0 + wm*32 + mt*16 + gid;
        #pragma unroll
        for (int nt = 0; nt < 4; nt++) {
            int cc = cbase + wn*32 + nt*8 + tig*2;
            // pre-round for combine (idempotent vs combine's own cvt)
            *(float2*)(Cd + (size_t)r0 * strideN + cc)     = make_float2(f2tf32(c[mt][nt][0]), f2tf32(c[mt][nt][1]));
            *(float2*)(Cd + (size_t)(r0+8) * strideN + cc) = make_float2(f2tf32(c[mt][nt][2]), f2tf32(c[mt][nt][3]));
        }
    }
}

// ======== generic GEMM (BK=32, used for Wo) ========
__global__ __launch_bounds__(256)
void gemm_tc(const float* __restrict__ X, const float* __restrict__ W0,
             float* __restrict__ C, int N)
{
    extern __shared__ float sm[];
    float (*As)[32][136] = (float (*)[32][136])sm;
    float (*Bs)[32][72]  = (float (*)[32][72])(sm + 2*32*136);

    int tid = threadIdx.x;
    int lane = tid & 31, warp = tid >> 5;
    int wm = warp & 3, wn = warp >> 2;
    int gid = lane >> 2, tig = lane & 3;
    int m0 = blockIdx.y * 128, n0 = blockIdx.x * 64;

    float c[2][4][4];
    #pragma unroll
    for (int mt = 0; mt < 2; mt++)
        #pragma unroll
        for (int nt = 0; nt < 4; nt++)
            #pragma unroll
            for (int e = 0; e < 4; e++) c[mt][nt][e] = 0.f;

    int ra = tid >> 2;
    int ka = (tid & 3) * 4;
    int sw = 8 * (tid & 3);
    const float* xp0 = X + (size_t)(m0 + ra) * Kd + ka;
    const float* xp1 = X + (size_t)(m0 + ra + 64) * Kd + ka;
    const float* wp  = W0 + (size_t)(n0 + ra) * Kd + ka;
    int ca = ra ^ sw, ca1 = (ra + 64) ^ sw;

    {
        float4 a00 = *(const float4*)(xp0);
        float4 a01 = *(const float4*)(xp0 + 16);
        float4 a10 = *(const float4*)(xp1);
        float4 a11 = *(const float4*)(xp1 + 16);
        float4 b0  = *(const float4*)(wp);
        float4 b1  = *(const float4*)(wp + 16);
        As[0][ka+0][ca]  = f2tf32(a00.x); As[0][ka+1][ca]  = f2tf32(a00.y);
        As[0][ka+2][ca]  = f2tf32(a00.z); As[0][ka+3][ca]  = f2tf32(a00.w);
        As[0][ka+16][ca] = f2tf32(a01.x); As[0][ka+17][ca] = f2tf32(a01.y);
        As[0][ka+18][ca] = f2tf32(a01.z); As[0][ka+19][ca] = f2tf32(a01.w);
        As[0][ka+0][ca1]  = f2tf32(a10.x); As[0][ka+1][ca1]  = f2tf32(a10.y);
        As[0][ka+2][ca1]  = f2tf32(a10.z); As[0][ka+3][ca1]  = f2tf32(a10.w);
        As[0][ka+16][ca1] = f2tf32(a11.x); As[0][ka+17][ca1] = f2tf32(a11.y);
        As[0][ka+18][ca1] = f2tf32(a11.z); As[0][ka+19][ca1] = f2tf32(a11.w);
        Bs[0][ka+0][ca]  = f2tf32(b0.x); Bs[0][ka+1][ca]  = f2tf32(b0.y);
        Bs[0][ka+2][ca]  = f2tf32(b0.z); Bs[0][ka+3][ca]  = f2tf32(b0.w);
        Bs[0][ka+16][ca] = f2tf32(b1.x); Bs[0][ka+17][ca] = f2tf32(b1.y);
        Bs[0][ka+18][ca] = f2tf32(b1.z); Bs[0][ka+19][ca] = f2tf32(b1.w);
    }
    __syncthreads();

    const int NIT = Kd / 32;
    for (int it = 0; it < NIT; it++) {
        int cur = it & 1;
        float4 a00, a01, a10, a11, b0, b1;
        if (it + 1 < NIT) {
            int k0 = (it + 1) * 32;
            a00 = *(const float4*)(xp0 + k0);
            a01 = *(const float4*)(xp0 + k0 + 16);
            a10 = *(const float4*)(xp1 + k0);
            a11 = *(const float4*)(xp1 + k0 + 16);
            b0  = *(const float4*)(wp  + k0);
            b1  = *(const float4*)(wp  + k0 + 16);
        }
        #pragma unroll
        for (int ks = 0; ks < 32; ks += 8) {
            int swl = 8 * ((ks >> 2) & 3);
            int swh = 8 * (((ks + 4) >> 2) & 3);
            int klo = ks + tig, khi = ks + tig + 4;
            unsigned a[2][4], b[4][2];
            #pragma unroll
            for (int mt = 0; mt < 2; mt++) {
                int mr = wm*32 + mt*16 + gid;
                a[mt][0] = __float_as_uint(As[cur][klo][ mr      ^ swl]);
                a[mt][1] = __float_as_uint(As[cur][klo][(mr + 8) ^ swl]);
                a[mt][2] = __float_as_uint(As[cur][khi][ mr      ^ swh]);
                a[mt][3] = __float_as_uint(As[cur][khi][(mr + 8) ^ swh]);
            }
            #pragma unroll
            for (int nt = 0; nt < 4; nt++) {
                int nc = wn*32 + nt*8 + gid;
                b[nt][0] = __float_as_uint(Bs[cur][klo][nc ^ swl]);
                b[nt][1] = __float_as_uint(Bs[cur][khi][nc ^ swh]);
            }
            #pragma unroll
            for (int mt = 0; mt < 2; mt++)
                #pragma unroll
                for (int nt = 0; nt < 4; nt++)
                    mma_tf32(c[mt][nt], a[mt], b[nt]);
        }
        if (it + 1 < NIT) {
            int nx = cur ^ 1;
            As[nx][ka+0][ca]  = f2tf32(a00.x); As[nx][ka+1][ca]  = f2tf32(a00.y);
            As[nx][ka+2][ca]  = f2tf32(a00.z); As[nx][ka+3][ca]  = f2tf32(a00.w);
            As[nx][ka+16][ca] = f2tf32(a01.x); As[nx][ka+17][ca] = f2tf32(a01.y);
            As[nx][ka+18][ca] = f2tf32(a01.z); As[nx][ka+19][ca] = f2tf32(a01.w);
            As[nx][ka+0][ca1]  = f2tf32(a10.x); As[nx][ka+1][ca1]  = f2tf32(a10.y);
            As[nx][ka+2][ca1]  = f2tf32(a10.z); As[nx][ka+3][ca1]  = f2tf32(a10.w);
            As[nx][ka+16][ca1] = f2tf32(a11.x); As[nx][ka+17][ca1] = f2tf32(a11.y);
            As[nx][ka+18][ca1] = f2tf32(a11.z); As[nx][ka+19][ca1] = f2tf32(a11.w);
            Bs[nx][ka+0][ca]  = f2tf32(b0.x); Bs[nx][ka+1][ca]  = f2tf32(b0.y);
            Bs[nx][ka+2][ca]  = f2tf32(b0.z); Bs[nx][ka+3][ca]  = f2tf32(b0.w);
            Bs[nx][ka+16][ca] = f2tf32(b1.x); Bs[nx][ka+17][ca] = f2tf32(b1.y);
            Bs[nx][ka+18][ca] = f2tf32(b1.z); Bs[nx][ka+19][ca] = f2tf32(b1.w);
        }
        __syncthreads();
    }
    #pragma unroll
    for (int mt = 0; mt < 2; mt++) {
        int r0 = m0 + wm*32 + mt*16 + gid;
        #pragma unroll
        for (int nt = 0; nt < 4; nt++) {
            int cc = n0 + wn*32 + nt*8 + tig*2;
            *(float2*)(C + (size_t)r0 * N + cc)     = make_float2(c[mt][nt][0], c[mt][nt][1]);
            *(float2*)(C + (size_t)(r0+8) * N + cc) = make_float2(c[mt][nt][2], c[mt][nt][3]);
        }
    }
}

// ======== combine v4: inputs pre-rounded to tf32 -> no cvt in staging ========
__global__ __launch_bounds__(256)
void combine_tc3()
{
    extern __shared__ float dynsm[];
    float (*As)[2][32][72] = (float (*)[2][32][72])dynsm;
    float (*Bs)[2][32][72] = (float (*)[2][32][72])(dynsm + 2*2*32*72);

    int bz = blockIdx.z;
    int b = bz / 3, t = bz % 3;
    const float* Wt = (t == 0) ? g_wap : (t == 1) ? g_wbd : g_wrs;
    int m0 = (int)(gridDim.y - 1 - blockIdx.y) * 64;
    int n0 = blockIdx.x * 64;
    int colbase = t * D3 + n0;

    int tid = threadIdx.x;
    int lane = tid & 31, warp = tid >> 5;
    int wm = warp & 3, wn = warp >> 2;
    int gid = lane >> 2, tig = lane & 3;

    float c[2][4][4];
    #pragma unroll
    for (int p = 0; p < 2; p++)
        #pragma unroll
        for (int nt = 0; nt < 4; nt++)
            #pragma unroll
            for (int e = 0; e < 4; e++) c[p][nt][e] = 0.f;

    int ra = tid >> 2;
    int ka = (tid & 3) * 4;
    int cA = ra ^ (8 * (tid & 3));
    int kb = tid >> 4;
    int nb = (tid & 15) * 4;
    int swb = 8 * ((kb >> 2) & 3);
    int nbs = nb ^ swb;

    const float* aws = g_ws + (size_t)(b*Ss + m0 + ra) * Ss + ka;
    const float* awt = Wt   + (size_t)(b*Ss + m0 + ra) * Ss + ka;
    const float* bpv = g_V   + (size_t)(b*Ss + kb) * Dd + colbase + nb;
    const float* bpt = g_ABR + (size_t)(b*Ss + kb) * Dd + colbase + nb;

    const int NIT = m0/32 + 2;

    {
        float4 a00 = *(const float4*)(aws);
        float4 a01 = *(const float4*)(aws + 16);
        float4 a10 = *(const float4*)(awt);
        float4 a11 = *(const float4*)(awt + 16);
        float4 b00 = *(const float4*)(bpv);
        float4 b01 = *(const float4*)(bpv + (size_t)16 * Dd);
        float4 b10 = *(const float4*)(bpt);
        float4 b11 = *(const float4*)(bpt + (size_t)16 * Dd);
        As[0][0][ka+0][cA] = a00.x; As[0][0][ka+1][cA] = a00.y;
        As[0][0][ka+2][cA] = a00.z; As[0][0][ka+3][cA] = a00.w;
        As[0][0][ka+16][cA] = a01.x; As[0][0][ka+17][cA] = a01.y;
        As[0][0][ka+18][cA] = a01.z; As[0][0][ka+19][cA] = a01.w;
        As[0][1][ka+0][cA] = a10.x; As[0][1][ka+1][cA] = a10.y;
        As[0][1][ka+2][cA] = a10.z; As[0][1][ka+3][cA] = a10.w;
        As[0][1][ka+16][cA] = a11.x; As[0][1][ka+17][cA] = a11.y;
        As[0][1][ka+18][cA] = a11.z; As[0][1][ka+19][cA] = a11.w;
        *(float4*)&Bs[0][0][kb   ][nbs] = b00;
        *(float4*)&Bs[0][0][kb+16][nbs] = b01;
        *(float4*)&Bs[0][1][kb   ][nbs] = b10;
        *(float4*)&Bs[0][1][kb+16][nbs] = b11;
    }
    __syncthreads();

    for (int it = 0; it < NIT; it++) {
        int cur = it & 1;
        float4 a00, a01, a10, a11, b00, b01, b10, b11;
        if (it + 1 < NIT) {
            int k0 = (it + 1) * 32;
            a00 = *(const float4*)(aws + k0);
            a01 = *(const float4*)(aws + k0 + 16);
            a10 = *(const float4*)(awt + k0);
            a11 = *(const float4*)(awt + k0 + 16);
            b00 = *(const float4*)(bpv + (size_t)k0 * Dd);
            b01 = *(const float4*)(bpv + (size_t)(k0+16) * Dd);
            b10 = *(const float4*)(bpt + (size_t)k0 * Dd);
            b11 = *(const float4*)(bpt + (size_t)(k0+16) * Dd);
        }
        #pragma unroll
        for (int ks = 0; ks < 32; ks += 8) {
            int swl = 8 * ((ks >> 2) & 3);
            int swh = 8 * (((ks + 4) >> 2) & 3);
            int klo = ks + tig, khi = ks + tig + 4;
            int mr = wm*16 + gid;
            #pragma unroll
            for (int p = 0; p < 2; p++) {
                unsigned a[4], bfr[4][2];
                a[0] = __float_as_uint(As[cur][p][klo][ mr      ^ swl]);
                a[1] = __float_as_uint(As[cur][p][klo][(mr + 8) ^ swl]);
                a[2] = __float_as_uint(As[cur][p][khi][ mr      ^ swh]);
                a[3] = __float_as_uint(As[cur][p][khi][(mr + 8) ^ swh]);
                #pragma unroll
                for (int nt = 0; nt < 4; nt++) {
                    int nc = wn*32 + nt*8 + gid;
                    bfr[nt][0] = __float_as_uint(Bs[cur][p][klo][nc ^ swl]);
                    bfr[nt][1] = __float_as_uint(Bs[cur][p][khi][nc ^ swh]);
                }
                #pragma unroll
                for (int nt = 0; nt < 4; nt++)
                    mma_tf32(c[p][nt], a, bfr[nt]);
            }
        }
        if (it + 1 < NIT) {
            int nx = cur ^ 1;
            As[nx][0][ka+0][cA] = a00.x; As[nx][0][ka+1][cA] = a00.y;
            As[nx][0][ka+2][cA] = a00.z; As[nx][0][ka+3][cA] = a00.w;
            As[nx][0][ka+16][cA] = a01.x; As[nx][0][ka+17][cA] = a01.y;
            As[nx][0][ka+18][cA] = a01.z; As[nx][0][ka+19][cA] = a01.w;
            As[nx][1][ka+0][cA] = a10.x; As[nx][1][ka+1][cA] = a10.y;
            As[nx][1][ka+2][cA] = a10.z; As[nx][1][ka+3][cA] = a10.w;
            As[nx][1][ka+16][cA] = a11.x; As[nx][1][ka+17][cA] = a11.y;
            As[nx][1][ka+18][cA] = a11.z; As[nx][1][ka+19][cA] = a11.w;
            *(float4*)&Bs[nx][0][kb   ][nbs] = b00;
            *(float4*)&Bs[nx][0][kb+16][nbs] = b01;
            *(float4*)&Bs[nx][1][kb   ][nbs] = b10;
            *(float4*)&Bs[nx][1][kb+16][nbs] = b11;
        }
        __syncthreads();
    }

    int r0 = m0 + wm*16 + gid;
    float is0 = g_invden[b*Ss + r0],     it0 = g_invden[(t+1)*BS + b*Ss + r0];
    float is1 = g_invden[b*Ss + r0 + 8], it1 = g_invden[(t+1)*BS + b*Ss + r0 + 8];
    int rg = b*Ss + r0;
    #pragma unroll
    for (int nt = 0; nt < 4; nt++) {
        int cc = colbase + wn*32 + nt*8 + tig*2;
        *(float2*)(g_comb + (size_t)rg * Dd + cc) =
            make_float2(is0*c[0][nt][0] + it0*c[1][nt][0],
                        is0*c[0][nt][1] + it0*c[1][nt][1]);
        *(float2*)(g_comb + (size_t)(rg+8) * Dd + cc) =
            make_float2(is1*c[0][nt][2] + it1*c[1][nt][2],
                        is1*c[0][nt][3] + it1*c[1][nt][3]);
    }
}

// ---------------- merged setup (runs on its own stream) ----------------
__global__ __launch_bounds__(256)
void setup_kernel(const float* __restrict__ vemb, const float* __restrict__ spec,
                  const float* __restrict__ Wspec, const float* __restrict__ adj,
                  const float* __restrict__ vg)
{
    int tid = threadIdx.x;
    if (blockIdx.x == 0) {
        __shared__ float eb[NV*DV];
        __shared__ float adj_s[NV*NV];
        for (int t = tid; t < NV*DV; t += 256) {
            int u = t / DV, d = t % DV;
            float s = vemb[t];
            #pragma unroll
            for (int h = 0; h < 6; h++) s += 0.1f * spec[u*6+h] * Wspec[d*6+h];
            eb[t] = s;
        }
        for (int t = tid; t < NV*NV; t += 256) adj_s[t] = adj[t];
        __syncthreads();
        for (int t = tid; t < NV*DV; t += 256) {
            int v = t / DV, d = t % DV;
            float s = eb[t];
            #pragma unroll 8
            for (int u = 0; u < NV; u++) s += 0.1f * adj_s[u*NV + v] * eb[u*DV + d];
            g_emb2[t] = s;
        }
    } else {
        int v = blockIdx.x - 1;
        int lane = tid & 31, warp = tid >> 5;
        float s = 0.f;
        if (tid < 192) {
            float4 x4 = ((const float4*)(vg + (size_t)v*Dd))[tid];
            s = 1.f/(1.f + __expf(-x4.x)) + 1.f/(1.f + __expf(-x4.y))
              + 1.f/(1.f + __expf(-x4.z)) + 1.f/(1.f + __expf(-x4.w));
        }
        #pragma unroll
        for (int off = 16; off; off >>= 1) s += __shfl_xor_sync(0xffffffffu, s, off);
        __shared__ float red[8];
        if (lane == 0) red[warp] = s;
        __syncthreads();
        if (tid == 0) {
            float tot = 0.f;
            #pragma unroll
            for (int w = 0; w < 8; w++) tot += red[w];
            g_gm[v] = tot * (1.f / Dd);
        }
    }
}

// ---------------- row-persistent attention (causal-only stores; tf32 scalars) ----------------
__global__ __launch_bounds__(256)
void attn_row(float* __restrict__ pi_out)
{
    extern __shared__ float sm[];
    float (*Ks)[256][36] = (float (*)[256][36])sm;
    float* Fs = sm + 2*256*36;

    int i = Ss - 1 - (int)blockIdx.x;
    int b = blockIdx.y;
    int row_g = b*Ss + i;
    size_t rowbase = (size_t)row_g * Ss;
    int tid = threadIdx.x;
    int warp = tid >> 5, lane = tid & 31;
    int gid = lane >> 2, tig = lane & 3;

    __shared__ float q_s[DV];
    __shared__ float gm_s[NV];
    __shared__ float wred[8][4];

    if (tid < DV) q_s[tid] = g_QK[(size_t)row_g*64 + tid];
    if (tid >= 64 && tid < 128) gm_s[tid-64] = g_gm[tid-64];
    __syncthreads();
    const float LOG2E = 1.4426950408889634f;
    for (int t = tid; t < 2048; t += 256) {
        int d = t >> 6, v = t & 63;
        Fs[d*72 + v] = f2tf32(q_s[d] * LOG2E * g_emb2[v*DV + d]);
    }

    float gmr[16];
    #pragma unroll
    for (int nt = 0; nt < 8; nt++) {
        gmr[nt*2]   = gm_s[nt*8 + tig*2];
        gmr[nt*2+1] = gm_s[nt*8 + tig*2 + 1];
    }

    float bws = 0.f, bap = 0.f, bbd = 0.f, brs = 0.f;
    int ntiles = (i >> 8) + 1;
    int kr = tid >> 3, kq = (tid & 7) * 4;

    #pragma unroll
    for (int pp = 0; pp < 8; pp++) {
        int r = kr + pp*32;
        unsigned dst = smem_u32(&Ks[0][r][kq]);
        CP_ASYNC16(dst, g_QK + (size_t)(b*Ss + r)*64 + 32 + kq);
    }
    CP_COMMIT();

    for (int jt = 0; jt < ntiles; jt++) {
        int j0 = jt * 256;
        int cur = jt & 1;
        CP_WAIT0();
        __syncthreads();

        float c[2][8][4];
        #pragma unroll
        for (int mt = 0; mt < 2; mt++)
            #pragma unroll
            for (int nt = 0; nt < 8; nt++)
                #pragma unroll
                for (int e = 0; e < 4; e++) c[mt][nt][e] = 0.f;

        #pragma unroll
        for (int ks = 0; ks < 32; ks += 8) {
            unsigned a[2][4], bf[8][2];
            #pragma unroll
            for (int mt = 0; mt < 2; mt++) {
                int mr = warp*32 + mt*16 + gid;
                a[mt][0] = __float_as_uint(f2tf32(Ks[cur][mr  ][ks+tig]));
                a[mt][1] = __float_as_uint(f2tf32(Ks[cur][mr+8][ks+tig]));
                a[mt][2] = __float_as_uint(f2tf32(Ks[cur][mr  ][ks+tig+4]));
                a[mt][3] = __float_as_uint(f2tf32(Ks[cur][mr+8][ks+tig+4]));
            }
            #pragma unroll
            for (int nt = 0; nt < 8; nt++) {
                int nc = nt*8 + gid;
                bf[nt][0] = __float_as_uint(Fs[(ks+tig  )*72 + nc]);
                bf[nt][1] = __float_as_uint(Fs[(ks+tig+4)*72 + nc]);
            }
            #pragma unroll
            for (int mt = 0; mt < 2; mt++)
                #pragma unroll
                for (int nt = 0; nt < 8; nt++)
                    mma_tf32(c[mt][nt], a[mt], bf[nt]);
        }

        if (jt + 1 < ntiles) {
            int j0n = (jt + 1) * 256;
            int nx = cur ^ 1;
            #pragma unroll
            for (int pp = 0; pp < 8; pp++) {
                int r = kr + pp*32;
                unsigned dst = smem_u32(&Ks[nx][r][kq]);
                CP_ASYNC16(dst, g_QK + (size_t)(b*Ss + j0n + r)*64 + 32 + kq);
            }
            CP_COMMIT();
        }

        #pragma unroll
        for (int mt = 0; mt < 2; mt++)
        #pragma unroll
        for (int rh = 0; rh < 2; rh++) {
            int j = j0 + warp*32 + mt*16 + rh*8 + gid;
            size_t pair = rowbase + j;
            float e[16];
            float sum = 0.f, sg = 0.f, sap = 0.f;
            #pragma unroll
            for (int q = 0; q < 16; q++) {
                float ev = exp2f(c[mt][q>>1][rh*2 + (q&1)]);
                e[q] = ev;
                sum += ev;
                sg = fmaf(ev, gmr[q], sg);
                if (q & 1) sap += ev;
            }
            float sbd = (tig & 1) ? sum : 0.f;
            float srs = (tig & 2) ? sum : 0.f;
            sum += __shfl_xor_sync(0xffffffffu, sum, 1);
            sum += __shfl_xor_sync(0xffffffffu, sum, 2);
            sg  += __shfl_xor_sync(0xffffffffu, sg , 1);
            sg  += __shfl_xor_sync(0xffffffffu, sg , 2);
            sap += __shfl_xor_sync(0xffffffffu, sap, 1);
            sap += __shfl_xor_sync(0xffffffffu, sap, 2);
            sbd += __shfl_xor_sync(0xffffffffu, sbd, 1);
            sbd += __shfl_xor_sync(0xffffffffu, sbd, 2);
            srs += __shfl_xor_sync(0xffffffffu, srs, 1);
            srs += __shfl_xor_sync(0xffffffffu, srs, 2);

            if (j <= i) {
                float inv = 1.f / sum;
                float* po = pi_out + pair*NV + tig*2;
                #pragma unroll
                for (int nt = 0; nt < 8; nt++)
                    __stcs((float2*)(po + nt*8), make_float2(e[nt*2]*inv, e[nt*2+1]*inv));
                if (tig == 0) {
                    float ws = sg*inv, ap = sap*inv, bd = sbd*inv, rs = srs*inv;
                    // pre-round for combine (idempotent: combine used to cvt these)
                    g_ws[pair]  = f2tf32(ws);
                    g_wap[pair] = f2tf32(ap);
                    g_wbd[pair] = f2tf32(bd);
                    g_wrs[pair] = f2tf32(rs);
                    bws += ws; bap += ap; bbd += bd; brs += rs;
                }
            }
        }
    }

    #pragma unroll
    for (int off = 16; off; off >>= 1) {
        bws += __shfl_xor_sync(0xffffffffu, bws, off);
        bap += __shfl_xor_sync(0xffffffffu, bap, off);
        bbd += __shfl_xor_sync(0xffffffffu, bbd, off);
        brs += __shfl_xor_sync(0xffffffffu, brs, off);
    }
    if (lane == 0) {
        wred[warp][0] = bws; wred[warp][1] = bap;
        wred[warp][2] = bbd; wred[warp][3] = brs;
    }
    __syncthreads();
    if (tid < 4) {
        float s = 0.f;
        #pragma unroll
        for (int w = 0; w < 8; w++) s += wred[w][tid];
        if (tid == 0) {
            g_invden[row_g] = 1.f / (s + EPSV);
        } else {
            float d1 = s + EPSV, S2 = s / d1;
            g_invden[tid*BS + row_g] = 1.f / (d1 * (S2 + EPSV));
        }
    }
}

// ---------------- layernorm ----------------
__global__ void ln_kernel(const float* __restrict__ bo, const float* __restrict__ gamma,
                          const float* __restrict__ beta, float* __restrict__ out)
{
    int row = blockIdx.x, tid = threadIdx.x;
    const float* r = g_res + (size_t)row * Dd;
    float v[3];
    float s = 0.f;
    #pragma unroll
    for (int q = 0; q < 3; q++) { int c = tid + q*256; v[q] = r[c] + bo[c]; s += v[q]; }
    __shared__ float red[256];
    __shared__ float mu_s, inv_s;
    red[tid] = s; __syncthreads();
    for (int off = 128; off; off >>= 1) {
        if (tid < off) red[tid] += red[tid + off];
        __syncthreads();
    }
    if (tid == 0) mu_s = red[0] * (1.f / Dd);
    __syncthreads();
    float mu = mu_s;
    float s2 = 0.f;
    #pragma unroll
    for (int q = 0; q < 3; q++) { float d = v[q] - mu; s2 += d*d; }
    __syncthreads();
    red[tid] = s2; __syncthreads();
    for (int off = 128; off; off >>= 1) {
        if (tid < off) red[tid] += red[tid + off];
        __syncthreads();
    }
    if (tid == 0) inv_s = rsqrtf(red[0] * (1.f / Dd) + LNEPS);
    __syncthreads();
    float inv = inv_s;
    #pragma unroll
    for (int q = 0; q < 3; q++) {
        int c = tid + q*256;
        out[(size_t)row*Dd + c] = (v[q] - mu) * inv * gamma[c] + beta[c];
    }
}

// ---------------- launch ----------------
extern "C" void kernel_launch(void* const* d_in, const int* in_sizes, int n_in,
                              void* d_out, int out_size)
{
    const float* x      = (const float*)d_in[0];
    const float* Wq     = (const float*)d_in[2];
    const float* Wk     = (const float*)d_in[3];
    const float* vemb   = (const float*)d_in[4];
    const float* vgates = (const float*)d_in[5];
    const float* Wv     = (const float*)d_in[6];
    const float* Wspec  = (const float*)d_in[7];
    const float* Wa     = (const float*)d_in[8];
    const float* Wb     = (const float*)d_in[9];
    const float* Wr     = (const float*)d_in[10];
    const float* Wo     = (const float*)d_in[11];
    const float* bo     = (const float*)d_in[12];
    const float* gamma  = (const float*)d_in[13];
    const float* beta   = (const float*)d_in[14];
    const float* adj    = (const float*)d_in[15];
    const float* spec   = (const float*)d_in[16];

    float* out    = (float*)d_out;
    float* pi_out = out + NORMED_ELEMS;

    float *pQK, *pV, *pABR, *pComb, *pRes;
    cudaGetSymbolAddress((void**)&pQK,   g_QK);
    cudaGetSymbolAddress((void**)&pV,    g_V);
    cudaGetSymbolAddress((void**)&pABR,  g_ABR);
    cudaGetSymbolAddress((void**)&pComb, g_comb);
    cudaGetSymbolAddress((void**)&pRes,  g_res);

    const int COMBINE_SMEM = 2*2*32*72*4 * 2;          // 73728
    const int GEMM_SMEM    = (2*32*136 + 2*32*72) * 4; // 53248
    const int ATTN_SMEM    = (2*256*36 + 32*72) * 4;   // 82944

    static cudaStream_t s1 = nullptr, s2 = nullptr;
    static cudaEvent_t ev_fork = nullptr, ev_join = nullptr, ev_setup = nullptr;
    if (!s1) {
        cudaFuncSetAttribute(combine_tc3, cudaFuncAttributeMaxDynamicSharedMemorySize, COMBINE_SMEM);
        cudaFuncSetAttribute(gemm_fused,  cudaFuncAttributeMaxDynamicSharedMemorySize, GEMM_SMEM);
        cudaFuncSetAttribute(gemm_qk,     cudaFuncAttributeMaxDynamicSharedMemorySize, GEMM_SMEM);
        cudaFuncSetAttribute(gemm_tc,     cudaFuncAttributeMaxDynamicSharedMemorySize, GEMM_SMEM);
        cudaFuncSetAttribute(attn_row,    cudaFuncAttributeMaxDynamicSharedMemorySize, ATTN_SMEM);
        cudaStreamCreateWithFlags(&s1, cudaStreamNonBlocking);
        cudaStreamCreateWithFlags(&s2, cudaStreamNonBlocking);
        cudaEventCreateWithFlags(&ev_fork,  cudaEventDisableTiming);
        cudaEventCreateWithFlags(&ev_join,  cudaEventDisableTiming);
        cudaEventCreateWithFlags(&ev_setup, cudaEventDisableTiming);
    }

    dim3 thr(256);

    cudaEventRecord(ev_fork, 0);
    cudaStreamWaitEvent(s1, ev_fork, 0);
    cudaStreamWaitEvent(s2, ev_fork, 0);

    // s2: setup (emb2 + gate means) — needed only by attn
    setup_kernel<<<65, thr, 0, s2>>>(vemb, spec, Wspec, adj, vgates);
    cudaEventRecord(ev_setup, s2);

    // s1: zerofill (no deps) + V/ABR projection — needed only by combine
    zerofill_kernel<<<dim3(Ss, Bb), thr, 0, s1>>>(pi_out);
    gemm_fused<<<dim3(24, 16), thr, GEMM_SMEM, s1>>>(x, Wq, Wk, Wv, Wa, Wb, Wr,
                                                     pQK, pV, pABR, /*n_off=*/1);
    cudaEventRecord(ev_join, s1);

    // main stream: split-K QK projection + reduce, then attention
    gemm_qk<<<dim3(6, 16), thr, GEMM_SMEM>>>(x, Wq, Wk);
    qk_reduce<<<128, thr>>>();
    cudaStreamWaitEvent(0, ev_setup, 0);
    attn_row<<<dim3(Ss, Bb), thr, ATTN_SMEM>>>(pi_out);

    // join: combine needs V/ABR + attn outputs + zerofilled w-scalars
    cudaStreamWaitEvent(0, ev_join, 0);
    combine_tc3<<<dim3(4, 16, 6), thr, COMBINE_SMEM>>>();

    gemm_tc<<<dim3(12, 16), thr, GEMM_SMEM>>>(pComb, Wo, pRes, Dd);
    ln_kernel<<<BS, 256>>>(bo, gamma, beta, out);
}